// round 1
// baseline (speedup 1.0000x reference)
#include <cuda_runtime.h>

#define EPS 1e-5f
#define HW 6400
#define NC 128
#define ND 256
#define NH 80

// ---------------- scratch (static device globals; no allocation) -------------
__device__ float d_x1 [NC*HW];
__device__ float d_q  [NC*HW];
__device__ float d_k  [NC*HW];
__device__ float d_v  [NC*HW];
__device__ float d_p  [NC*HW];
__device__ float d_Rh [NH*HW];
__device__ float d_Rw [NH*HW];
__device__ float d_ABh[NH*HW];
__device__ float d_ABw[NH*HW];
__device__ float d_PA [NH*HW];
__device__ float d_PB [NH*HW];
__device__ float d_o1 [NC*HW];
__device__ float d_o2 [NC*HW];

// ---------------- generic tiled SGEMM with fused epilogues -------------------
// C[m, n] (n over HW=6400) = sum_k A(m,k) * B[k*HW + n]
// TRANSA=false: A[m*K + k] ; TRANSA=true: A[k*M + m]
// EPI: 0 plain, 1 +bias[m], 2 BN+SiLU, 3 BN+SiLU + resid[m*HW+n]
// ACCUM: C += result instead of C = result
template<int EPI, bool TRANSA, bool ACCUM>
__global__ void __launch_bounds__(256) gemm_epi(
    const float* __restrict__ A, const float* __restrict__ B,
    float* __restrict__ C, int M, int K,
    const float* __restrict__ bias,
    const float* __restrict__ g, const float* __restrict__ bb,
    const float* __restrict__ mm, const float* __restrict__ vv,
    const float* __restrict__ resid)
{
    __shared__ float As[16][68];
    __shared__ float Bs[16][68];
    const int tid = threadIdx.x;
    const int ty = tid >> 4, tx = tid & 15;
    const int m0 = blockIdx.y * 64, n0 = blockIdx.x * 64;

    float acc[4][4];
    #pragma unroll
    for (int a = 0; a < 4; a++)
        #pragma unroll
        for (int b = 0; b < 4; b++) acc[a][b] = 0.f;

    for (int k0 = 0; k0 < K; k0 += 16) {
        if (!TRANSA) {
            int mA = tid >> 2;
            int kA = (tid & 3) << 2;
            int gm = m0 + mA;
            float4 a4 = make_float4(0.f, 0.f, 0.f, 0.f);
            if (gm < M) a4 = *(const float4*)&A[gm * K + k0 + kA];
            As[kA + 0][mA] = a4.x; As[kA + 1][mA] = a4.y;
            As[kA + 2][mA] = a4.z; As[kA + 3][mA] = a4.w;
        } else {
            int kA = tid >> 4;
            int m4 = (tid & 15) << 2;
            float4 a4 = make_float4(0.f, 0.f, 0.f, 0.f);
            if (m0 + m4 < M) a4 = *(const float4*)&A[(k0 + kA) * M + m0 + m4];
            *(float4*)&As[kA][m4] = a4;
        }
        {
            int kB = tid >> 4;
            int n4 = (tid & 15) << 2;
            *(float4*)&Bs[kB][n4] = *(const float4*)&B[(k0 + kB) * HW + n0 + n4];
        }
        __syncthreads();
        #pragma unroll
        for (int kk = 0; kk < 16; ++kk) {
            float4 av = *(float4*)&As[kk][ty * 4];
            float4 bv = *(float4*)&Bs[kk][tx * 4];
            float am[4] = {av.x, av.y, av.z, av.w};
            float bn[4] = {bv.x, bv.y, bv.z, bv.w};
            #pragma unroll
            for (int a = 0; a < 4; a++)
                #pragma unroll
                for (int b = 0; b < 4; b++) acc[a][b] += am[a] * bn[b];
        }
        __syncthreads();
    }

    #pragma unroll
    for (int a = 0; a < 4; a++) {
        int gm = m0 + ty * 4 + a;
        if (gm >= M) continue;
        float sc = 0.f, sh = 0.f;
        if (EPI >= 2) {
            sc = g[gm] * rsqrtf(vv[gm] + EPS);
            sh = bb[gm] - mm[gm] * sc;
        }
        float4 r;
        float* rp = &r.x;
        #pragma unroll
        for (int b = 0; b < 4; b++) {
            float val = acc[a][b];
            if (EPI == 1) val += bias[gm];
            if (EPI >= 2) {
                val = val * sc + sh;
                val = val / (1.f + __expf(-val));   // SiLU
            }
            rp[b] = val;
        }
        int idx = gm * HW + n0 + tx * 4;
        if (EPI == 3) {
            float4 x4 = *(const float4*)&resid[idx];
            r.x += x4.x; r.y += x4.y; r.z += x4.z; r.w += x4.w;
        }
        if (ACCUM) {
            float4 c4 = *(float4*)&C[idx];
            r.x += c4.x; r.y += c4.y; r.z += c4.z; r.w += c4.w;
        }
        *(float4*)&C[idx] = r;
    }
}

// ---------------- per-column softmax over 80 rows (for branch 2) -------------
__global__ void softmax80(const float* __restrict__ in, float* __restrict__ out)
{
    int i = blockIdx.x * blockDim.x + threadIdx.x;
    if (i >= HW) return;
    float mx = -1e30f;
    for (int t = 0; t < NH; ++t) mx = fmaxf(mx, in[t * HW + i]);
    float s = 0.f;
    for (int t = 0; t < NH; ++t) s += __expf(in[t * HW + i] - mx);
    float inv = 1.f / s;
    for (int t = 0; t < NH; ++t) out[t * HW + i] = __expf(in[t * HW + i] - mx) * inv;
}

// ---------------- branch-1 flash attention -----------------------------------
// logits(i,j) = sum_c q[c,i]*k[c,j] + Rh[i/80, j] + Rw[i%80, j]
// out1[c,i]   = sum_j v[c,j] * softmax_j(logits)
// BI=64 rows per block, BJ=64 per tile, d=128, online softmax, all fp32.
#define FL_SM_FLOATS (3*128*68 + 64*68 + 192)

__global__ void __launch_bounds__(256) flash_kernel(
    const float* __restrict__ q, const float* __restrict__ k,
    const float* __restrict__ v, const float* __restrict__ Rh,
    const float* __restrict__ Rw, float* __restrict__ out1)
{
    extern __shared__ float sm[];
    float* Qs   = sm;                 // [128][68]
    float* Ks   = Qs + 128 * 68;      // [128][68]
    float* Vs   = Ks + 128 * 68;      // [128][68]
    float* Ss   = Vs + 128 * 68;      // [64][68]
    float* mrow = Ss + 64 * 68;       // [64]
    float* lrow = mrow + 64;          // [64]
    float* frow = lrow + 64;          // [64]

    const int tid  = threadIdx.x;
    const int ty   = tid >> 4, tx = tid & 15;
    const int warp = tid >> 5, lane = tid & 31;
    const int i0   = blockIdx.x * 64;

    {   // load Q tile [128 c][64 i]
        int cr = tid >> 4;
        int j4 = (tid & 15) << 2;
        #pragma unroll
        for (int it = 0; it < 8; ++it) {
            int c = cr + it * 16;
            *(float4*)&Qs[c * 68 + j4] = *(const float4*)&q[c * HW + i0 + j4];
        }
    }
    if (tid < 64) { mrow[tid] = -1e30f; lrow[tid] = 0.f; }

    float o[4][8];
    #pragma unroll
    for (int a = 0; a < 4; a++)
        #pragma unroll
        for (int c8 = 0; c8 < 8; c8++) o[a][c8] = 0.f;

    int hi_[4], wi_[4];
    #pragma unroll
    for (int a = 0; a < 4; a++) {
        int gi = i0 + ty * 4 + a;
        hi_[a] = gi / 80;
        wi_[a] = gi % 80;
    }
    __syncthreads();

    for (int j0 = 0; j0 < HW; j0 += 64) {
        {   // load K tile
            int cr = tid >> 4;
            int j4 = (tid & 15) << 2;
            #pragma unroll
            for (int it = 0; it < 8; ++it) {
                int c = cr + it * 16;
                *(float4*)&Ks[c * 68 + j4] = *(const float4*)&k[c * HW + j0 + j4];
            }
        }
        __syncthreads();

        // S = Q^T K  (4x4 microtile per thread)
        float s[4][4];
        #pragma unroll
        for (int a = 0; a < 4; a++)
            #pragma unroll
            for (int b = 0; b < 4; b++) s[a][b] = 0.f;
        #pragma unroll 8
        for (int c = 0; c < 128; ++c) {
            float4 qa = *(float4*)&Qs[c * 68 + ty * 4];
            float4 kb = *(float4*)&Ks[c * 68 + tx * 4];
            float am[4] = {qa.x, qa.y, qa.z, qa.w};
            float bm[4] = {kb.x, kb.y, kb.z, kb.w};
            #pragma unroll
            for (int a = 0; a < 4; a++)
                #pragma unroll
                for (int b = 0; b < 4; b++) s[a][b] += am[a] * bm[b];
        }

        // + separable positional bias, store to Ss
        #pragma unroll
        for (int a = 0; a < 4; a++) {
            const float* rh = &Rh[hi_[a] * HW + j0 + tx * 4];
            const float* rw = &Rw[wi_[a] * HW + j0 + tx * 4];
            float4 r4;
            r4.x = s[a][0] + rh[0] + rw[0];
            r4.y = s[a][1] + rh[1] + rw[1];
            r4.z = s[a][2] + rh[2] + rw[2];
            r4.w = s[a][3] + rh[3] + rw[3];
            *(float4*)&Ss[(ty * 4 + a) * 68 + tx * 4] = r4;
        }

        {   // load V tile (overlaps with softmax latency)
            int cr = tid >> 4;
            int j4 = (tid & 15) << 2;
            #pragma unroll
            for (int it = 0; it < 8; ++it) {
                int c = cr + it * 16;
                *(float4*)&Vs[c * 68 + j4] = *(const float4*)&v[c * HW + j0 + j4];
            }
        }
        __syncthreads();

        // online softmax: warp w owns rows w*8 .. w*8+7
        #pragma unroll
        for (int r8 = 0; r8 < 8; ++r8) {
            int r = warp * 8 + r8;
            float v1 = Ss[r * 68 + lane];
            float v2 = Ss[r * 68 + 32 + lane];
            float tm = fmaxf(v1, v2);
            #pragma unroll
            for (int off = 16; off; off >>= 1)
                tm = fmaxf(tm, __shfl_xor_sync(0xffffffffu, tm, off));
            float mold = mrow[r];
            float nm = fmaxf(mold, tm);
            float e1 = __expf(v1 - nm), e2 = __expf(v2 - nm);
            float ssum = e1 + e2;
            #pragma unroll
            for (int off = 16; off; off >>= 1)
                ssum += __shfl_xor_sync(0xffffffffu, ssum, off);
            Ss[r * 68 + lane]      = e1;
            Ss[r * 68 + 32 + lane] = e2;
            if (lane == 0) {
                float f = __expf(mold - nm);
                lrow[r] = lrow[r] * f + ssum;
                mrow[r] = nm;
                frow[r] = f;
            }
        }
        __syncthreads();

        // O update: O[i][c] = O*f + P @ V^T   (4 i x 8 c per thread, c = c8*16+tx)
        float fa[4];
        #pragma unroll
        for (int a = 0; a < 4; a++) fa[a] = frow[ty * 4 + a];
        #pragma unroll
        for (int a = 0; a < 4; a++)
            #pragma unroll
            for (int c8 = 0; c8 < 8; c8++) o[a][c8] *= fa[a];

        #pragma unroll 4
        for (int jj = 0; jj < 64; jj += 4) {
            float4 p4[4];
            #pragma unroll
            for (int a = 0; a < 4; a++)
                p4[a] = *(float4*)&Ss[(ty * 4 + a) * 68 + jj];
            float4 v4[8];
            #pragma unroll
            for (int c8 = 0; c8 < 8; c8++)
                v4[c8] = *(float4*)&Vs[(c8 * 16 + tx) * 68 + jj];
            #pragma unroll
            for (int a = 0; a < 4; a++)
                #pragma unroll
                for (int c8 = 0; c8 < 8; c8++)
                    o[a][c8] += p4[a].x * v4[c8].x + p4[a].y * v4[c8].y +
                                p4[a].z * v4[c8].z + p4[a].w * v4[c8].w;
        }
        __syncthreads();
    }

    #pragma unroll
    for (int a = 0; a < 4; a++) {
        float inv = 1.f / lrow[ty * 4 + a];
        int gi = i0 + ty * 4 + a;
        #pragma unroll
        for (int c8 = 0; c8 < 8; c8++)
            out1[(c8 * 16 + tx) * HW + gi] = o[a][c8] * inv;
    }
}

// -------------------------------- launch -------------------------------------
extern "C" void kernel_launch(void* const* d_in, const int* in_sizes, int n_in,
                              void* d_out, int out_size)
{
    (void)in_sizes; (void)n_in; (void)out_size;
    const float* x    = (const float*)d_in[0];
    const float* w1   = (const float*)d_in[1];
    const float* g1   = (const float*)d_in[2];
    const float* b1   = (const float*)d_in[3];
    const float* m1   = (const float*)d_in[4];
    const float* v1   = (const float*)d_in[5];
    const float* w2   = (const float*)d_in[6];
    const float* g2   = (const float*)d_in[7];
    const float* b2   = (const float*)d_in[8];
    const float* m2   = (const float*)d_in[9];
    const float* v2   = (const float*)d_in[10];
    const float* w3   = (const float*)d_in[11];
    const float* g3   = (const float*)d_in[12];
    const float* b3   = (const float*)d_in[13];
    const float* m3   = (const float*)d_in[14];
    const float* v3   = (const float*)d_in[15];
    const float* wq   = (const float*)d_in[16];
    const float* bq   = (const float*)d_in[17];
    const float* wk   = (const float*)d_in[18];
    const float* bk   = (const float*)d_in[19];
    const float* wv   = (const float*)d_in[20];
    const float* bv   = (const float*)d_in[21];
    const float* wp   = (const float*)d_in[22];
    const float* bp   = (const float*)d_in[23];
    const float* relh = (const float*)d_in[24];
    const float* relw = (const float*)d_in[25];
    const float* efh  = (const float*)d_in[26];
    const float* efw  = (const float*)d_in[27];
    float* out = (float*)d_out;

    float *px1, *pq, *pk, *pv, *pp, *pRh, *pRw, *pABh, *pABw, *pPA, *pPB, *po1, *po2;
    cudaGetSymbolAddress((void**)&px1, d_x1);
    cudaGetSymbolAddress((void**)&pq,  d_q);
    cudaGetSymbolAddress((void**)&pk,  d_k);
    cudaGetSymbolAddress((void**)&pv,  d_v);
    cudaGetSymbolAddress((void**)&pp,  d_p);
    cudaGetSymbolAddress((void**)&pRh, d_Rh);
    cudaGetSymbolAddress((void**)&pRw, d_Rw);
    cudaGetSymbolAddress((void**)&pABh, d_ABh);
    cudaGetSymbolAddress((void**)&pABw, d_ABw);
    cudaGetSymbolAddress((void**)&pPA, d_PA);
    cudaGetSymbolAddress((void**)&pPB, d_PB);
    cudaGetSymbolAddress((void**)&po1, d_o1);
    cudaGetSymbolAddress((void**)&po2, d_o2);

    cudaFuncSetAttribute(flash_kernel,
        cudaFuncAttributeMaxDynamicSharedMemorySize, FL_SM_FLOATS * 4);

    dim3 g100_2(100, 2), g100_4(100, 4);

    // x1 = SiLU(BN(w1 @ x))
    gemm_epi<2, false, false><<<g100_2, 256>>>(w1, x, px1, NC, ND,
        nullptr, g1, b1, m1, v1, nullptr);
    // q, k, v, p projections (+bias)
    gemm_epi<1, false, false><<<g100_2, 256>>>(wq, px1, pq, NC, NC,
        bq, nullptr, nullptr, nullptr, nullptr, nullptr);
    gemm_epi<1, false, false><<<g100_2, 256>>>(wk, px1, pk, NC, NC,
        bk, nullptr, nullptr, nullptr, nullptr, nullptr);
    gemm_epi<1, false, false><<<g100_2, 256>>>(wv, px1, pv, NC, NC,
        bv, nullptr, nullptr, nullptr, nullptr, nullptr);
    gemm_epi<1, false, false><<<g100_2, 256>>>(wp, px1, pp, NC, NC,
        bp, nullptr, nullptr, nullptr, nullptr, nullptr);
    // Rh = rel_h^T q, Rw = rel_w^T q   [80, 6400]
    gemm_epi<0, true, false><<<g100_2, 256>>>(relh, pq, pRh, NH, NC,
        nullptr, nullptr, nullptr, nullptr, nullptr, nullptr);
    gemm_epi<0, true, false><<<g100_2, 256>>>(relw, pq, pRw, NH, NC,
        nullptr, nullptr, nullptr, nullptr, nullptr, nullptr);
    // branch-2 separable logits: ABh = ef_h^T p, ABw = ef_w^T p
    gemm_epi<0, true, false><<<g100_2, 256>>>(efh, pp, pABh, NH, NC,
        nullptr, nullptr, nullptr, nullptr, nullptr, nullptr);
    gemm_epi<0, true, false><<<g100_2, 256>>>(efw, pp, pABw, NH, NC,
        nullptr, nullptr, nullptr, nullptr, nullptr, nullptr);
    // factored softmaxes
    softmax80<<<25, 256>>>(pABh, pPA);
    softmax80<<<25, 256>>>(pABw, pPB);
    // out2 = ef_h @ PA + ef_w @ PB
    gemm_epi<0, false, false><<<g100_2, 256>>>(efh, pPA, po2, NC, NH,
        nullptr, nullptr, nullptr, nullptr, nullptr, nullptr);
    gemm_epi<0, false, true><<<g100_2, 256>>>(efw, pPB, po2, NC, NH,
        nullptr, nullptr, nullptr, nullptr, nullptr, nullptr);
    // branch-1 flash attention -> out1
    flash_kernel<<<100, 256, FL_SM_FLOATS * 4>>>(pq, pk, pv, pRh, pRw, po1);
    // out = x + SiLU(BN(w2 @ out1)) + SiLU(BN(w3 @ out2))
    gemm_epi<3, false, false><<<g100_4, 256>>>(w2, po1, out, ND, NC,
        nullptr, g2, b2, m2, v2, x);
    gemm_epi<2, false, true><<<g100_4, 256>>>(w3, po2, out, ND, NC,
        nullptr, g3, b3, m3, v3, nullptr);
}

// round 2
// speedup vs baseline: 1.2381x; 1.2381x over previous
#include <cuda_runtime.h>

#define EPS 1e-5f
#define HW 6400
#define NC 128
#define ND 256
#define NH 80
#define SPLIT 3

// ---------------- packed fp32x2 helpers (Blackwell FFMA2 pipe) ---------------
__device__ __forceinline__ void fma2(unsigned long long& d,
                                     unsigned long long a, unsigned long long b) {
    asm("fma.rn.f32x2 %0, %1, %2, %0;" : "+l"(d) : "l"(a), "l"(b));
}
__device__ __forceinline__ void mul2(unsigned long long& d, unsigned long long a) {
    asm("mul.rn.f32x2 %0, %0, %1;" : "+l"(d) : "l"(a));
}
__device__ __forceinline__ unsigned long long pk2(float x, float y) {
    unsigned long long r;
    asm("mov.b64 %0, {%1,%2};" : "=l"(r) : "f"(x), "f"(y));
    return r;
}
__device__ __forceinline__ float2 upk2(unsigned long long v) {
    float2 t;
    asm("mov.b64 {%0,%1}, %2;" : "=f"(t.x), "=f"(t.y) : "l"(v));
    return t;
}

// ---------------- scratch (static device globals; no allocation) -------------
__device__ float d_x1 [NC*HW];
__device__ float d_q  [NC*HW];
__device__ float d_k  [NC*HW];
__device__ float d_v  [NC*HW];
__device__ float d_p  [NC*HW];
__device__ float d_Rh [NH*HW];
__device__ float d_Rw [NH*HW];
__device__ float d_ABh[NH*HW];
__device__ float d_ABw[NH*HW];
__device__ float d_PA [NH*HW];
__device__ float d_PB [NH*HW];
__device__ float d_o1 [NC*HW];
__device__ float d_o2 [NC*HW];
__device__ float d_op [SPLIT*NC*HW];
__device__ float d_mp [SPLIT*HW];
__device__ float d_lp [SPLIT*HW];

// ---------------- generic tiled SGEMM with fused epilogues -------------------
// C[m, n] (n over HW=6400) = sum_k A(m,k) * B[k*HW + n]
// TRANSA=false: A[m*K + k] (fast FFMA2 path); TRANSA=true: A[k*M + m] (scalar)
// EPI: 0 plain, 1 +bias[m], 2 BN+SiLU, 3 BN+SiLU + resid[m*HW+n]
template<int EPI, bool TRANSA, bool ACCUM>
__global__ void __launch_bounds__(256) gemm_epi(
    const float* __restrict__ A, const float* __restrict__ B,
    float* __restrict__ C, int M, int K,
    const float* __restrict__ bias,
    const float* __restrict__ g, const float* __restrict__ bb,
    const float* __restrict__ mm, const float* __restrict__ vv,
    const float* __restrict__ resid)
{
    __shared__ float As[16 * 136];   // NOTRANS: duplicated [k][2m]; TRANSA: [k][m] (68 stride)
    __shared__ float Bs[16 * 68];
    const int tid = threadIdx.x;
    const int ty = tid >> 4, tx = tid & 15;
    const int m0 = blockIdx.y * 64, n0 = blockIdx.x * 64;

    float acc[4][4];

    if (!TRANSA) {
        unsigned long long acc2[4][2];
        #pragma unroll
        for (int a = 0; a < 4; a++) { acc2[a][0] = 0ull; acc2[a][1] = 0ull; }

        for (int k0 = 0; k0 < K; k0 += 16) {
            {
                int mA = tid >> 2;
                int kA = (tid & 3) << 2;
                int gm = m0 + mA;
                float4 a4 = make_float4(0.f, 0.f, 0.f, 0.f);
                if (gm < M) a4 = *(const float4*)&A[gm * K + k0 + kA];
                float av[4] = {a4.x, a4.y, a4.z, a4.w};
                #pragma unroll
                for (int i = 0; i < 4; i++) {
                    As[(kA + i) * 136 + 2 * mA]     = av[i];
                    As[(kA + i) * 136 + 2 * mA + 1] = av[i];
                }
            }
            {
                int kB = tid >> 4;
                int n4 = (tid & 15) << 2;
                *(float4*)&Bs[kB * 68 + n4] = *(const float4*)&B[(k0 + kB) * HW + n0 + n4];
            }
            __syncthreads();
            #pragma unroll
            for (int kk = 0; kk < 16; ++kk) {
                ulonglong2 ad0 = *(const ulonglong2*)&As[kk * 136 + ty * 8];
                ulonglong2 ad1 = *(const ulonglong2*)&As[kk * 136 + ty * 8 + 4];
                ulonglong2 bp  = *(const ulonglong2*)&Bs[kk * 68 + tx * 4];
                fma2(acc2[0][0], ad0.x, bp.x); fma2(acc2[0][1], ad0.x, bp.y);
                fma2(acc2[1][0], ad0.y, bp.x); fma2(acc2[1][1], ad0.y, bp.y);
                fma2(acc2[2][0], ad1.x, bp.x); fma2(acc2[2][1], ad1.x, bp.y);
                fma2(acc2[3][0], ad1.y, bp.x); fma2(acc2[3][1], ad1.y, bp.y);
            }
            __syncthreads();
        }
        #pragma unroll
        for (int a = 0; a < 4; a++) {
            float2 lo = upk2(acc2[a][0]);
            float2 hi = upk2(acc2[a][1]);
            acc[a][0] = lo.x; acc[a][1] = lo.y; acc[a][2] = hi.x; acc[a][3] = hi.y;
        }
    } else {
        #pragma unroll
        for (int a = 0; a < 4; a++)
            #pragma unroll
            for (int b = 0; b < 4; b++) acc[a][b] = 0.f;

        for (int k0 = 0; k0 < K; k0 += 16) {
            {
                int kA = tid >> 4;
                int m4 = (tid & 15) << 2;
                float4 a4 = make_float4(0.f, 0.f, 0.f, 0.f);
                if (m0 + m4 < M) a4 = *(const float4*)&A[(k0 + kA) * M + m0 + m4];
                *(float4*)&As[kA * 68 + m4] = a4;
            }
            {
                int kB = tid >> 4;
                int n4 = (tid & 15) << 2;
                *(float4*)&Bs[kB * 68 + n4] = *(const float4*)&B[(k0 + kB) * HW + n0 + n4];
            }
            __syncthreads();
            #pragma unroll
            for (int kk = 0; kk < 16; ++kk) {
                float4 av = *(float4*)&As[kk * 68 + ty * 4];
                float4 bv = *(float4*)&Bs[kk * 68 + tx * 4];
                float am[4] = {av.x, av.y, av.z, av.w};
                float bn[4] = {bv.x, bv.y, bv.z, bv.w};
                #pragma unroll
                for (int a = 0; a < 4; a++)
                    #pragma unroll
                    for (int b = 0; b < 4; b++) acc[a][b] += am[a] * bn[b];
            }
            __syncthreads();
        }
    }

    #pragma unroll
    for (int a = 0; a < 4; a++) {
        int gm = m0 + ty * 4 + a;
        if (gm >= M) continue;
        float sc = 0.f, sh = 0.f;
        if (EPI >= 2) {
            sc = g[gm] * rsqrtf(vv[gm] + EPS);
            sh = bb[gm] - mm[gm] * sc;
        }
        float4 r;
        float* rp = &r.x;
        #pragma unroll
        for (int b = 0; b < 4; b++) {
            float val = acc[a][b];
            if (EPI == 1) val += bias[gm];
            if (EPI >= 2) {
                val = val * sc + sh;
                val = val / (1.f + __expf(-val));   // SiLU
            }
            rp[b] = val;
        }
        int idx = gm * HW + n0 + tx * 4;
        if (EPI == 3) {
            float4 x4 = *(const float4*)&resid[idx];
            r.x += x4.x; r.y += x4.y; r.z += x4.z; r.w += x4.w;
        }
        if (ACCUM) {
            float4 c4 = *(float4*)&C[idx];
            r.x += c4.x; r.y += c4.y; r.z += c4.z; r.w += c4.w;
        }
        *(float4*)&C[idx] = r;
    }
}

// ---------------- per-column softmax over 80 rows (for branch 2) -------------
__global__ void softmax80(const float* __restrict__ in, float* __restrict__ out)
{
    int i = blockIdx.x * blockDim.x + threadIdx.x;
    if (i >= HW) return;
    float mx = -1e30f;
    for (int t = 0; t < NH; ++t) mx = fmaxf(mx, in[t * HW + i]);
    float s = 0.f;
    for (int t = 0; t < NH; ++t) s += __expf(in[t * HW + i] - mx);
    float inv = 1.f / s;
    for (int t = 0; t < NH; ++t) out[t * HW + i] = __expf(in[t * HW + i] - mx) * inv;
}

// ---------------- branch-1 flash attention (FFMA2 + split-j) -----------------
// logits(i,j) = sum_c q[c,i]*k[c,j] + Rh[i/80, j] + Rw[i%80, j]
// Each (i-tile, split) CTA scans a third of j; emits unnormalized o + (m, l).
#define FL_SM_FLOATS (128*132 + 2*128*68 + 64*68 + 192)

__global__ void __launch_bounds__(256) flash_kernel(
    const float* __restrict__ q, const float* __restrict__ k,
    const float* __restrict__ v, const float* __restrict__ Rh,
    const float* __restrict__ Rw, float* __restrict__ op,
    float* __restrict__ mp, float* __restrict__ lp)
{
    extern __shared__ float sm[];
    float* Qd   = sm;                 // [128][132] duplicated q pairs
    float* Ks   = Qd + 128 * 132;     // [128][68]
    float* Vs   = Ks + 128 * 68;      // [128][68]
    float* Ss   = Vs + 128 * 68;      // [64][68]
    float* mrow = Ss + 64 * 68;       // [64]
    float* lrow = mrow + 64;
    float* frow = lrow + 64;

    const int tid  = threadIdx.x;
    const int ty   = tid >> 4, tx = tid & 15;
    const int warp = tid >> 5, lane = tid & 31;
    const int i0   = blockIdx.x * 64;
    const int spl  = blockIdx.y;
    const int t0   = (spl * 100) / SPLIT;
    const int t1   = ((spl + 1) * 100) / SPLIT;

    {   // load Q tile duplicated: Qd[c][2i] = Qd[c][2i+1] = q[c][i0+i]
        int cr = tid >> 4;
        int j4 = (tid & 15) << 2;
        #pragma unroll
        for (int it = 0; it < 8; ++it) {
            int c = cr + it * 16;
            float4 t = *(const float4*)&q[c * HW + i0 + j4];
            *(float4*)&Qd[c * 132 + 2 * j4]     = make_float4(t.x, t.x, t.y, t.y);
            *(float4*)&Qd[c * 132 + 2 * j4 + 4] = make_float4(t.z, t.z, t.w, t.w);
        }
    }
    if (tid < 64) { mrow[tid] = -1e30f; lrow[tid] = 0.f; }

    unsigned long long o2[4][8];   // packed pairs along j (reduction dim)
    #pragma unroll
    for (int a = 0; a < 4; a++)
        #pragma unroll
        for (int c8 = 0; c8 < 8; c8++) o2[a][c8] = 0ull;

    int hi_[4], wi_[4];
    #pragma unroll
    for (int a = 0; a < 4; a++) {
        int gi = i0 + ty * 4 + a;
        hi_[a] = gi / 80;
        wi_[a] = gi % 80;
    }
    __syncthreads();

    for (int t = t0; t < t1; ++t) {
        const int j0 = t * 64;
        {   // load K tile [128 c][64 j]
            int cr = tid >> 4;
            int j4 = (tid & 15) << 2;
            #pragma unroll
            for (int it = 0; it < 8; ++it) {
                int c = cr + it * 16;
                *(float4*)&Ks[c * 68 + j4] = *(const float4*)&k[c * HW + j0 + j4];
            }
        }
        __syncthreads();

        // S = Q^T K via FFMA2: dup-q broadcast pairs x natural k pairs
        unsigned long long s2[4][2];
        #pragma unroll
        for (int a = 0; a < 4; a++) { s2[a][0] = 0ull; s2[a][1] = 0ull; }
        #pragma unroll 4
        for (int c = 0; c < 128; ++c) {
            ulonglong2 qd0 = *(const ulonglong2*)&Qd[c * 132 + ty * 8];
            ulonglong2 qd1 = *(const ulonglong2*)&Qd[c * 132 + ty * 8 + 4];
            ulonglong2 kp  = *(const ulonglong2*)&Ks[c * 68 + tx * 4];
            fma2(s2[0][0], qd0.x, kp.x); fma2(s2[0][1], qd0.x, kp.y);
            fma2(s2[1][0], qd0.y, kp.x); fma2(s2[1][1], qd0.y, kp.y);
            fma2(s2[2][0], qd1.x, kp.x); fma2(s2[2][1], qd1.x, kp.y);
            fma2(s2[3][0], qd1.y, kp.x); fma2(s2[3][1], qd1.y, kp.y);
        }

        // + separable positional bias, store to Ss
        #pragma unroll
        for (int a = 0; a < 4; a++) {
            const float* rh = &Rh[hi_[a] * HW + j0 + tx * 4];
            const float* rw = &Rw[wi_[a] * HW + j0 + tx * 4];
            float2 lo = upk2(s2[a][0]);
            float2 hi = upk2(s2[a][1]);
            float4 r4;
            r4.x = lo.x + rh[0] + rw[0];
            r4.y = lo.y + rh[1] + rw[1];
            r4.z = hi.x + rh[2] + rw[2];
            r4.w = hi.y + rh[3] + rw[3];
            *(float4*)&Ss[(ty * 4 + a) * 68 + tx * 4] = r4;
        }

        {   // load V tile (overlaps with softmax latency)
            int cr = tid >> 4;
            int j4 = (tid & 15) << 2;
            #pragma unroll
            for (int it = 0; it < 8; ++it) {
                int c = cr + it * 16;
                *(float4*)&Vs[c * 68 + j4] = *(const float4*)&v[c * HW + j0 + j4];
            }
        }
        __syncthreads();

        // online softmax: warp w owns rows w*8 .. w*8+7
        #pragma unroll
        for (int r8 = 0; r8 < 8; ++r8) {
            int r = warp * 8 + r8;
            float v1 = Ss[r * 68 + lane];
            float v2 = Ss[r * 68 + 32 + lane];
            float tm = fmaxf(v1, v2);
            #pragma unroll
            for (int off = 16; off; off >>= 1)
                tm = fmaxf(tm, __shfl_xor_sync(0xffffffffu, tm, off));
            float mold = mrow[r];
            float nm = fmaxf(mold, tm);
            float e1 = __expf(v1 - nm), e2 = __expf(v2 - nm);
            float ssum = e1 + e2;
            #pragma unroll
            for (int off = 16; off; off >>= 1)
                ssum += __shfl_xor_sync(0xffffffffu, ssum, off);
            Ss[r * 68 + lane]      = e1;
            Ss[r * 68 + 32 + lane] = e2;
            if (lane == 0) {
                float f = __expf(mold - nm);
                lrow[r] = lrow[r] * f + ssum;
                mrow[r] = nm;
                frow[r] = f;
            }
        }
        __syncthreads();

        // O rescale + P @ V^T with FFMA2 (pairs along j; horizontal add at end)
        #pragma unroll
        for (int a = 0; a < 4; a++) {
            unsigned long long fp = pk2(frow[ty * 4 + a], frow[ty * 4 + a]);
            #pragma unroll
            for (int c8 = 0; c8 < 8; c8++) mul2(o2[a][c8], fp);
        }

        #pragma unroll 4
        for (int jj = 0; jj < 64; jj += 4) {
            ulonglong2 p2[4];
            #pragma unroll
            for (int a = 0; a < 4; a++)
                p2[a] = *(const ulonglong2*)&Ss[(ty * 4 + a) * 68 + jj];
            ulonglong2 v2[8];
            #pragma unroll
            for (int c8 = 0; c8 < 8; c8++)
                v2[c8] = *(const ulonglong2*)&Vs[(c8 * 16 + tx) * 68 + jj];
            #pragma unroll
            for (int a = 0; a < 4; a++)
                #pragma unroll
                for (int c8 = 0; c8 < 8; c8++) {
                    fma2(o2[a][c8], p2[a].x, v2[c8].x);
                    fma2(o2[a][c8], p2[a].y, v2[c8].y);
                }
        }
        __syncthreads();
    }

    // emit unnormalized partials + (m, l)
    #pragma unroll
    for (int a = 0; a < 4; a++) {
        int gi = i0 + ty * 4 + a;
        #pragma unroll
        for (int c8 = 0; c8 < 8; c8++) {
            float2 t = upk2(o2[a][c8]);
            op[(spl * NC + c8 * 16 + tx) * HW + gi] = t.x + t.y;
        }
    }
    if (tid < 64) {
        mp[spl * HW + i0 + tid] = mrow[tid];
        lp[spl * HW + i0 + tid] = lrow[tid];
    }
}

// ---------------- split-j combine: out1 = sum_s o_s * e^{m_s - M} / L --------
__global__ void combine_kernel(const float* __restrict__ op,
                               const float* __restrict__ mp,
                               const float* __restrict__ lp,
                               float* __restrict__ out1)
{
    int i = blockIdx.x * blockDim.x + threadIdx.x;
    if (i >= HW) return;
    float m0 = mp[i], m1 = mp[HW + i], m2 = mp[2 * HW + i];
    float M = fmaxf(m0, fmaxf(m1, m2));
    float w0 = __expf(m0 - M), w1 = __expf(m1 - M), w2 = __expf(m2 - M);
    float L = lp[i] * w0 + lp[HW + i] * w1 + lp[2 * HW + i] * w2;
    float inv = 1.f / L;
    for (int c = 0; c < NC; ++c) {
        float s = op[c * HW + i] * w0
                + op[(NC + c) * HW + i] * w1
                + op[(2 * NC + c) * HW + i] * w2;
        out1[c * HW + i] = s * inv;
    }
}

// -------------------------------- launch -------------------------------------
extern "C" void kernel_launch(void* const* d_in, const int* in_sizes, int n_in,
                              void* d_out, int out_size)
{
    (void)in_sizes; (void)n_in; (void)out_size;
    const float* x    = (const float*)d_in[0];
    const float* w1   = (const float*)d_in[1];
    const float* g1   = (const float*)d_in[2];
    const float* b1   = (const float*)d_in[3];
    const float* m1   = (const float*)d_in[4];
    const float* v1   = (const float*)d_in[5];
    const float* w2   = (const float*)d_in[6];
    const float* g2   = (const float*)d_in[7];
    const float* b2   = (const float*)d_in[8];
    const float* m2   = (const float*)d_in[9];
    const float* v2   = (const float*)d_in[10];
    const float* w3   = (const float*)d_in[11];
    const float* g3   = (const float*)d_in[12];
    const float* b3   = (const float*)d_in[13];
    const float* m3   = (const float*)d_in[14];
    const float* v3   = (const float*)d_in[15];
    const float* wq   = (const float*)d_in[16];
    const float* bq   = (const float*)d_in[17];
    const float* wk   = (const float*)d_in[18];
    const float* bk   = (const float*)d_in[19];
    const float* wv   = (const float*)d_in[20];
    const float* bv   = (const float*)d_in[21];
    const float* wp   = (const float*)d_in[22];
    const float* bp   = (const float*)d_in[23];
    const float* relh = (const float*)d_in[24];
    const float* relw = (const float*)d_in[25];
    const float* efh  = (const float*)d_in[26];
    const float* efw  = (const float*)d_in[27];
    float* out = (float*)d_out;

    float *px1, *pq, *pk, *pv, *pp, *pRh, *pRw, *pABh, *pABw, *pPA, *pPB;
    float *po1, *po2, *pop, *pmp, *plp;
    cudaGetSymbolAddress((void**)&px1, d_x1);
    cudaGetSymbolAddress((void**)&pq,  d_q);
    cudaGetSymbolAddress((void**)&pk,  d_k);
    cudaGetSymbolAddress((void**)&pv,  d_v);
    cudaGetSymbolAddress((void**)&pp,  d_p);
    cudaGetSymbolAddress((void**)&pRh, d_Rh);
    cudaGetSymbolAddress((void**)&pRw, d_Rw);
    cudaGetSymbolAddress((void**)&pABh, d_ABh);
    cudaGetSymbolAddress((void**)&pABw, d_ABw);
    cudaGetSymbolAddress((void**)&pPA, d_PA);
    cudaGetSymbolAddress((void**)&pPB, d_PB);
    cudaGetSymbolAddress((void**)&po1, d_o1);
    cudaGetSymbolAddress((void**)&po2, d_o2);
    cudaGetSymbolAddress((void**)&pop, d_op);
    cudaGetSymbolAddress((void**)&pmp, d_mp);
    cudaGetSymbolAddress((void**)&plp, d_lp);

    cudaFuncSetAttribute(flash_kernel,
        cudaFuncAttributeMaxDynamicSharedMemorySize, FL_SM_FLOATS * 4);

    dim3 g100_2(100, 2), g100_4(100, 4), gfl(100, SPLIT);

    // x1 = SiLU(BN(w1 @ x))
    gemm_epi<2, false, false><<<g100_2, 256>>>(w1, x, px1, NC, ND,
        nullptr, g1, b1, m1, v1, nullptr);
    // q, k, v, p projections (+bias)
    gemm_epi<1, false, false><<<g100_2, 256>>>(wq, px1, pq, NC, NC,
        bq, nullptr, nullptr, nullptr, nullptr, nullptr);
    gemm_epi<1, false, false><<<g100_2, 256>>>(wk, px1, pk, NC, NC,
        bk, nullptr, nullptr, nullptr, nullptr, nullptr);
    gemm_epi<1, false, false><<<g100_2, 256>>>(wv, px1, pv, NC, NC,
        bv, nullptr, nullptr, nullptr, nullptr, nullptr);
    gemm_epi<1, false, false><<<g100_2, 256>>>(wp, px1, pp, NC, NC,
        bp, nullptr, nullptr, nullptr, nullptr, nullptr);
    // Rh = rel_h^T q, Rw = rel_w^T q   [80, 6400]
    gemm_epi<0, true, false><<<g100_2, 256>>>(relh, pq, pRh, NH, NC,
        nullptr, nullptr, nullptr, nullptr, nullptr, nullptr);
    gemm_epi<0, true, false><<<g100_2, 256>>>(relw, pq, pRw, NH, NC,
        nullptr, nullptr, nullptr, nullptr, nullptr, nullptr);
    // branch-2 separable logits: ABh = ef_h^T p, ABw = ef_w^T p
    gemm_epi<0, true, false><<<g100_2, 256>>>(efh, pp, pABh, NH, NC,
        nullptr, nullptr, nullptr, nullptr, nullptr, nullptr);
    gemm_epi<0, true, false><<<g100_2, 256>>>(efw, pp, pABw, NH, NC,
        nullptr, nullptr, nullptr, nullptr, nullptr, nullptr);
    // factored softmaxes
    softmax80<<<25, 256>>>(pABh, pPA);
    softmax80<<<25, 256>>>(pABw, pPB);
    // out2 = ef_h @ PA + ef_w @ PB
    gemm_epi<0, false, false><<<g100_2, 256>>>(efh, pPA, po2, NC, NH,
        nullptr, nullptr, nullptr, nullptr, nullptr, nullptr);
    gemm_epi<0, false, true><<<g100_2, 256>>>(efw, pPB, po2, NC, NH,
        nullptr, nullptr, nullptr, nullptr, nullptr, nullptr);
    // branch-1 flash attention (split-j) -> partials -> combine -> out1
    flash_kernel<<<gfl, 256, FL_SM_FLOATS * 4>>>(pq, pk, pv, pRh, pRw,
        pop, pmp, plp);
    combine_kernel<<<25, 256>>>(pop, pmp, plp, po1);
    // out = x + SiLU(BN(w2 @ out1)) + SiLU(BN(w3 @ out2))
    gemm_epi<3, false, false><<<g100_4, 256>>>(w2, po1, out, ND, NC,
        nullptr, g2, b2, m2, v2, x);
    gemm_epi<2, false, true><<<g100_4, 256>>>(w3, po2, out, ND, NC,
        nullptr, g3, b3, m3, v3, nullptr);
}

// round 3
// speedup vs baseline: 2.9453x; 2.3789x over previous
#include <cuda_runtime.h>
#include <cuda_bf16.h>
#include <cstdint>

#define EPS 1e-5f
#define HW 6400
#define NC 128
#define ND 256
#define NH 80
#define SPLIT 3

// ---------------- packed fp32x2 helpers (for the GEMM chain) -----------------
__device__ __forceinline__ void fma2(unsigned long long& d,
                                     unsigned long long a, unsigned long long b) {
    asm("fma.rn.f32x2 %0, %1, %2, %0;" : "+l"(d) : "l"(a), "l"(b));
}
__device__ __forceinline__ float2 upk2(unsigned long long v) {
    float2 t;
    asm("mov.b64 {%0,%1}, %2;" : "=f"(t.x), "=f"(t.y) : "l"(v));
    return t;
}

// ---------------- tensor-core helpers ----------------------------------------
__device__ __forceinline__ void ldsm4(uint32_t& r0, uint32_t& r1,
                                      uint32_t& r2, uint32_t& r3, uint32_t a) {
    asm volatile("ldmatrix.sync.aligned.m8n8.x4.shared.b16 {%0,%1,%2,%3},[%4];"
        : "=r"(r0), "=r"(r1), "=r"(r2), "=r"(r3) : "r"(a));
}
__device__ __forceinline__ void ldsm4t(uint32_t& r0, uint32_t& r1,
                                       uint32_t& r2, uint32_t& r3, uint32_t a) {
    asm volatile("ldmatrix.sync.aligned.m8n8.x4.trans.shared.b16 {%0,%1,%2,%3},[%4];"
        : "=r"(r0), "=r"(r1), "=r"(r2), "=r"(r3) : "r"(a));
}
__device__ __forceinline__ void mma_bf16(float* d, uint32_t a0, uint32_t a1,
                                         uint32_t a2, uint32_t a3,
                                         uint32_t b0, uint32_t b1) {
    asm volatile("mma.sync.aligned.m16n8k16.row.col.f32.bf16.bf16.f32 "
        "{%0,%1,%2,%3},{%4,%5,%6,%7},{%8,%9},{%0,%1,%2,%3};"
        : "+f"(d[0]), "+f"(d[1]), "+f"(d[2]), "+f"(d[3])
        : "r"(a0), "r"(a1), "r"(a2), "r"(a3), "r"(b0), "r"(b1));
}

// ---------------- scratch (static device globals; no allocation) -------------
__device__ float d_x1 [NC*HW];
__device__ float d_q  [NC*HW];
__device__ float d_k  [NC*HW];
__device__ float d_v  [NC*HW];
__device__ float d_p  [NC*HW];
__device__ float d_Rh [NH*HW];
__device__ float d_Rw [NH*HW];
__device__ float d_ABh[NH*HW];
__device__ float d_ABw[NH*HW];
__device__ float d_PA [NH*HW];
__device__ float d_PB [NH*HW];
__device__ float d_o1 [NC*HW];
__device__ float d_o2 [NC*HW];
__device__ float d_op [SPLIT*NC*HW];
__device__ float d_mp [SPLIT*HW];
__device__ float d_lp [SPLIT*HW];

// ---------------- generic tiled SGEMM with fused epilogues -------------------
template<int EPI, bool TRANSA, bool ACCUM>
__global__ void __launch_bounds__(256) gemm_epi(
    const float* __restrict__ A, const float* __restrict__ B,
    float* __restrict__ C, int M, int K,
    const float* __restrict__ bias,
    const float* __restrict__ g, const float* __restrict__ bb,
    const float* __restrict__ mm, const float* __restrict__ vv,
    const float* __restrict__ resid)
{
    __shared__ float As[16 * 136];
    __shared__ float Bs[16 * 68];
    const int tid = threadIdx.x;
    const int ty = tid >> 4, tx = tid & 15;
    const int m0 = blockIdx.y * 64, n0 = blockIdx.x * 64;

    float acc[4][4];

    if (!TRANSA) {
        unsigned long long acc2[4][2];
        #pragma unroll
        for (int a = 0; a < 4; a++) { acc2[a][0] = 0ull; acc2[a][1] = 0ull; }

        for (int k0 = 0; k0 < K; k0 += 16) {
            {
                int mA = tid >> 2;
                int kA = (tid & 3) << 2;
                int gm = m0 + mA;
                float4 a4 = make_float4(0.f, 0.f, 0.f, 0.f);
                if (gm < M) a4 = *(const float4*)&A[gm * K + k0 + kA];
                float av[4] = {a4.x, a4.y, a4.z, a4.w};
                #pragma unroll
                for (int i = 0; i < 4; i++) {
                    As[(kA + i) * 136 + 2 * mA]     = av[i];
                    As[(kA + i) * 136 + 2 * mA + 1] = av[i];
                }
            }
            {
                int kB = tid >> 4;
                int n4 = (tid & 15) << 2;
                *(float4*)&Bs[kB * 68 + n4] = *(const float4*)&B[(k0 + kB) * HW + n0 + n4];
            }
            __syncthreads();
            #pragma unroll
            for (int kk = 0; kk < 16; ++kk) {
                ulonglong2 ad0 = *(const ulonglong2*)&As[kk * 136 + ty * 8];
                ulonglong2 ad1 = *(const ulonglong2*)&As[kk * 136 + ty * 8 + 4];
                ulonglong2 bp  = *(const ulonglong2*)&Bs[kk * 68 + tx * 4];
                fma2(acc2[0][0], ad0.x, bp.x); fma2(acc2[0][1], ad0.x, bp.y);
                fma2(acc2[1][0], ad0.y, bp.x); fma2(acc2[1][1], ad0.y, bp.y);
                fma2(acc2[2][0], ad1.x, bp.x); fma2(acc2[2][1], ad1.x, bp.y);
                fma2(acc2[3][0], ad1.y, bp.x); fma2(acc2[3][1], ad1.y, bp.y);
            }
            __syncthreads();
        }
        #pragma unroll
        for (int a = 0; a < 4; a++) {
            float2 lo = upk2(acc2[a][0]);
            float2 hi = upk2(acc2[a][1]);
            acc[a][0] = lo.x; acc[a][1] = lo.y; acc[a][2] = hi.x; acc[a][3] = hi.y;
        }
    } else {
        #pragma unroll
        for (int a = 0; a < 4; a++)
            #pragma unroll
            for (int b = 0; b < 4; b++) acc[a][b] = 0.f;

        for (int k0 = 0; k0 < K; k0 += 16) {
            {
                int kA = tid >> 4;
                int m4 = (tid & 15) << 2;
                float4 a4 = make_float4(0.f, 0.f, 0.f, 0.f);
                if (m0 + m4 < M) a4 = *(const float4*)&A[(k0 + kA) * M + m0 + m4];
                *(float4*)&As[kA * 68 + m4] = a4;
            }
            {
                int kB = tid >> 4;
                int n4 = (tid & 15) << 2;
                *(float4*)&Bs[kB * 68 + n4] = *(const float4*)&B[(k0 + kB) * HW + n0 + n4];
            }
            __syncthreads();
            #pragma unroll
            for (int kk = 0; kk < 16; ++kk) {
                float4 av = *(float4*)&As[kk * 68 + ty * 4];
                float4 bv = *(float4*)&Bs[kk * 68 + tx * 4];
                float am[4] = {av.x, av.y, av.z, av.w};
                float bn[4] = {bv.x, bv.y, bv.z, bv.w};
                #pragma unroll
                for (int a = 0; a < 4; a++)
                    #pragma unroll
                    for (int b = 0; b < 4; b++) acc[a][b] += am[a] * bn[b];
            }
            __syncthreads();
        }
    }

    #pragma unroll
    for (int a = 0; a < 4; a++) {
        int gm = m0 + ty * 4 + a;
        if (gm >= M) continue;
        float sc = 0.f, sh = 0.f;
        if (EPI >= 2) {
            sc = g[gm] * rsqrtf(vv[gm] + EPS);
            sh = bb[gm] - mm[gm] * sc;
        }
        float4 r;
        float* rp = &r.x;
        #pragma unroll
        for (int b = 0; b < 4; b++) {
            float val = acc[a][b];
            if (EPI == 1) val += bias[gm];
            if (EPI >= 2) {
                val = val * sc + sh;
                val = val / (1.f + __expf(-val));   // SiLU
            }
            rp[b] = val;
        }
        int idx = gm * HW + n0 + tx * 4;
        if (EPI == 3) {
            float4 x4 = *(const float4*)&resid[idx];
            r.x += x4.x; r.y += x4.y; r.z += x4.z; r.w += x4.w;
        }
        if (ACCUM) {
            float4 c4 = *(float4*)&C[idx];
            r.x += c4.x; r.y += c4.y; r.z += c4.z; r.w += c4.w;
        }
        *(float4*)&C[idx] = r;
    }
}

// ---------------- per-column softmax over 80 rows (for branch 2) -------------
__global__ void softmax80(const float* __restrict__ in, float* __restrict__ out)
{
    int i = blockIdx.x * blockDim.x + threadIdx.x;
    if (i >= HW) return;
    float mx = -1e30f;
    for (int t = 0; t < NH; ++t) mx = fmaxf(mx, in[t * HW + i]);
    float s = 0.f;
    for (int t = 0; t < NH; ++t) s += __expf(in[t * HW + i] - mx);
    float inv = 1.f / s;
    for (int t = 0; t < NH; ++t) out[t * HW + i] = __expf(in[t * HW + i] - mx) * inv;
}

// ---------------- branch-1 flash attention (bf16 mma.sync + split-j) ---------
// smem byte layout (per CTA)
#define QS_OFF   0               // bf16 [128][72]
#define KS_OFF   18432           // bf16 [128][72]
#define VS_OFF   36864           // bf16 [128][72]
#define PS_OFF   55296           // bf16 [64][72]
#define SS_OFF   64512           // f32  [64][72]
#define RWS_OFF  82944           // f32  [64][68]
#define RHS_OFF  100352          // f32  [2][68]
#define MR_OFF   100896          // f32  [64]
#define LR_OFF   101152
#define FR_OFF   101408
#define FL_SM_BYTES 101760

__global__ void __launch_bounds__(256, 2) flash_kernel(
    const float* __restrict__ q, const float* __restrict__ k,
    const float* __restrict__ v, const float* __restrict__ Rh,
    const float* __restrict__ Rw, float* __restrict__ op,
    float* __restrict__ mp, float* __restrict__ lp)
{
    extern __shared__ char smc[];
    __nv_bfloat16* Qs = (__nv_bfloat16*)(smc + QS_OFF);
    __nv_bfloat16* Ks = (__nv_bfloat16*)(smc + KS_OFF);
    __nv_bfloat16* Vs = (__nv_bfloat16*)(smc + VS_OFF);
    __nv_bfloat16* Ps = (__nv_bfloat16*)(smc + PS_OFF);
    float* Ss   = (float*)(smc + SS_OFF);
    float* Rws  = (float*)(smc + RWS_OFF);
    float* Rhs  = (float*)(smc + RHS_OFF);
    float* mrow = (float*)(smc + MR_OFF);
    float* lrow = (float*)(smc + LR_OFF);
    float* frow = (float*)(smc + FR_OFF);

    const int tid  = threadIdx.x;
    const int wid  = tid >> 5, lane = tid & 31;
    const int lr   = lane & 7, gq = lane >> 3;
    const int i0   = blockIdx.x * 64;
    const int spl  = blockIdx.y;
    const int t0   = (spl * 100) / SPLIT;
    const int t1   = ((spl + 1) * 100) / SPLIT;
    const int h0   = i0 / 80;
    const int i0w  = (wid & 3) * 16;
    const int jbase = (wid >> 2) * 32;
    const int cbase = (wid >> 2) * 64;

    const uint32_t qsb = (uint32_t)__cvta_generic_to_shared(Qs);
    const uint32_t ksb = (uint32_t)__cvta_generic_to_shared(Ks);
    const uint32_t vsb = (uint32_t)__cvta_generic_to_shared(Vs);
    const uint32_t psb = (uint32_t)__cvta_generic_to_shared(Ps);

    {   // Q tile: bf16 [c][i], stride 72
        int cr = tid >> 4, i4 = (tid & 15) << 2;
        #pragma unroll
        for (int it = 0; it < 8; ++it) {
            int c = cr + it * 16;
            float4 t = *(const float4*)&q[c * HW + i0 + i4];
            __nv_bfloat162* dst = (__nv_bfloat162*)&Qs[c * 72 + i4];
            dst[0] = __floats2bfloat162_rn(t.x, t.y);
            dst[1] = __floats2bfloat162_rn(t.z, t.w);
        }
    }
    if (tid < 64) { mrow[tid] = -1e30f; lrow[tid] = 0.f; }

    float d[8][4];
    #pragma unroll
    for (int nt = 0; nt < 8; ++nt)
        #pragma unroll
        for (int e = 0; e < 4; ++e) d[nt][e] = 0.f;

    __syncthreads();

    for (int t = t0; t < t1; ++t) {
        const int j0 = t * 64;
        {   // K, V tiles bf16 [c][j]
            int cr = tid >> 4, j4 = (tid & 15) << 2;
            #pragma unroll
            for (int it = 0; it < 8; ++it) {
                int c = cr + it * 16;
                float4 a = *(const float4*)&k[c * HW + j0 + j4];
                __nv_bfloat162* dk = (__nv_bfloat162*)&Ks[c * 72 + j4];
                dk[0] = __floats2bfloat162_rn(a.x, a.y);
                dk[1] = __floats2bfloat162_rn(a.z, a.w);
                float4 b = *(const float4*)&v[c * HW + j0 + j4];
                __nv_bfloat162* dv = (__nv_bfloat162*)&Vs[c * 72 + j4];
                dv[0] = __floats2bfloat162_rn(b.x, b.y);
                dv[1] = __floats2bfloat162_rn(b.z, b.w);
            }
        }
        // positional bias tiles: Rws[64 i][64 j], Rhs[2][64]
        #pragma unroll
        for (int e = 0; e < 4; ++e) {
            int ee = tid + e * 256;
            int row = ee >> 4, c4 = (ee & 15) << 2;
            int wr = (i0 + row) % 80;
            *(float4*)&Rws[row * 68 + c4] = *(const float4*)&Rw[wr * HW + j0 + c4];
        }
        if (tid < 128) {
            int sel = tid >> 6, col = tid & 63;
            int hh = sel ? (i0 + 63) / 80 : h0;
            Rhs[sel * 68 + col] = Rh[hh * HW + j0 + col];
        }
        __syncthreads();

        // ---- QK^T on tensor cores ----
        float sf[4][4];
        #pragma unroll
        for (int nt = 0; nt < 4; ++nt)
            #pragma unroll
            for (int e = 0; e < 4; ++e) sf[nt][e] = 0.f;

        #pragma unroll
        for (int ks = 0; ks < 8; ++ks) {
            int k0 = ks * 16;
            uint32_t a0, a1, a2, a3;
            ldsm4t(a0, a1, a2, a3,
                   qsb + (uint32_t)(((k0 + lr + (gq >> 1) * 8) * 72 + i0w + (gq & 1) * 8) * 2));
            #pragma unroll
            for (int np = 0; np < 2; ++np) {
                int jb = jbase + np * 16;
                uint32_t b0, b1, b2, b3;
                ldsm4t(b0, b1, b2, b3,
                       ksb + (uint32_t)(((k0 + lr + (gq & 1) * 8) * 72 + jb + (gq >> 1) * 8) * 2));
                mma_bf16(sf[np * 2],     a0, a1, a2, a3, b0, b1);
                mma_bf16(sf[np * 2 + 1], a0, a1, a2, a3, b2, b3);
            }
        }
        {   // store S fragments to smem (fp32)
            int row = i0w + (lane >> 2);
            int cc = 2 * (lane & 3);
            #pragma unroll
            for (int nt = 0; nt < 4; ++nt) {
                int col = jbase + nt * 8 + cc;
                *(float2*)&Ss[row * 72 + col]       = make_float2(sf[nt][0], sf[nt][1]);
                *(float2*)&Ss[(row + 8) * 72 + col] = make_float2(sf[nt][2], sf[nt][3]);
            }
        }
        __syncthreads();

        // ---- online softmax (warp w owns rows w*8..w*8+7), write P as bf16 ----
        #pragma unroll
        for (int r8 = 0; r8 < 8; ++r8) {
            int r = wid * 8 + r8;
            int rs = (((i0 + r) / 80) != h0) ? 1 : 0;
            float v1 = Ss[r * 72 + lane]      + Rhs[rs * 68 + lane]      + Rws[r * 68 + lane];
            float v2 = Ss[r * 72 + 32 + lane] + Rhs[rs * 68 + 32 + lane] + Rws[r * 68 + 32 + lane];
            float tm = fmaxf(v1, v2);
            #pragma unroll
            for (int off = 16; off; off >>= 1)
                tm = fmaxf(tm, __shfl_xor_sync(0xffffffffu, tm, off));
            float mold = mrow[r];
            float nm = fmaxf(mold, tm);
            float e1 = __expf(v1 - nm), e2 = __expf(v2 - nm);
            float ssum = e1 + e2;
            #pragma unroll
            for (int off = 16; off; off >>= 1)
                ssum += __shfl_xor_sync(0xffffffffu, ssum, off);
            Ps[r * 72 + lane]      = __float2bfloat16(e1);
            Ps[r * 72 + 32 + lane] = __float2bfloat16(e2);
            if (lane == 0) {
                float f = __expf(mold - nm);
                lrow[r] = lrow[r] * f + ssum;
                mrow[r] = nm;
                frow[r] = f;
            }
        }
        __syncthreads();

        // ---- rescale O, then P @ V^T on tensor cores ----
        {
            float f0 = frow[i0w + (lane >> 2)];
            float f1 = frow[i0w + 8 + (lane >> 2)];
            #pragma unroll
            for (int nt = 0; nt < 8; ++nt) {
                d[nt][0] *= f0; d[nt][1] *= f0;
                d[nt][2] *= f1; d[nt][3] *= f1;
            }
        }
        #pragma unroll
        for (int ks = 0; ks < 4; ++ks) {
            int j0s = ks * 16;
            uint32_t a0, a1, a2, a3;
            ldsm4(a0, a1, a2, a3,
                  psb + (uint32_t)(((i0w + lr + (gq & 1) * 8) * 72 + j0s + (gq >> 1) * 8) * 2));
            #pragma unroll
            for (int np = 0; np < 4; ++np) {
                int cb = cbase + np * 16;
                uint32_t b0, b1, b2, b3;
                ldsm4(b0, b1, b2, b3,
                      vsb + (uint32_t)(((cb + lr + (gq >> 1) * 8) * 72 + j0s + (gq & 1) * 8) * 2));
                mma_bf16(d[np * 2],     a0, a1, a2, a3, b0, b1);
                mma_bf16(d[np * 2 + 1], a0, a1, a2, a3, b2, b3);
            }
        }
        __syncthreads();
    }

    // emit unnormalized partials + (m, l)
    {
        int row0 = i0w + (lane >> 2);
        int cc = 2 * (lane & 3);
        #pragma unroll
        for (int nt = 0; nt < 8; ++nt) {
            int c = cbase + nt * 8 + cc;
            op[(spl * NC + c)     * HW + i0 + row0]     = d[nt][0];
            op[(spl * NC + c + 1) * HW + i0 + row0]     = d[nt][1];
            op[(spl * NC + c)     * HW + i0 + row0 + 8] = d[nt][2];
            op[(spl * NC + c + 1) * HW + i0 + row0 + 8] = d[nt][3];
        }
    }
    if (tid < 64) {
        mp[spl * HW + i0 + tid] = mrow[tid];
        lp[spl * HW + i0 + tid] = lrow[tid];
    }
}

// ---------------- split-j combine: out1 = sum_s o_s * e^{m_s - M} / L --------
__global__ void combine_kernel(const float* __restrict__ op,
                               const float* __restrict__ mp,
                               const float* __restrict__ lp,
                               float* __restrict__ out1)
{
    int i = blockIdx.x * blockDim.x + threadIdx.x;
    if (i >= HW) return;
    float m0 = mp[i], m1 = mp[HW + i], m2 = mp[2 * HW + i];
    float M = fmaxf(m0, fmaxf(m1, m2));
    float w0 = __expf(m0 - M), w1 = __expf(m1 - M), w2 = __expf(m2 - M);
    float L = lp[i] * w0 + lp[HW + i] * w1 + lp[2 * HW + i] * w2;
    float inv = 1.f / L;
    for (int c = 0; c < NC; ++c) {
        float s = op[c * HW + i] * w0
                + op[(NC + c) * HW + i] * w1
                + op[(2 * NC + c) * HW + i] * w2;
        out1[c * HW + i] = s * inv;
    }
}

// -------------------------------- launch -------------------------------------
extern "C" void kernel_launch(void* const* d_in, const int* in_sizes, int n_in,
                              void* d_out, int out_size)
{
    (void)in_sizes; (void)n_in; (void)out_size;
    const float* x    = (const float*)d_in[0];
    const float* w1   = (const float*)d_in[1];
    const float* g1   = (const float*)d_in[2];
    const float* b1   = (const float*)d_in[3];
    const float* m1   = (const float*)d_in[4];
    const float* v1   = (const float*)d_in[5];
    const float* w2   = (const float*)d_in[6];
    const float* g2   = (const float*)d_in[7];
    const float* b2   = (const float*)d_in[8];
    const float* m2   = (const float*)d_in[9];
    const float* v2   = (const float*)d_in[10];
    const float* w3   = (const float*)d_in[11];
    const float* g3   = (const float*)d_in[12];
    const float* b3   = (const float*)d_in[13];
    const float* m3   = (const float*)d_in[14];
    const float* v3   = (const float*)d_in[15];
    const float* wq   = (const float*)d_in[16];
    const float* bq   = (const float*)d_in[17];
    const float* wk   = (const float*)d_in[18];
    const float* bk   = (const float*)d_in[19];
    const float* wv   = (const float*)d_in[20];
    const float* bv   = (const float*)d_in[21];
    const float* wp   = (const float*)d_in[22];
    const float* bp   = (const float*)d_in[23];
    const float* relh = (const float*)d_in[24];
    const float* relw = (const float*)d_in[25];
    const float* efh  = (const float*)d_in[26];
    const float* efw  = (const float*)d_in[27];
    float* out = (float*)d_out;

    float *px1, *pq, *pk, *pv, *pp, *pRh, *pRw, *pABh, *pABw, *pPA, *pPB;
    float *po1, *po2, *pop, *pmp, *plp;
    cudaGetSymbolAddress((void**)&px1, d_x1);
    cudaGetSymbolAddress((void**)&pq,  d_q);
    cudaGetSymbolAddress((void**)&pk,  d_k);
    cudaGetSymbolAddress((void**)&pv,  d_v);
    cudaGetSymbolAddress((void**)&pp,  d_p);
    cudaGetSymbolAddress((void**)&pRh, d_Rh);
    cudaGetSymbolAddress((void**)&pRw, d_Rw);
    cudaGetSymbolAddress((void**)&pABh, d_ABh);
    cudaGetSymbolAddress((void**)&pABw, d_ABw);
    cudaGetSymbolAddress((void**)&pPA, d_PA);
    cudaGetSymbolAddress((void**)&pPB, d_PB);
    cudaGetSymbolAddress((void**)&po1, d_o1);
    cudaGetSymbolAddress((void**)&po2, d_o2);
    cudaGetSymbolAddress((void**)&pop, d_op);
    cudaGetSymbolAddress((void**)&pmp, d_mp);
    cudaGetSymbolAddress((void**)&plp, d_lp);

    cudaFuncSetAttribute(flash_kernel,
        cudaFuncAttributeMaxDynamicSharedMemorySize, FL_SM_BYTES);

    dim3 g100_2(100, 2), g100_4(100, 4), gfl(100, SPLIT);

    // x1 = SiLU(BN(w1 @ x))
    gemm_epi<2, false, false><<<g100_2, 256>>>(w1, x, px1, NC, ND,
        nullptr, g1, b1, m1, v1, nullptr);
    // q, k, v, p projections (+bias)
    gemm_epi<1, false, false><<<g100_2, 256>>>(wq, px1, pq, NC, NC,
        bq, nullptr, nullptr, nullptr, nullptr, nullptr);
    gemm_epi<1, false, false><<<g100_2, 256>>>(wk, px1, pk, NC, NC,
        bk, nullptr, nullptr, nullptr, nullptr, nullptr);
    gemm_epi<1, false, false><<<g100_2, 256>>>(wv, px1, pv, NC, NC,
        bv, nullptr, nullptr, nullptr, nullptr, nullptr);
    gemm_epi<1, false, false><<<g100_2, 256>>>(wp, px1, pp, NC, NC,
        bp, nullptr, nullptr, nullptr, nullptr, nullptr);
    // Rh = rel_h^T q, Rw = rel_w^T q   [80, 6400]
    gemm_epi<0, true, false><<<g100_2, 256>>>(relh, pq, pRh, NH, NC,
        nullptr, nullptr, nullptr, nullptr, nullptr, nullptr);
    gemm_epi<0, true, false><<<g100_2, 256>>>(relw, pq, pRw, NH, NC,
        nullptr, nullptr, nullptr, nullptr, nullptr, nullptr);
    // branch-2 separable logits: ABh = ef_h^T p, ABw = ef_w^T p
    gemm_epi<0, true, false><<<g100_2, 256>>>(efh, pp, pABh, NH, NC,
        nullptr, nullptr, nullptr, nullptr, nullptr, nullptr);
    gemm_epi<0, true, false><<<g100_2, 256>>>(efw, pp, pABw, NH, NC,
        nullptr, nullptr, nullptr, nullptr, nullptr, nullptr);
    // factored softmaxes
    softmax80<<<25, 256>>>(pABh, pPA);
    softmax80<<<25, 256>>>(pABw, pPB);
    // out2 = ef_h @ PA + ef_w @ PB
    gemm_epi<0, false, false><<<g100_2, 256>>>(efh, pPA, po2, NC, NH,
        nullptr, nullptr, nullptr, nullptr, nullptr, nullptr);
    gemm_epi<0, false, true><<<g100_2, 256>>>(efw, pPB, po2, NC, NH,
        nullptr, nullptr, nullptr, nullptr, nullptr, nullptr);
    // branch-1 flash attention (bf16 tensor cores, split-j) -> combine -> out1
    flash_kernel<<<gfl, 256, FL_SM_BYTES>>>(pq, pk, pv, pRh, pRw,
        pop, pmp, plp);
    combine_kernel<<<25, 256>>>(pop, pmp, plp, po1);
    // out = x + SiLU(BN(w2 @ out1)) + SiLU(BN(w3 @ out2))
    gemm_epi<3, false, false><<<g100_4, 256>>>(w2, po1, out, ND, NC,
        nullptr, g2, b2, m2, v2, x);
    gemm_epi<2, false, true><<<g100_4, 256>>>(w3, po2, out, ND, NC,
        nullptr, g3, b3, m3, v3, nullptr);
}

// round 5
// speedup vs baseline: 3.6907x; 1.2531x over previous
#include <cuda_runtime.h>
#include <cuda_bf16.h>
#include <cstdint>

#define EPS 1e-5f
#define HW 6400
#define NC 128
#define ND 256
#define NH 80
#define SPLIT 3

// ---------------- tensor-core helpers ----------------------------------------
__device__ __forceinline__ void ldsm4(uint32_t& r0, uint32_t& r1,
                                      uint32_t& r2, uint32_t& r3, uint32_t a) {
    asm volatile("ldmatrix.sync.aligned.m8n8.x4.shared.b16 {%0,%1,%2,%3},[%4];"
        : "=r"(r0), "=r"(r1), "=r"(r2), "=r"(r3) : "r"(a));
}
__device__ __forceinline__ void ldsm4t(uint32_t& r0, uint32_t& r1,
                                       uint32_t& r2, uint32_t& r3, uint32_t a) {
    asm volatile("ldmatrix.sync.aligned.m8n8.x4.trans.shared.b16 {%0,%1,%2,%3},[%4];"
        : "=r"(r0), "=r"(r1), "=r"(r2), "=r"(r3) : "r"(a));
}
__device__ __forceinline__ void mma_bf16(float* d, uint32_t a0, uint32_t a1,
                                         uint32_t a2, uint32_t a3,
                                         uint32_t b0, uint32_t b1) {
    asm volatile("mma.sync.aligned.m16n8k16.row.col.f32.bf16.bf16.f32 "
        "{%0,%1,%2,%3},{%4,%5,%6,%7},{%8,%9},{%0,%1,%2,%3};"
        : "+f"(d[0]), "+f"(d[1]), "+f"(d[2]), "+f"(d[3])
        : "r"(a0), "r"(a1), "r"(a2), "r"(a3), "r"(b0), "r"(b1));
}
__device__ __forceinline__ void mma_tf32(float* d, uint32_t a0, uint32_t a1,
                                         uint32_t a2, uint32_t a3,
                                         uint32_t b0, uint32_t b1) {
    asm volatile("mma.sync.aligned.m16n8k8.row.col.f32.tf32.tf32.f32 "
        "{%0,%1,%2,%3},{%4,%5,%6,%7},{%8,%9},{%0,%1,%2,%3};"
        : "+f"(d[0]), "+f"(d[1]), "+f"(d[2]), "+f"(d[3])
        : "r"(a0), "r"(a1), "r"(a2), "r"(a3), "r"(b0), "r"(b1));
}
__device__ __forceinline__ float tf32r(float x) {
    uint32_t r;
    asm("cvt.rna.tf32.f32 %0, %1;" : "=r"(r) : "f"(x));
    return __uint_as_float(r);
}

// ---------------- scratch (static device globals; no allocation) -------------
__device__ float d_x1 [NC*HW];
__device__ float d_q  [NC*HW];
__device__ float d_k  [NC*HW];
__device__ float d_v  [NC*HW];
__device__ float d_p  [NC*HW];
__device__ float d_Rh [NH*HW];
__device__ float d_Rw [NH*HW];
__device__ float d_ABh[NH*HW];
__device__ float d_ABw[NH*HW];
__device__ float d_PA [NH*HW];
__device__ float d_PB [NH*HW];
__device__ float d_o1 [NC*HW];
__device__ float d_o2 [NC*HW];
__device__ float d_op [SPLIT*NC*HW];
__device__ float d_mp [SPLIT*HW];
__device__ float d_lp [SPLIT*HW];

// ---------------- tf32 tensor-core GEMM with fused epilogues -----------------
// C[m, n over HW] = sum_k A(m,k) * B[k][n]  (+ optional A2*B2 when DUAL)
// A fp32.  AKM=false: A[m*K+k].  AKM=true: A[k*M+m].   B fp32 [k][HW].
// EPI: 0 none, 1 +bias[m], 2 BN+SiLU, 3 BN+SiLU + resid.  ACC: C +=.
template<int EPI, bool AKM, bool ACC, bool DUAL>
__global__ void __launch_bounds__(256) tgemm(
    const float* __restrict__ A, const float* __restrict__ B,
    const float* __restrict__ A2, const float* __restrict__ B2,
    float* __restrict__ C, int M, int K, int K2,
    const float* __restrict__ bias,
    const float* __restrict__ g, const float* __restrict__ bb,
    const float* __restrict__ mm, const float* __restrict__ vv,
    const float* __restrict__ resid)
{
    __shared__ float Wt[64 * 72];   // [k][m] tf32-rounded
    __shared__ float Bt[64 * 72];   // [k][n] tf32-rounded
    const int tid = threadIdx.x;
    const int wid = tid >> 5, lane = tid & 31;
    const int m0 = blockIdx.y * 64, n0 = blockIdx.x * 64;
    const int i0w = (wid & 3) * 16;
    const int jbase = (wid >> 2) * 32;
    const int lrow = lane >> 2, lk = lane & 3;

    float sf[4][4];
    #pragma unroll
    for (int nt = 0; nt < 4; ++nt)
        #pragma unroll
        for (int e = 0; e < 4; ++e) sf[nt][e] = 0.f;

    const int nsrc = DUAL ? 2 : 1;
    for (int src = 0; src < nsrc; ++src) {
        const float* Ap = src ? A2 : A;
        const float* Bp = src ? B2 : B;
        const int    Kp = src ? K2 : K;
        for (int kc = 0; kc < Kp; kc += 64) {
            const int ck = (Kp - kc < 64) ? (Kp - kc) : 64;
            if (AKM) {                        // A[k][M] k-major
                int m4 = (tid & 15) << 2;
                for (int kk = tid >> 4; kk < ck; kk += 16) {
                    float4 a4 = make_float4(0.f, 0.f, 0.f, 0.f);
                    if (m0 + m4 < M)
                        a4 = *(const float4*)&Ap[(size_t)(kc + kk) * M + m0 + m4];
                    float* wp = &Wt[kk * 72 + m4];
                    wp[0] = tf32r(a4.x); wp[1] = tf32r(a4.y);
                    wp[2] = tf32r(a4.z); wp[3] = tf32r(a4.w);
                }
            } else {                          // A[m][K]: transpose on stage
                int m = tid >> 2;
                bool mok = (m0 + m) < M;
                for (int k4 = (tid & 3) << 2; k4 < ck; k4 += 16) {
                    float4 a4 = make_float4(0.f, 0.f, 0.f, 0.f);
                    if (mok) a4 = *(const float4*)&Ap[(size_t)(m0 + m) * Kp + kc + k4];
                    Wt[(k4 + 0) * 72 + m] = tf32r(a4.x);
                    Wt[(k4 + 1) * 72 + m] = tf32r(a4.y);
                    Wt[(k4 + 2) * 72 + m] = tf32r(a4.z);
                    Wt[(k4 + 3) * 72 + m] = tf32r(a4.w);
                }
            }
            {
                int n4 = (tid & 15) << 2;
                for (int kk = tid >> 4; kk < ck; kk += 16) {
                    float4 b4 = *(const float4*)&Bp[(size_t)(kc + kk) * HW + n0 + n4];
                    float* bp = &Bt[kk * 72 + n4];
                    bp[0] = tf32r(b4.x); bp[1] = tf32r(b4.y);
                    bp[2] = tf32r(b4.z); bp[3] = tf32r(b4.w);
                }
            }
            __syncthreads();
            const int nks = ck >> 3;
            for (int ks = 0; ks < nks; ++ks) {
                int k0 = ks * 8;
                uint32_t a0 = __float_as_uint(Wt[(k0 + lk) * 72 + i0w + lrow]);
                uint32_t a1 = __float_as_uint(Wt[(k0 + lk) * 72 + i0w + lrow + 8]);
                uint32_t a2 = __float_as_uint(Wt[(k0 + lk + 4) * 72 + i0w + lrow]);
                uint32_t a3 = __float_as_uint(Wt[(k0 + lk + 4) * 72 + i0w + lrow + 8]);
                #pragma unroll
                for (int np = 0; np < 4; ++np) {
                    int ncol = jbase + np * 8 + lrow;
                    uint32_t b0 = __float_as_uint(Bt[(k0 + lk) * 72 + ncol]);
                    uint32_t b1 = __float_as_uint(Bt[(k0 + lk + 4) * 72 + ncol]);
                    mma_tf32(sf[np], a0, a1, a2, a3, b0, b1);
                }
            }
            __syncthreads();
        }
    }

    // epilogue: thread owns rows (i0w+lrow, +8), cols jbase+np*8+2*lk (+1)
    const int cc0 = 2 * lk;
    #pragma unroll
    for (int rr = 0; rr < 2; ++rr) {
        int gm = m0 + i0w + lrow + rr * 8;
        if (gm >= M) continue;
        float bsv = 0.f, sc = 0.f, sh = 0.f;
        if (EPI == 1) bsv = bias[gm];
        if (EPI >= 2) {
            sc = g[gm] * rsqrtf(vv[gm] + EPS);
            sh = bb[gm] - mm[gm] * sc;
        }
        #pragma unroll
        for (int nt = 0; nt < 4; ++nt) {
            float e0 = sf[nt][rr * 2 + 0];
            float e1 = sf[nt][rr * 2 + 1];
            if (EPI == 1) { e0 += bsv; e1 += bsv; }
            if (EPI >= 2) {
                e0 = e0 * sc + sh; e1 = e1 * sc + sh;
                e0 = e0 / (1.f + __expf(-e0));
                e1 = e1 / (1.f + __expf(-e1));
            }
            size_t idx = (size_t)gm * HW + n0 + jbase + nt * 8 + cc0;
            if (EPI == 3) {
                float2 x2 = *(const float2*)&resid[idx];
                e0 += x2.x; e1 += x2.y;
            }
            if (ACC) {
                float2 c2 = *(float2*)&C[idx];
                e0 += c2.x; e1 += c2.y;
            }
            *(float2*)&C[idx] = make_float2(e0, e1);
        }
    }
}

// ---------------- per-column softmax over 80 rows (for branch 2) -------------
__global__ void softmax80(const float* __restrict__ in, float* __restrict__ out)
{
    int i = blockIdx.x * blockDim.x + threadIdx.x;
    if (i >= HW) return;
    float mx = -1e30f;
    for (int t = 0; t < NH; ++t) mx = fmaxf(mx, in[t * HW + i]);
    float s = 0.f;
    for (int t = 0; t < NH; ++t) s += __expf(in[t * HW + i] - mx);
    float inv = 1.f / s;
    for (int t = 0; t < NH; ++t) out[t * HW + i] = __expf(in[t * HW + i] - mx) * inv;
}

// ---------------- branch-1 flash attention (bf16 mma.sync + split-j) ---------
#define QS_OFF   0               // bf16 [128][72]
#define KS_OFF   18432           // bf16 [128][72]
#define VS_OFF   36864           // bf16 [128][72]
#define PS_OFF   55296           // bf16 [64][72]
#define SS_OFF   64512           // f32  [64][72]
#define RWS_OFF  82944           // f32  [64][68]
#define RHS_OFF  100352          // f32  [2][68]
#define MR_OFF   100896          // f32  [64]
#define LR_OFF   101152
#define FR_OFF   101408
#define FL_SM_BYTES 101760

__global__ void __launch_bounds__(256, 2) flash_kernel(
    const float* __restrict__ q, const float* __restrict__ k,
    const float* __restrict__ v, const float* __restrict__ Rh,
    const float* __restrict__ Rw, float* __restrict__ op,
    float* __restrict__ mp, float* __restrict__ lp)
{
    extern __shared__ char smc[];
    __nv_bfloat16* Qs = (__nv_bfloat16*)(smc + QS_OFF);
    __nv_bfloat16* Ks = (__nv_bfloat16*)(smc + KS_OFF);
    __nv_bfloat16* Vs = (__nv_bfloat16*)(smc + VS_OFF);
    __nv_bfloat16* Ps = (__nv_bfloat16*)(smc + PS_OFF);
    float* Ss   = (float*)(smc + SS_OFF);
    float* Rws  = (float*)(smc + RWS_OFF);
    float* Rhs  = (float*)(smc + RHS_OFF);
    float* mrow = (float*)(smc + MR_OFF);
    float* lrow = (float*)(smc + LR_OFF);
    float* frow = (float*)(smc + FR_OFF);

    const int tid  = threadIdx.x;
    const int wid  = tid >> 5, lane = tid & 31;
    const int lr   = lane & 7, gq = lane >> 3;
    const int i0   = blockIdx.x * 64;
    const int spl  = blockIdx.y;
    const int t0   = (spl * 100) / SPLIT;
    const int t1   = ((spl + 1) * 100) / SPLIT;
    const int h0   = i0 / 80;
    const int i0w  = (wid & 3) * 16;
    const int jbase = (wid >> 2) * 32;
    const int cbase = (wid >> 2) * 64;

    const uint32_t qsb = (uint32_t)__cvta_generic_to_shared(Qs);
    const uint32_t ksb = (uint32_t)__cvta_generic_to_shared(Ks);
    const uint32_t vsb = (uint32_t)__cvta_generic_to_shared(Vs);
    const uint32_t psb = (uint32_t)__cvta_generic_to_shared(Ps);

    {   // Q tile: bf16 [c][i], stride 72
        int cr = tid >> 4, i4 = (tid & 15) << 2;
        #pragma unroll
        for (int it = 0; it < 8; ++it) {
            int c = cr + it * 16;
            float4 t = *(const float4*)&q[(size_t)c * HW + i0 + i4];
            __nv_bfloat162* dst = (__nv_bfloat162*)&Qs[c * 72 + i4];
            dst[0] = __floats2bfloat162_rn(t.x, t.y);
            dst[1] = __floats2bfloat162_rn(t.z, t.w);
        }
    }
    if (tid < 64) { mrow[tid] = -1e30f; lrow[tid] = 0.f; }

    float d[8][4];
    #pragma unroll
    for (int nt = 0; nt < 8; ++nt)
        #pragma unroll
        for (int e = 0; e < 4; ++e) d[nt][e] = 0.f;

    __syncthreads();

    for (int t = t0; t < t1; ++t) {
        const int j0 = t * 64;
        {   // K, V tiles bf16 [c][j]
            int cr = tid >> 4, j4 = (tid & 15) << 2;
            #pragma unroll
            for (int it = 0; it < 8; ++it) {
                int c = cr + it * 16;
                float4 a = *(const float4*)&k[(size_t)c * HW + j0 + j4];
                __nv_bfloat162* dk = (__nv_bfloat162*)&Ks[c * 72 + j4];
                dk[0] = __floats2bfloat162_rn(a.x, a.y);
                dk[1] = __floats2bfloat162_rn(a.z, a.w);
                float4 b = *(const float4*)&v[(size_t)c * HW + j0 + j4];
                __nv_bfloat162* dv = (__nv_bfloat162*)&Vs[c * 72 + j4];
                dv[0] = __floats2bfloat162_rn(b.x, b.y);
                dv[1] = __floats2bfloat162_rn(b.z, b.w);
            }
        }
        // positional bias tiles: Rws[64 i][64 j], Rhs[2][64]
        #pragma unroll
        for (int e = 0; e < 4; ++e) {
            int ee = tid + e * 256;
            int row = ee >> 4, c4 = (ee & 15) << 2;
            int wr = (i0 + row) % 80;
            *(float4*)&Rws[row * 68 + c4] = *(const float4*)&Rw[wr * HW + j0 + c4];
        }
        if (tid < 128) {
            int sel = tid >> 6, col = tid & 63;
            int hh = sel ? (i0 + 63) / 80 : h0;
            Rhs[sel * 68 + col] = Rh[hh * HW + j0 + col];
        }
        __syncthreads();

        // ---- QK^T on tensor cores ----
        float sf[4][4];
        #pragma unroll
        for (int nt = 0; nt < 4; ++nt)
            #pragma unroll
            for (int e = 0; e < 4; ++e) sf[nt][e] = 0.f;

        #pragma unroll
        for (int ks = 0; ks < 8; ++ks) {
            int k0 = ks * 16;
            uint32_t a0, a1, a2, a3;
            ldsm4t(a0, a1, a2, a3,
                   qsb + (uint32_t)(((k0 + lr + (gq >> 1) * 8) * 72 + i0w + (gq & 1) * 8) * 2));
            #pragma unroll
            for (int np = 0; np < 2; ++np) {
                int jb = jbase + np * 16;
                uint32_t b0, b1, b2, b3;
                ldsm4t(b0, b1, b2, b3,
                       ksb + (uint32_t)(((k0 + lr + (gq & 1) * 8) * 72 + jb + (gq >> 1) * 8) * 2));
                mma_bf16(sf[np * 2],     a0, a1, a2, a3, b0, b1);
                mma_bf16(sf[np * 2 + 1], a0, a1, a2, a3, b2, b3);
            }
        }
        {   // store S fragments to smem (fp32)
            int row = i0w + (lane >> 2);
            int cc = 2 * (lane & 3);
            #pragma unroll
            for (int nt = 0; nt < 4; ++nt) {
                int col = jbase + nt * 8 + cc;
                *(float2*)&Ss[row * 72 + col]       = make_float2(sf[nt][0], sf[nt][1]);
                *(float2*)&Ss[(row + 8) * 72 + col] = make_float2(sf[nt][2], sf[nt][3]);
            }
        }
        __syncthreads();

        // ---- online softmax (warp w owns rows w*8..w*8+7), write P as bf16 ----
        #pragma unroll
        for (int r8 = 0; r8 < 8; ++r8) {
            int r = wid * 8 + r8;
            int rs = (((i0 + r) / 80) != h0) ? 1 : 0;
            float v1 = Ss[r * 72 + lane]      + Rhs[rs * 68 + lane]      + Rws[r * 68 + lane];
            float v2 = Ss[r * 72 + 32 + lane] + Rhs[rs * 68 + 32 + lane] + Rws[r * 68 + 32 + lane];
            float tm = fmaxf(v1, v2);
            #pragma unroll
            for (int off = 16; off; off >>= 1)
                tm = fmaxf(tm, __shfl_xor_sync(0xffffffffu, tm, off));
            float mold = mrow[r];
            float nm = fmaxf(mold, tm);
            float e1 = __expf(v1 - nm), e2 = __expf(v2 - nm);
            float ssum = e1 + e2;
            #pragma unroll
            for (int off = 16; off; off >>= 1)
                ssum += __shfl_xor_sync(0xffffffffu, ssum, off);
            Ps[r * 72 + lane]      = __float2bfloat16(e1);
            Ps[r * 72 + 32 + lane] = __float2bfloat16(e2);
            if (lane == 0) {
                float f = __expf(mold - nm);
                lrow[r] = lrow[r] * f + ssum;
                mrow[r] = nm;
                frow[r] = f;
            }
        }
        __syncthreads();

        // ---- rescale O, then P @ V^T on tensor cores ----
        {
            float f0 = frow[i0w + (lane >> 2)];
            float f1 = frow[i0w + 8 + (lane >> 2)];
            #pragma unroll
            for (int nt = 0; nt < 8; ++nt) {
                d[nt][0] *= f0; d[nt][1] *= f0;
                d[nt][2] *= f1; d[nt][3] *= f1;
            }
        }
        #pragma unroll
        for (int ks = 0; ks < 4; ++ks) {
            int j0s = ks * 16;
            uint32_t a0, a1, a2, a3;
            ldsm4(a0, a1, a2, a3,
                  psb + (uint32_t)(((i0w + lr + (gq & 1) * 8) * 72 + j0s + (gq >> 1) * 8) * 2));
            #pragma unroll
            for (int np = 0; np < 4; ++np) {
                int cb = cbase + np * 16;
                uint32_t b0, b1, b2, b3;
                ldsm4(b0, b1, b2, b3,
                      vsb + (uint32_t)(((cb + lr + (gq >> 1) * 8) * 72 + j0s + (gq & 1) * 8) * 2));
                mma_bf16(d[np * 2],     a0, a1, a2, a3, b0, b1);
                mma_bf16(d[np * 2 + 1], a0, a1, a2, a3, b2, b3);
            }
        }
        __syncthreads();
    }

    // emit unnormalized partials + (m, l)
    {
        int row0 = i0w + (lane >> 2);
        int cc = 2 * (lane & 3);
        #pragma unroll
        for (int nt = 0; nt < 8; ++nt) {
            int c = cbase + nt * 8 + cc;
            op[(spl * NC + c)     * HW + i0 + row0]     = d[nt][0];
            op[(spl * NC + c + 1) * HW + i0 + row0]     = d[nt][1];
            op[(spl * NC + c)     * HW + i0 + row0 + 8] = d[nt][2];
            op[(spl * NC + c + 1) * HW + i0 + row0 + 8] = d[nt][3];
        }
    }
    if (tid < 64) {
        mp[spl * HW + i0 + tid] = mrow[tid];
        lp[spl * HW + i0 + tid] = lrow[tid];
    }
}

// ---------------- split-j combine: out1 = sum_s o_s * e^{m_s - M} / L --------
__global__ void combine_kernel(const float* __restrict__ op,
                               const float* __restrict__ mp,
                               const float* __restrict__ lp,
                               float* __restrict__ out1)
{
    int i = blockIdx.x * blockDim.x + threadIdx.x;
    if (i >= HW) return;
    float m0 = mp[i], m1 = mp[HW + i], m2 = mp[2 * HW + i];
    float M = fmaxf(m0, fmaxf(m1, m2));
    float w0 = __expf(m0 - M), w1 = __expf(m1 - M), w2 = __expf(m2 - M);
    float L = lp[i] * w0 + lp[HW + i] * w1 + lp[2 * HW + i] * w2;
    float inv = 1.f / L;
    for (int c = 0; c < NC; ++c) {
        float s = op[c * HW + i] * w0
                + op[(NC + c) * HW + i] * w1
                + op[(2 * NC + c) * HW + i] * w2;
        out1[c * HW + i] = s * inv;
    }
}

// -------------------------------- launch -------------------------------------
extern "C" void kernel_launch(void* const* d_in, const int* in_sizes, int n_in,
                              void* d_out, int out_size)
{
    (void)in_sizes; (void)n_in; (void)out_size;
    const float* x    = (const float*)d_in[0];
    const float* w1   = (const float*)d_in[1];
    const float* g1   = (const float*)d_in[2];
    const float* b1   = (const float*)d_in[3];
    const float* m1   = (const float*)d_in[4];
    const float* v1   = (const float*)d_in[5];
    const float* w2   = (const float*)d_in[6];
    const float* g2   = (const float*)d_in[7];
    const float* b2   = (const float*)d_in[8];
    const float* m2   = (const float*)d_in[9];
    const float* v2   = (const float*)d_in[10];
    const float* w3   = (const float*)d_in[11];
    const float* g3   = (const float*)d_in[12];
    const float* b3   = (const float*)d_in[13];
    const float* m3   = (const float*)d_in[14];
    const float* v3   = (const float*)d_in[15];
    const float* wq   = (const float*)d_in[16];
    const float* bq   = (const float*)d_in[17];
    const float* wk   = (const float*)d_in[18];
    const float* bk   = (const float*)d_in[19];
    const float* wv   = (const float*)d_in[20];
    const float* bv   = (const float*)d_in[21];
    const float* wp   = (const float*)d_in[22];
    const float* bp   = (const float*)d_in[23];
    const float* relh = (const float*)d_in[24];
    const float* relw = (const float*)d_in[25];
    const float* efh  = (const float*)d_in[26];
    const float* efw  = (const float*)d_in[27];
    float* out = (float*)d_out;

    float *px1, *pq, *pk, *pv, *pp, *pRh, *pRw, *pABh, *pABw, *pPA, *pPB;
    float *po1, *po2, *pop, *pmp, *plp;
    cudaGetSymbolAddress((void**)&px1, d_x1);
    cudaGetSymbolAddress((void**)&pq,  d_q);
    cudaGetSymbolAddress((void**)&pk,  d_k);
    cudaGetSymbolAddress((void**)&pv,  d_v);
    cudaGetSymbolAddress((void**)&pp,  d_p);
    cudaGetSymbolAddress((void**)&pRh, d_Rh);
    cudaGetSymbolAddress((void**)&pRw, d_Rw);
    cudaGetSymbolAddress((void**)&pABh, d_ABh);
    cudaGetSymbolAddress((void**)&pABw, d_ABw);
    cudaGetSymbolAddress((void**)&pPA, d_PA);
    cudaGetSymbolAddress((void**)&pPB, d_PB);
    cudaGetSymbolAddress((void**)&po1, d_o1);
    cudaGetSymbolAddress((void**)&po2, d_o2);
    cudaGetSymbolAddress((void**)&pop, d_op);
    cudaGetSymbolAddress((void**)&pmp, d_mp);
    cudaGetSymbolAddress((void**)&plp, d_lp);

    cudaFuncSetAttribute(flash_kernel,
        cudaFuncAttributeMaxDynamicSharedMemorySize, FL_SM_BYTES);

    dim3 g100_2(100, 2), g100_4(100, 4), gfl(100, SPLIT);

    // x1 = SiLU(BN(w1 @ x))
    tgemm<2, false, false, false><<<g100_2, 256>>>(
        w1, x, nullptr, nullptr, px1, NC, ND, 0,
        nullptr, g1, b1, m1, v1, nullptr);
    // q, k, v, p projections (+bias)
    tgemm<1, false, false, false><<<g100_2, 256>>>(
        wq, px1, nullptr, nullptr, pq, NC, NC, 0,
        bq, nullptr, nullptr, nullptr, nullptr, nullptr);
    tgemm<1, false, false, false><<<g100_2, 256>>>(
        wk, px1, nullptr, nullptr, pk, NC, NC, 0,
        bk, nullptr, nullptr, nullptr, nullptr, nullptr);
    tgemm<1, false, false, false><<<g100_2, 256>>>(
        wv, px1, nullptr, nullptr, pv, NC, NC, 0,
        bv, nullptr, nullptr, nullptr, nullptr, nullptr);
    tgemm<1, false, false, false><<<g100_2, 256>>>(
        wp, px1, nullptr, nullptr, pp, NC, NC, 0,
        bp, nullptr, nullptr, nullptr, nullptr, nullptr);
    // Rh = rel_h^T q, Rw = rel_w^T q   [80, 6400]
    tgemm<0, true, false, false><<<g100_2, 256>>>(
        relh, pq, nullptr, nullptr, pRh, NH, NC, 0,
        nullptr, nullptr, nullptr, nullptr, nullptr, nullptr);
    tgemm<0, true, false, false><<<g100_2, 256>>>(
        relw, pq, nullptr, nullptr, pRw, NH, NC, 0,
        nullptr, nullptr, nullptr, nullptr, nullptr, nullptr);
    // branch-2 separable logits: ABh = ef_h^T p, ABw = ef_w^T p
    tgemm<0, true, false, false><<<g100_2, 256>>>(
        efh, pp, nullptr, nullptr, pABh, NH, NC, 0,
        nullptr, nullptr, nullptr, nullptr, nullptr, nullptr);
    tgemm<0, true, false, false><<<g100_2, 256>>>(
        efw, pp, nullptr, nullptr, pABw, NH, NC, 0,
        nullptr, nullptr, nullptr, nullptr, nullptr, nullptr);
    // factored softmaxes
    softmax80<<<25, 256>>>(pABh, pPA);
    softmax80<<<25, 256>>>(pABw, pPB);
    // out2 = ef_h @ PA + ef_w @ PB  (fused dual GEMM)
    tgemm<0, false, false, true><<<g100_2, 256>>>(
        efh, pPA, efw, pPB, po2, NC, NH, NH,
        nullptr, nullptr, nullptr, nullptr, nullptr, nullptr);
    // branch-1 flash attention (bf16 tensor cores, split-j) -> combine -> out1
    flash_kernel<<<gfl, 256, FL_SM_BYTES>>>(pq, pk, pv, pRh, pRw,
        pop, pmp, plp);
    combine_kernel<<<25, 256>>>(pop, pmp, plp, po1);
    // out = x + SiLU(BN(w2 @ out1)) + SiLU(BN(w3 @ out2))
    tgemm<3, false, false, false><<<g100_4, 256>>>(
        w2, po1, nullptr, nullptr, out, ND, NC, 0,
        nullptr, g2, b2, m2, v2, x);
    tgemm<2, false, true, false><<<g100_4, 256>>>(
        w3, po2, nullptr, nullptr, out, ND, NC, 0,
        nullptr, g3, b3, m3, v3, nullptr);
}

// round 6
// speedup vs baseline: 4.3311x; 1.1735x over previous
#include <cuda_runtime.h>
#include <cuda_bf16.h>
#include <cstdint>

#define EPS 1e-5f
#define HW 6400
#define NC 128
#define ND 256
#define NH 80
#define SPLIT 3

// ---------------- tensor-core helpers ----------------------------------------
__device__ __forceinline__ void ldsm4(uint32_t& r0, uint32_t& r1,
                                      uint32_t& r2, uint32_t& r3, uint32_t a) {
    asm volatile("ldmatrix.sync.aligned.m8n8.x4.shared.b16 {%0,%1,%2,%3},[%4];"
        : "=r"(r0), "=r"(r1), "=r"(r2), "=r"(r3) : "r"(a));
}
__device__ __forceinline__ void ldsm4t(uint32_t& r0, uint32_t& r1,
                                       uint32_t& r2, uint32_t& r3, uint32_t a) {
    asm volatile("ldmatrix.sync.aligned.m8n8.x4.trans.shared.b16 {%0,%1,%2,%3},[%4];"
        : "=r"(r0), "=r"(r1), "=r"(r2), "=r"(r3) : "r"(a));
}
__device__ __forceinline__ void mma_bf16(float* d, uint32_t a0, uint32_t a1,
                                         uint32_t a2, uint32_t a3,
                                         uint32_t b0, uint32_t b1) {
    asm volatile("mma.sync.aligned.m16n8k16.row.col.f32.bf16.bf16.f32 "
        "{%0,%1,%2,%3},{%4,%5,%6,%7},{%8,%9},{%0,%1,%2,%3};"
        : "+f"(d[0]), "+f"(d[1]), "+f"(d[2]), "+f"(d[3])
        : "r"(a0), "r"(a1), "r"(a2), "r"(a3), "r"(b0), "r"(b1));
}
__device__ __forceinline__ void mma_tf32(float* d, uint32_t a0, uint32_t a1,
                                         uint32_t a2, uint32_t a3,
                                         uint32_t b0, uint32_t b1) {
    asm volatile("mma.sync.aligned.m16n8k8.row.col.f32.tf32.tf32.f32 "
        "{%0,%1,%2,%3},{%4,%5,%6,%7},{%8,%9},{%0,%1,%2,%3};"
        : "+f"(d[0]), "+f"(d[1]), "+f"(d[2]), "+f"(d[3])
        : "r"(a0), "r"(a1), "r"(a2), "r"(a3), "r"(b0), "r"(b1));
}
__device__ __forceinline__ float tf32r(float x) {
    uint32_t r;
    asm("cvt.rna.tf32.f32 %0, %1;" : "=r"(r) : "f"(x));
    return __uint_as_float(r);
}
__device__ __forceinline__ void cpa16(uint32_t s, const void* g) {
    asm volatile("cp.async.cg.shared.global [%0], [%1], 16;" :: "r"(s), "l"(g));
}
#define CPA_COMMIT() asm volatile("cp.async.commit_group;")

// ---------------- scratch (static device globals; no allocation) -------------
__device__ float d_x1 [NC*HW];
__device__ float d_q  [NC*HW];
__device__ float d_p  [NC*HW];
__device__ __nv_bfloat16 d_qb[NC*HW];
__device__ __nv_bfloat16 d_kb[NC*HW];
__device__ __nv_bfloat16 d_vb[NC*HW];
__device__ float d_RW [2*NH*HW];   // [Rh(80); Rw(80)]
__device__ float d_AB [2*NH*HW];   // [ABh(80); ABw(80)]
__device__ float d_PA [NH*HW];
__device__ float d_PB [NH*HW];
__device__ float d_o1 [NC*HW];
__device__ float d_o2 [NC*HW];
__device__ float d_op [SPLIT*NC*HW];
__device__ float d_mp [SPLIT*HW];
__device__ float d_lp [SPLIT*HW];

// ---------------- tf32 GEMM (x1 conv + dual out2) -----------------------------
// EPI: 0 none, 2 BN+SiLU.  DUAL: C = A*B + A2*B2.
template<int EPI, bool DUAL>
__global__ void __launch_bounds__(256) tgemm(
    const float* __restrict__ A, const float* __restrict__ B,
    const float* __restrict__ A2, const float* __restrict__ B2,
    float* __restrict__ C, int M, int K, int K2,
    const float* __restrict__ g, const float* __restrict__ bb,
    const float* __restrict__ mm, const float* __restrict__ vv)
{
    __shared__ float Wt[64 * 72];
    __shared__ float Bt[64 * 72];
    const int tid = threadIdx.x;
    const int wid = tid >> 5, lane = tid & 31;
    const int m0 = blockIdx.y * 64, n0 = blockIdx.x * 64;
    const int i0w = (wid & 3) * 16;
    const int jbase = (wid >> 2) * 32;
    const int lrow = lane >> 2, lk = lane & 3;

    float sf[4][4];
    #pragma unroll
    for (int nt = 0; nt < 4; ++nt)
        #pragma unroll
        for (int e = 0; e < 4; ++e) sf[nt][e] = 0.f;

    const int nsrc = DUAL ? 2 : 1;
    for (int src = 0; src < nsrc; ++src) {
        const float* Ap = src ? A2 : A;
        const float* Bp = src ? B2 : B;
        const int    Kp = src ? K2 : K;
        for (int kc = 0; kc < Kp; kc += 64) {
            const int ck = (Kp - kc < 64) ? (Kp - kc) : 64;
            {   // A[m][K]: transpose on stage
                int m = tid >> 2;
                bool mok = (m0 + m) < M;
                for (int k4 = (tid & 3) << 2; k4 < ck; k4 += 16) {
                    float4 a4 = make_float4(0.f, 0.f, 0.f, 0.f);
                    if (mok) a4 = *(const float4*)&Ap[(size_t)(m0 + m) * Kp + kc + k4];
                    Wt[(k4 + 0) * 72 + m] = tf32r(a4.x);
                    Wt[(k4 + 1) * 72 + m] = tf32r(a4.y);
                    Wt[(k4 + 2) * 72 + m] = tf32r(a4.z);
                    Wt[(k4 + 3) * 72 + m] = tf32r(a4.w);
                }
            }
            {
                int n4 = (tid & 15) << 2;
                for (int kk = tid >> 4; kk < ck; kk += 16) {
                    float4 b4 = *(const float4*)&Bp[(size_t)(kc + kk) * HW + n0 + n4];
                    float* bp = &Bt[kk * 72 + n4];
                    bp[0] = tf32r(b4.x); bp[1] = tf32r(b4.y);
                    bp[2] = tf32r(b4.z); bp[3] = tf32r(b4.w);
                }
            }
            __syncthreads();
            const int nks = ck >> 3;
            for (int ks = 0; ks < nks; ++ks) {
                int k0 = ks * 8;
                uint32_t a0 = __float_as_uint(Wt[(k0 + lk) * 72 + i0w + lrow]);
                uint32_t a1 = __float_as_uint(Wt[(k0 + lk) * 72 + i0w + lrow + 8]);
                uint32_t a2 = __float_as_uint(Wt[(k0 + lk + 4) * 72 + i0w + lrow]);
                uint32_t a3 = __float_as_uint(Wt[(k0 + lk + 4) * 72 + i0w + lrow + 8]);
                #pragma unroll
                for (int np = 0; np < 4; ++np) {
                    int ncol = jbase + np * 8 + lrow;
                    uint32_t b0 = __float_as_uint(Bt[(k0 + lk) * 72 + ncol]);
                    uint32_t b1 = __float_as_uint(Bt[(k0 + lk + 4) * 72 + ncol]);
                    mma_tf32(sf[np], a0, a1, a2, a3, b0, b1);
                }
            }
            __syncthreads();
        }
    }

    const int cc0 = 2 * lk;
    #pragma unroll
    for (int rr = 0; rr < 2; ++rr) {
        int gm = m0 + i0w + lrow + rr * 8;
        if (gm >= M) continue;
        float sc = 0.f, sh = 0.f;
        if (EPI == 2) {
            sc = g[gm] * rsqrtf(vv[gm] + EPS);
            sh = bb[gm] - mm[gm] * sc;
        }
        #pragma unroll
        for (int nt = 0; nt < 4; ++nt) {
            float e0 = sf[nt][rr * 2 + 0];
            float e1 = sf[nt][rr * 2 + 1];
            if (EPI == 2) {
                e0 = e0 * sc + sh; e1 = e1 * sc + sh;
                e0 = e0 / (1.f + __expf(-e0));
                e1 = e1 / (1.f + __expf(-e1));
            }
            size_t idx = (size_t)gm * HW + n0 + jbase + nt * 8 + cc0;
            *(float2*)&C[idx] = make_float2(e0, e1);
        }
    }
}

// ---------------- fused q/k/v/p projection (z selects weight) ----------------
__global__ void __launch_bounds__(256) proj4(
    const float* __restrict__ x1,
    const float* __restrict__ wq, const float* __restrict__ bq,
    const float* __restrict__ wk, const float* __restrict__ bk,
    const float* __restrict__ wv, const float* __restrict__ bv,
    const float* __restrict__ wp, const float* __restrict__ bp,
    float* __restrict__ qf, __nv_bfloat16* __restrict__ qb,
    __nv_bfloat16* __restrict__ kb, __nv_bfloat16* __restrict__ vb,
    float* __restrict__ pf)
{
    __shared__ float Wt[64 * 72];
    __shared__ float Bt[64 * 72];
    const int z = blockIdx.z;
    const float* A    = (z == 0) ? wq : (z == 1) ? wk : (z == 2) ? wv : wp;
    const float* bias = (z == 0) ? bq : (z == 1) ? bk : (z == 2) ? bv : bp;
    const int tid = threadIdx.x;
    const int wid = tid >> 5, lane = tid & 31;
    const int m0 = blockIdx.y * 64, n0 = blockIdx.x * 64;
    const int i0w = (wid & 3) * 16;
    const int jbase = (wid >> 2) * 32;
    const int lrow = lane >> 2, lk = lane & 3;

    float sf[4][4];
    #pragma unroll
    for (int nt = 0; nt < 4; ++nt)
        #pragma unroll
        for (int e = 0; e < 4; ++e) sf[nt][e] = 0.f;

    for (int kc = 0; kc < NC; kc += 64) {
        {
            int m = tid >> 2;
            #pragma unroll
            for (int k4 = (tid & 3) << 2; k4 < 64; k4 += 16) {
                float4 a4 = *(const float4*)&A[(size_t)(m0 + m) * NC + kc + k4];
                Wt[(k4 + 0) * 72 + m] = tf32r(a4.x);
                Wt[(k4 + 1) * 72 + m] = tf32r(a4.y);
                Wt[(k4 + 2) * 72 + m] = tf32r(a4.z);
                Wt[(k4 + 3) * 72 + m] = tf32r(a4.w);
            }
        }
        {
            int n4 = (tid & 15) << 2;
            #pragma unroll
            for (int kk = tid >> 4; kk < 64; kk += 16) {
                float4 b4 = *(const float4*)&x1[(size_t)(kc + kk) * HW + n0 + n4];
                float* bp = &Bt[kk * 72 + n4];
                bp[0] = tf32r(b4.x); bp[1] = tf32r(b4.y);
                bp[2] = tf32r(b4.z); bp[3] = tf32r(b4.w);
            }
        }
        __syncthreads();
        #pragma unroll
        for (int ks = 0; ks < 8; ++ks) {
            int k0 = ks * 8;
            uint32_t a0 = __float_as_uint(Wt[(k0 + lk) * 72 + i0w + lrow]);
            uint32_t a1 = __float_as_uint(Wt[(k0 + lk) * 72 + i0w + lrow + 8]);
            uint32_t a2 = __float_as_uint(Wt[(k0 + lk + 4) * 72 + i0w + lrow]);
            uint32_t a3 = __float_as_uint(Wt[(k0 + lk + 4) * 72 + i0w + lrow + 8]);
            #pragma unroll
            for (int np = 0; np < 4; ++np) {
                int ncol = jbase + np * 8 + lrow;
                uint32_t b0 = __float_as_uint(Bt[(k0 + lk) * 72 + ncol]);
                uint32_t b1 = __float_as_uint(Bt[(k0 + lk + 4) * 72 + ncol]);
                mma_tf32(sf[np], a0, a1, a2, a3, b0, b1);
            }
        }
        __syncthreads();
    }

    const int cc0 = 2 * lk;
    #pragma unroll
    for (int rr = 0; rr < 2; ++rr) {
        int gm = m0 + i0w + lrow + rr * 8;
        float bsv = bias[gm];
        #pragma unroll
        for (int nt = 0; nt < 4; ++nt) {
            float e0 = sf[nt][rr * 2 + 0] + bsv;
            float e1 = sf[nt][rr * 2 + 1] + bsv;
            size_t idx = (size_t)gm * HW + n0 + jbase + nt * 8 + cc0;
            if (z == 0) {
                *(float2*)&qf[idx] = make_float2(e0, e1);
                *(__nv_bfloat162*)&qb[idx] = __floats2bfloat162_rn(e0, e1);
            } else if (z == 1) {
                *(__nv_bfloat162*)&kb[idx] = __floats2bfloat162_rn(e0, e1);
            } else if (z == 2) {
                *(__nv_bfloat162*)&vb[idx] = __floats2bfloat162_rn(e0, e1);
            } else {
                *(float2*)&pf[idx] = make_float2(e0, e1);
            }
        }
    }
}

// ---------------- stacked k-major GEMM: C[160][HW] = [Alo;Ahi]^T-style -------
// rows 0..79: sum_k a_lo[k*80+m] * B[k][n]; rows 80..159: a_hi.
__global__ void __launch_bounds__(256) krgemm(
    const float* __restrict__ a_lo, const float* __restrict__ a_hi,
    const float* __restrict__ B, float* __restrict__ C)
{
    __shared__ float Wt[64 * 72];
    __shared__ float Bt[64 * 72];
    const int tid = threadIdx.x;
    const int wid = tid >> 5, lane = tid & 31;
    const int m0 = blockIdx.y * 64, n0 = blockIdx.x * 64;
    const int i0w = (wid & 3) * 16;
    const int jbase = (wid >> 2) * 32;
    const int lrow = lane >> 2, lk = lane & 3;
    const int M = 2 * NH;

    float sf[4][4];
    #pragma unroll
    for (int nt = 0; nt < 4; ++nt)
        #pragma unroll
        for (int e = 0; e < 4; ++e) sf[nt][e] = 0.f;

    for (int kc = 0; kc < NC; kc += 64) {
        {   // A stage: row-selected scalar loads (relh/relw boundary safe)
            #pragma unroll
            for (int kk = tid >> 4; kk < 64; kk += 16) {
                #pragma unroll
                for (int mi = tid & 15; mi < 64; mi += 16) {
                    int gm = m0 + mi;
                    float vA = 0.f;
                    if (gm < NH)          vA = a_lo[(size_t)(kc + kk) * NH + gm];
                    else if (gm < 2 * NH) vA = a_hi[(size_t)(kc + kk) * NH + gm - NH];
                    Wt[kk * 72 + mi] = tf32r(vA);
                }
            }
        }
        {
            int n4 = (tid & 15) << 2;
            #pragma unroll
            for (int kk = tid >> 4; kk < 64; kk += 16) {
                float4 b4 = *(const float4*)&B[(size_t)(kc + kk) * HW + n0 + n4];
                float* bp = &Bt[kk * 72 + n4];
                bp[0] = tf32r(b4.x); bp[1] = tf32r(b4.y);
                bp[2] = tf32r(b4.z); bp[3] = tf32r(b4.w);
            }
        }
        __syncthreads();
        #pragma unroll
        for (int ks = 0; ks < 8; ++ks) {
            int k0 = ks * 8;
            uint32_t a0 = __float_as_uint(Wt[(k0 + lk) * 72 + i0w + lrow]);
            uint32_t a1 = __float_as_uint(Wt[(k0 + lk) * 72 + i0w + lrow + 8]);
            uint32_t a2 = __float_as_uint(Wt[(k0 + lk + 4) * 72 + i0w + lrow]);
            uint32_t a3 = __float_as_uint(Wt[(k0 + lk + 4) * 72 + i0w + lrow + 8]);
            #pragma unroll
            for (int np = 0; np < 4; ++np) {
                int ncol = jbase + np * 8 + lrow;
                uint32_t b0 = __float_as_uint(Bt[(k0 + lk) * 72 + ncol]);
                uint32_t b1 = __float_as_uint(Bt[(k0 + lk + 4) * 72 + ncol]);
                mma_tf32(sf[np], a0, a1, a2, a3, b0, b1);
            }
        }
        __syncthreads();
    }

    const int cc0 = 2 * lk;
    #pragma unroll
    for (int rr = 0; rr < 2; ++rr) {
        int gm = m0 + i0w + lrow + rr * 8;
        if (gm >= M) continue;
        #pragma unroll
        for (int nt = 0; nt < 4; ++nt) {
            size_t idx = (size_t)gm * HW + n0 + jbase + nt * 8 + cc0;
            *(float2*)&C[idx] = make_float2(sf[nt][rr * 2 + 0], sf[nt][rr * 2 + 1]);
        }
    }
}

// ---------------- fused final: out = x + SiLU(BN2(w2@o1)) + SiLU(BN3(w3@o2)) -
__global__ void __launch_bounds__(256) final_gemm(
    const float* __restrict__ w2, const float* __restrict__ o1,
    const float* __restrict__ g2, const float* __restrict__ b2,
    const float* __restrict__ m2, const float* __restrict__ v2,
    const float* __restrict__ w3, const float* __restrict__ o2,
    const float* __restrict__ g3, const float* __restrict__ b3,
    const float* __restrict__ m3, const float* __restrict__ v3,
    const float* __restrict__ x, float* __restrict__ out)
{
    __shared__ float Wt[64 * 72];
    __shared__ float Bt[64 * 72];
    const int tid = threadIdx.x;
    const int wid = tid >> 5, lane = tid & 31;
    const int m0 = blockIdx.y * 64, n0 = blockIdx.x * 64;
    const int i0w = (wid & 3) * 16;
    const int jbase = (wid >> 2) * 32;
    const int lrow = lane >> 2, lk = lane & 3;

    float keep[4][4];
    float sf[4][4];
    #pragma unroll
    for (int nt = 0; nt < 4; ++nt)
        #pragma unroll
        for (int e = 0; e < 4; ++e) sf[nt][e] = 0.f;

    #pragma unroll
    for (int src = 0; src < 2; ++src) {
        const float* Ap = src ? w3 : w2;
        const float* Bp = src ? o2 : o1;
        for (int kc = 0; kc < NC; kc += 64) {
            {
                int m = tid >> 2;
                #pragma unroll
                for (int k4 = (tid & 3) << 2; k4 < 64; k4 += 16) {
                    float4 a4 = *(const float4*)&Ap[(size_t)(m0 + m) * NC + kc + k4];
                    Wt[(k4 + 0) * 72 + m] = tf32r(a4.x);
                    Wt[(k4 + 1) * 72 + m] = tf32r(a4.y);
                    Wt[(k4 + 2) * 72 + m] = tf32r(a4.z);
                    Wt[(k4 + 3) * 72 + m] = tf32r(a4.w);
                }
            }
            {
                int n4 = (tid & 15) << 2;
                #pragma unroll
                for (int kk = tid >> 4; kk < 64; kk += 16) {
                    float4 b4 = *(const float4*)&Bp[(size_t)(kc + kk) * HW + n0 + n4];
                    float* bp = &Bt[kk * 72 + n4];
                    bp[0] = tf32r(b4.x); bp[1] = tf32r(b4.y);
                    bp[2] = tf32r(b4.z); bp[3] = tf32r(b4.w);
                }
            }
            __syncthreads();
            #pragma unroll
            for (int ks = 0; ks < 8; ++ks) {
                int k0 = ks * 8;
                uint32_t a0 = __float_as_uint(Wt[(k0 + lk) * 72 + i0w + lrow]);
                uint32_t a1 = __float_as_uint(Wt[(k0 + lk) * 72 + i0w + lrow + 8]);
                uint32_t a2 = __float_as_uint(Wt[(k0 + lk + 4) * 72 + i0w + lrow]);
                uint32_t a3 = __float_as_uint(Wt[(k0 + lk + 4) * 72 + i0w + lrow + 8]);
                #pragma unroll
                for (int np = 0; np < 4; ++np) {
                    int ncol = jbase + np * 8 + lrow;
                    uint32_t b0 = __float_as_uint(Bt[(k0 + lk) * 72 + ncol]);
                    uint32_t b1 = __float_as_uint(Bt[(k0 + lk + 4) * 72 + ncol]);
                    mma_tf32(sf[np], a0, a1, a2, a3, b0, b1);
                }
            }
            __syncthreads();
        }
        // apply this source's BN+SiLU
        const float* gg = src ? g3 : g2;
        const float* bbp = src ? b3 : b2;
        const float* mmp = src ? m3 : m2;
        const float* vvp = src ? v3 : v2;
        #pragma unroll
        for (int rr = 0; rr < 2; ++rr) {
            int gm = m0 + i0w + lrow + rr * 8;
            float sc = gg[gm] * rsqrtf(vvp[gm] + EPS);
            float sh = bbp[gm] - mmp[gm] * sc;
            #pragma unroll
            for (int nt = 0; nt < 4; ++nt) {
                #pragma unroll
                for (int e2 = 0; e2 < 2; ++e2) {
                    float val = sf[nt][rr * 2 + e2] * sc + sh;
                    val = val / (1.f + __expf(-val));
                    if (src == 0) { keep[nt][rr * 2 + e2] = val; sf[nt][rr * 2 + e2] = 0.f; }
                    else          { keep[nt][rr * 2 + e2] += val; }
                }
            }
        }
    }

    const int cc0 = 2 * lk;
    #pragma unroll
    for (int rr = 0; rr < 2; ++rr) {
        int gm = m0 + i0w + lrow + rr * 8;
        #pragma unroll
        for (int nt = 0; nt < 4; ++nt) {
            size_t idx = (size_t)gm * HW + n0 + jbase + nt * 8 + cc0;
            float2 x2 = *(const float2*)&x[idx];
            *(float2*)&out[idx] = make_float2(keep[nt][rr * 2 + 0] + x2.x,
                                              keep[nt][rr * 2 + 1] + x2.y);
        }
    }
}

// ---------------- paired per-column softmax over 80 rows ---------------------
__global__ void softmax80x2(const float* __restrict__ AB,
                            float* __restrict__ PA, float* __restrict__ PB)
{
    int gid = blockIdx.x * blockDim.x + threadIdx.x;
    const float* in; float* out; int i;
    if (gid < HW) { in = AB; out = PA; i = gid; }
    else          { in = AB + NH * HW; out = PB; i = gid - HW; }
    float mx = -1e30f;
    for (int t = 0; t < NH; ++t) mx = fmaxf(mx, in[t * HW + i]);
    float s = 0.f;
    for (int t = 0; t < NH; ++t) s += __expf(in[t * HW + i] - mx);
    float inv = 1.f / s;
    for (int t = 0; t < NH; ++t) out[t * HW + i] = __expf(in[t * HW + i] - mx) * inv;
}

// ---------------- branch-1 flash attention (bf16 + cp.async pipelining) ------
#define QS_OFF   0               // bf16 [128][72]
#define KS_OFF   18432           // bf16 [128][72]
#define VS_OFF   36864           // bf16 [128][72]
#define PS_OFF   55296           // bf16 [64][72]
#define SS_OFF   64512           // f32  [64][72]
#define RWS_OFF  82944           // f32  [64][68]
#define RHS_OFF  100352          // f32  [2][68]
#define MR_OFF   100896          // f32  [64]
#define LR_OFF   101152
#define FR_OFF   101408
#define FL_SM_BYTES 101760

__global__ void __launch_bounds__(256, 2) flash_kernel(
    const __nv_bfloat16* __restrict__ q, const __nv_bfloat16* __restrict__ k,
    const __nv_bfloat16* __restrict__ v, const float* __restrict__ Rh,
    const float* __restrict__ Rw, float* __restrict__ op,
    float* __restrict__ mp, float* __restrict__ lp)
{
    extern __shared__ char smc[];
    __nv_bfloat16* Qs = (__nv_bfloat16*)(smc + QS_OFF);
    __nv_bfloat16* Ps = (__nv_bfloat16*)(smc + PS_OFF);
    float* Ss   = (float*)(smc + SS_OFF);
    float* Rws  = (float*)(smc + RWS_OFF);
    float* Rhs  = (float*)(smc + RHS_OFF);
    float* mrow = (float*)(smc + MR_OFF);
    float* lrow = (float*)(smc + LR_OFF);
    float* frow = (float*)(smc + FR_OFF);

    const int tid  = threadIdx.x;
    const int wid  = tid >> 5, lane = tid & 31;
    const int lr   = lane & 7, gq = lane >> 3;
    const int i0   = blockIdx.x * 64;
    const int spl  = blockIdx.y;
    const int t0   = (spl * 100) / SPLIT;
    const int t1   = ((spl + 1) * 100) / SPLIT;
    const int h0   = i0 / 80;
    const int i0w  = (wid & 3) * 16;
    const int jbase = (wid >> 2) * 32;
    const int cbase = (wid >> 2) * 64;

    const uint32_t qsb = (uint32_t)__cvta_generic_to_shared(Qs);
    const uint32_t ksb = (uint32_t)__cvta_generic_to_shared(smc + KS_OFF);
    const uint32_t vsb = (uint32_t)__cvta_generic_to_shared(smc + VS_OFF);
    const uint32_t psb = (uint32_t)__cvta_generic_to_shared(Ps);

    // prologue: issue K(t0) then V(t0) via cp.async (two groups)
    {
        int j0n = t0 * 64;
        #pragma unroll
        for (int it = 0; it < 4; ++it) {
            int ch = tid + it * 256;
            int c = ch >> 3, j8 = (ch & 7) * 8;
            cpa16(ksb + (uint32_t)((c * 72 + j8) * 2), &k[(size_t)c * HW + j0n + j8]);
        }
        CPA_COMMIT();
        #pragma unroll
        for (int it = 0; it < 4; ++it) {
            int ch = tid + it * 256;
            int c = ch >> 3, j8 = (ch & 7) * 8;
            cpa16(vsb + (uint32_t)((c * 72 + j8) * 2), &v[(size_t)c * HW + j0n + j8]);
        }
        CPA_COMMIT();
    }
    {   // Q tile: bf16 [c][i] direct copy
        int cr = tid >> 4, i4 = (tid & 15) << 2;
        #pragma unroll
        for (int it = 0; it < 8; ++it) {
            int c = cr + it * 16;
            *(uint2*)&Qs[c * 72 + i4] = *(const uint2*)&q[(size_t)c * HW + i0 + i4];
        }
    }
    if (tid < 64) { mrow[tid] = -1e30f; lrow[tid] = 0.f; }

    float d[8][4];
    #pragma unroll
    for (int nt = 0; nt < 8; ++nt)
        #pragma unroll
        for (int e = 0; e < 4; ++e) d[nt][e] = 0.f;

    for (int t = t0; t < t1; ++t) {
        const int j0 = t * 64;
        const bool more = (t + 1 < t1);
        // positional bias tiles (regular LDG/STS; visible after the Ss sync)
        #pragma unroll
        for (int e = 0; e < 4; ++e) {
            int ee = tid + e * 256;
            int row = ee >> 4, c4 = (ee & 15) << 2;
            int wr = (i0 + row) % 80;
            *(float4*)&Rws[row * 68 + c4] = *(const float4*)&Rw[wr * HW + j0 + c4];
        }
        if (tid < 128) {
            int sel = tid >> 6, col = tid & 63;
            int hh = sel ? (i0 + 63) / 80 : h0;
            Rhs[sel * 68 + col] = Rh[hh * HW + j0 + col];
        }
        asm volatile("cp.async.wait_group 1;");   // K(t) landed (V(t) may fly)
        __syncthreads();

        // ---- QK^T on tensor cores ----
        float sf[4][4];
        #pragma unroll
        for (int nt = 0; nt < 4; ++nt)
            #pragma unroll
            for (int e = 0; e < 4; ++e) sf[nt][e] = 0.f;

        #pragma unroll
        for (int ks = 0; ks < 8; ++ks) {
            int k0 = ks * 16;
            uint32_t a0, a1, a2, a3;
            ldsm4t(a0, a1, a2, a3,
                   qsb + (uint32_t)(((k0 + lr + (gq >> 1) * 8) * 72 + i0w + (gq & 1) * 8) * 2));
            #pragma unroll
            for (int np = 0; np < 2; ++np) {
                int jb = jbase + np * 16;
                uint32_t b0, b1, b2, b3;
                ldsm4t(b0, b1, b2, b3,
                       ksb + (uint32_t)(((k0 + lr + (gq & 1) * 8) * 72 + jb + (gq >> 1) * 8) * 2));
                mma_bf16(sf[np * 2],     a0, a1, a2, a3, b0, b1);
                mma_bf16(sf[np * 2 + 1], a0, a1, a2, a3, b2, b3);
            }
        }
        {   // store S fragments to smem (fp32)
            int row = i0w + (lane >> 2);
            int cc = 2 * (lane & 3);
            #pragma unroll
            for (int nt = 0; nt < 4; ++nt) {
                int col = jbase + nt * 8 + cc;
                *(float2*)&Ss[row * 72 + col]       = make_float2(sf[nt][0], sf[nt][1]);
                *(float2*)&Ss[(row + 8) * 72 + col] = make_float2(sf[nt][2], sf[nt][3]);
            }
        }
        __syncthreads();                          // Ss ready; Ks free

        if (more) {                               // overlap: K(t+1) into Ks in place
            int j0n = (t + 1) * 64;
            #pragma unroll
            for (int it = 0; it < 4; ++it) {
                int ch = tid + it * 256;
                int c = ch >> 3, j8 = (ch & 7) * 8;
                cpa16(ksb + (uint32_t)((c * 72 + j8) * 2), &k[(size_t)c * HW + j0n + j8]);
            }
            CPA_COMMIT();
        }

        // ---- online softmax ----
        #pragma unroll
        for (int r8 = 0; r8 < 8; ++r8) {
            int r = wid * 8 + r8;
            int rs = (((i0 + r) / 80) != h0) ? 1 : 0;
            float v1 = Ss[r * 72 + lane]      + Rhs[rs * 68 + lane]      + Rws[r * 68 + lane];
            float v2 = Ss[r * 72 + 32 + lane] + Rhs[rs * 68 + 32 + lane] + Rws[r * 68 + 32 + lane];
            float tm = fmaxf(v1, v2);
            #pragma unroll
            for (int off = 16; off; off >>= 1)
                tm = fmaxf(tm, __shfl_xor_sync(0xffffffffu, tm, off));
            float mold = mrow[r];
            float nm = fmaxf(mold, tm);
            float e1 = __expf(v1 - nm), e2 = __expf(v2 - nm);
            float ssum = e1 + e2;
            #pragma unroll
            for (int off = 16; off; off >>= 1)
                ssum += __shfl_xor_sync(0xffffffffu, ssum, off);
            Ps[r * 72 + lane]      = __float2bfloat16(e1);
            Ps[r * 72 + 32 + lane] = __float2bfloat16(e2);
            if (lane == 0) {
                float f = __expf(mold - nm);
                lrow[r] = lrow[r] * f + ssum;
                mrow[r] = nm;
                frow[r] = f;
            }
        }
        if (more) asm volatile("cp.async.wait_group 1;");  // V(t) landed
        else      asm volatile("cp.async.wait_group 0;");
        __syncthreads();                          // Ps + Vs visible

        // ---- rescale O, then P @ V^T ----
        {
            float f0 = frow[i0w + (lane >> 2)];
            float f1 = frow[i0w + 8 + (lane >> 2)];
            #pragma unroll
            for (int nt = 0; nt < 8; ++nt) {
                d[nt][0] *= f0; d[nt][1] *= f0;
                d[nt][2] *= f1; d[nt][3] *= f1;
            }
        }
        #pragma unroll
        for (int ks = 0; ks < 4; ++ks) {
            int j0s = ks * 16;
            uint32_t a0, a1, a2, a3;
            ldsm4(a0, a1, a2, a3,
                  psb + (uint32_t)(((i0w + lr + (gq & 1) * 8) * 72 + j0s + (gq >> 1) * 8) * 2));
            #pragma unroll
            for (int np = 0; np < 4; ++np) {
                int cb = cbase + np * 16;
                uint32_t b0, b1, b2, b3;
                ldsm4(b0, b1, b2, b3,
                      vsb + (uint32_t)(((cb + lr + (gq >> 1) * 8) * 72 + j0s + (gq & 1) * 8) * 2));
                mma_bf16(d[np * 2],     a0, a1, a2, a3, b0, b1);
                mma_bf16(d[np * 2 + 1], a0, a1, a2, a3, b2, b3);
            }
        }
        __syncthreads();                          // Vs free; Ps free

        if (more) {                               // overlap: V(t+1) into Vs
            int j0n = (t + 1) * 64;
            #pragma unroll
            for (int it = 0; it < 4; ++it) {
                int ch = tid + it * 256;
                int c = ch >> 3, j8 = (ch & 7) * 8;
                cpa16(vsb + (uint32_t)((c * 72 + j8) * 2), &v[(size_t)c * HW + j0n + j8]);
            }
            CPA_COMMIT();
        }
    }

    // emit unnormalized partials + (m, l)
    {
        int row0 = i0w + (lane >> 2);
        int cc = 2 * (lane & 3);
        #pragma unroll
        for (int nt = 0; nt < 8; ++nt) {
            int c = cbase + nt * 8 + cc;
            op[(spl * NC + c)     * HW + i0 + row0]     = d[nt][0];
            op[(spl * NC + c + 1) * HW + i0 + row0]     = d[nt][1];
            op[(spl * NC + c)     * HW + i0 + row0 + 8] = d[nt][2];
            op[(spl * NC + c + 1) * HW + i0 + row0 + 8] = d[nt][3];
        }
    }
    if (tid < 64) {
        mp[spl * HW + i0 + tid] = mrow[tid];
        lp[spl * HW + i0 + tid] = lrow[tid];
    }
}

// ---------------- split-j combine --------------------------------------------
__global__ void combine_kernel(const float* __restrict__ op,
                               const float* __restrict__ mp,
                               const float* __restrict__ lp,
                               float* __restrict__ out1)
{
    int i = blockIdx.x * blockDim.x + threadIdx.x;
    if (i >= HW) return;
    float m0 = mp[i], m1 = mp[HW + i], m2 = mp[2 * HW + i];
    float M = fmaxf(m0, fmaxf(m1, m2));
    float w0 = __expf(m0 - M), w1 = __expf(m1 - M), w2 = __expf(m2 - M);
    float L = lp[i] * w0 + lp[HW + i] * w1 + lp[2 * HW + i] * w2;
    float inv = 1.f / L;
    for (int c = 0; c < NC; ++c) {
        float s = op[c * HW + i] * w0
                + op[(NC + c) * HW + i] * w1
                + op[(2 * NC + c) * HW + i] * w2;
        out1[c * HW + i] = s * inv;
    }
}

// -------------------------------- launch -------------------------------------
extern "C" void kernel_launch(void* const* d_in, const int* in_sizes, int n_in,
                              void* d_out, int out_size)
{
    (void)in_sizes; (void)n_in; (void)out_size;
    const float* x    = (const float*)d_in[0];
    const float* w1   = (const float*)d_in[1];
    const float* g1   = (const float*)d_in[2];
    const float* b1   = (const float*)d_in[3];
    const float* m1   = (const float*)d_in[4];
    const float* v1   = (const float*)d_in[5];
    const float* w2   = (const float*)d_in[6];
    const float* g2   = (const float*)d_in[7];
    const float* b2   = (const float*)d_in[8];
    const float* m2   = (const float*)d_in[9];
    const float* v2   = (const float*)d_in[10];
    const float* w3   = (const float*)d_in[11];
    const float* g3   = (const float*)d_in[12];
    const float* b3   = (const float*)d_in[13];
    const float* m3   = (const float*)d_in[14];
    const float* v3   = (const float*)d_in[15];
    const float* wq   = (const float*)d_in[16];
    const float* bq   = (const float*)d_in[17];
    const float* wk   = (const float*)d_in[18];
    const float* bk   = (const float*)d_in[19];
    const float* wv   = (const float*)d_in[20];
    const float* bv   = (const float*)d_in[21];
    const float* wp   = (const float*)d_in[22];
    const float* bp   = (const float*)d_in[23];
    const float* relh = (const float*)d_in[24];
    const float* relw = (const float*)d_in[25];
    const float* efh  = (const float*)d_in[26];
    const float* efw  = (const float*)d_in[27];
    float* out = (float*)d_out;

    float *px1, *pq, *pp, *pRW, *pAB, *pPA, *pPB, *po1, *po2, *pop, *pmp, *plp;
    __nv_bfloat16 *pqb, *pkb, *pvb;
    cudaGetSymbolAddress((void**)&px1, d_x1);
    cudaGetSymbolAddress((void**)&pq,  d_q);
    cudaGetSymbolAddress((void**)&pp,  d_p);
    cudaGetSymbolAddress((void**)&pqb, d_qb);
    cudaGetSymbolAddress((void**)&pkb, d_kb);
    cudaGetSymbolAddress((void**)&pvb, d_vb);
    cudaGetSymbolAddress((void**)&pRW, d_RW);
    cudaGetSymbolAddress((void**)&pAB, d_AB);
    cudaGetSymbolAddress((void**)&pPA, d_PA);
    cudaGetSymbolAddress((void**)&pPB, d_PB);
    cudaGetSymbolAddress((void**)&po1, d_o1);
    cudaGetSymbolAddress((void**)&po2, d_o2);
    cudaGetSymbolAddress((void**)&pop, d_op);
    cudaGetSymbolAddress((void**)&pmp, d_mp);
    cudaGetSymbolAddress((void**)&plp, d_lp);

    cudaFuncSetAttribute(flash_kernel,
        cudaFuncAttributeMaxDynamicSharedMemorySize, FL_SM_BYTES);

    dim3 g100_2(100, 2), g100_3(100, 3), g100_4(100, 4);
    dim3 gproj(100, 2, 4), gfl(100, SPLIT);

    // [0] x1 = SiLU(BN(w1 @ x))
    tgemm<2, false><<<g100_2, 256>>>(w1, x, nullptr, nullptr, px1,
        NC, ND, 0, g1, b1, m1, v1);
    // [1] fused q/k/v/p projections (fp32 q,p + bf16 q,k,v)
    proj4<<<gproj, 256>>>(px1, wq, bq, wk, bk, wv, bv, wp, bp,
        pq, pqb, pkb, pvb, pp);
    // [2] [Rh; Rw] = [rel_h; rel_w]^T q   (stacked M=160)
    krgemm<<<g100_3, 256>>>(relh, relw, pq, pRW);
    // [3] [ABh; ABw] = [ef_h; ef_w]^T p
    krgemm<<<g100_3, 256>>>(efh, efw, pp, pAB);
    // [4] both factored softmaxes
    softmax80x2<<<50, 256>>>(pAB, pPA, pPB);
    // [5] flash attention (bf16 tensor cores, cp.async pipeline, split-j)
    flash_kernel<<<gfl, 256, FL_SM_BYTES>>>(pqb, pkb, pvb,
        pRW, pRW + NH * HW, pop, pmp, plp);
    // [6] out2 = ef_h @ PA + ef_w @ PB  (fused dual GEMM)
    tgemm<0, true><<<g100_2, 256>>>(efh, pPA, efw, pPB, po2,
        NC, NH, NH, nullptr, nullptr, nullptr, nullptr);
    // [7] split-j combine -> out1
    combine_kernel<<<25, 256>>>(pop, pmp, plp, po1);
    // [8] out = x + SiLU(BN2(w2@o1)) + SiLU(BN3(w3@o2))  (fused)
    final_gemm<<<g100_4, 256>>>(w2, po1, g2, b2, m2, v2,
        w3, po2, g3, b3, m3, v3, x, out);
}

// round 7
// speedup vs baseline: 4.3669x; 1.0083x over previous
#include <cuda_runtime.h>
#include <cuda_bf16.h>
#include <cuda_fp16.h>
#include <cstdint>

#define EPS 1e-5f
#define HW 6400
#define NC 128
#define ND 256
#define NH 80
#define SPLIT 6

// ---------------- tensor-core helpers ----------------------------------------
__device__ __forceinline__ void ldsm4(uint32_t& r0, uint32_t& r1,
                                      uint32_t& r2, uint32_t& r3, uint32_t a) {
    asm volatile("ldmatrix.sync.aligned.m8n8.x4.shared.b16 {%0,%1,%2,%3},[%4];"
        : "=r"(r0), "=r"(r1), "=r"(r2), "=r"(r3) : "r"(a));
}
__device__ __forceinline__ void ldsm4t(uint32_t& r0, uint32_t& r1,
                                       uint32_t& r2, uint32_t& r3, uint32_t a) {
    asm volatile("ldmatrix.sync.aligned.m8n8.x4.trans.shared.b16 {%0,%1,%2,%3},[%4];"
        : "=r"(r0), "=r"(r1), "=r"(r2), "=r"(r3) : "r"(a));
}
__device__ __forceinline__ void mma_bf16(float* d, uint32_t a0, uint32_t a1,
                                         uint32_t a2, uint32_t a3,
                                         uint32_t b0, uint32_t b1) {
    asm volatile("mma.sync.aligned.m16n8k16.row.col.f32.bf16.bf16.f32 "
        "{%0,%1,%2,%3},{%4,%5,%6,%7},{%8,%9},{%0,%1,%2,%3};"
        : "+f"(d[0]), "+f"(d[1]), "+f"(d[2]), "+f"(d[3])
        : "r"(a0), "r"(a1), "r"(a2), "r"(a3), "r"(b0), "r"(b1));
}
__device__ __forceinline__ void mma_f16(float* d, uint32_t a0, uint32_t a1,
                                        uint32_t a2, uint32_t a3,
                                        uint32_t b0, uint32_t b1) {
    asm volatile("mma.sync.aligned.m16n8k16.row.col.f32.f16.f16.f32 "
        "{%0,%1,%2,%3},{%4,%5,%6,%7},{%8,%9},{%0,%1,%2,%3};"
        : "+f"(d[0]), "+f"(d[1]), "+f"(d[2]), "+f"(d[3])
        : "r"(a0), "r"(a1), "r"(a2), "r"(a3), "r"(b0), "r"(b1));
}
__device__ __forceinline__ void mma_tf32(float* d, uint32_t a0, uint32_t a1,
                                         uint32_t a2, uint32_t a3,
                                         uint32_t b0, uint32_t b1) {
    asm volatile("mma.sync.aligned.m16n8k8.row.col.f32.tf32.tf32.f32 "
        "{%0,%1,%2,%3},{%4,%5,%6,%7},{%8,%9},{%0,%1,%2,%3};"
        : "+f"(d[0]), "+f"(d[1]), "+f"(d[2]), "+f"(d[3])
        : "r"(a0), "r"(a1), "r"(a2), "r"(a3), "r"(b0), "r"(b1));
}
__device__ __forceinline__ float tf32r(float x) {
    uint32_t r;
    asm("cvt.rna.tf32.f32 %0, %1;" : "=r"(r) : "f"(x));
    return __uint_as_float(r);
}
__device__ __forceinline__ void cpa16(uint32_t s, const void* g) {
    asm volatile("cp.async.cg.shared.global [%0], [%1], 16;" :: "r"(s), "l"(g));
}
#define CPA_COMMIT() asm volatile("cp.async.commit_group;")

// ---------------- scratch (static device globals; no allocation) -------------
__device__ float d_x1 [NC*HW];
__device__ float d_q  [NC*HW];
__device__ float d_p  [NC*HW];
__device__ __nv_bfloat16 d_qb[NC*HW];
__device__ __nv_bfloat16 d_kb[NC*HW];
__device__ __half d_vh[NC*HW];
__device__ float d_RW  [2*NH*HW];   // [Rh(80); Rw(80)]
__device__ float d_AB  [2*NH*HW];   // [ABh(80); ABw(80)]
__device__ float d_PAB [2*NH*HW];   // normalized [PA(80); PB(80)]
__device__ float d_W3  [ND*2*NH];   // [w3@efh | w3@efw]  m-major [256][160]
__device__ float d_o1  [NC*HW];
__device__ float d_op  [SPLIT*NC*HW];
__device__ float d_mp  [SPLIT*HW];
__device__ float d_lp  [SPLIT*HW];

// ---------------- tf32 GEMM (x1 conv) -----------------------------------------
template<int EPI>
__global__ void __launch_bounds__(256) tgemm(
    const float* __restrict__ A, const float* __restrict__ B,
    float* __restrict__ C, int M, int K,
    const float* __restrict__ g, const float* __restrict__ bb,
    const float* __restrict__ mm, const float* __restrict__ vv)
{
    __shared__ float Wt[64 * 72];
    __shared__ float Bt[64 * 72];
    const int tid = threadIdx.x;
    const int wid = tid >> 5, lane = tid & 31;
    const int m0 = blockIdx.y * 64, n0 = blockIdx.x * 64;
    const int i0w = (wid & 3) * 16;
    const int jbase = (wid >> 2) * 32;
    const int lrow = lane >> 2, lk = lane & 3;

    float sf[4][4];
    #pragma unroll
    for (int nt = 0; nt < 4; ++nt)
        #pragma unroll
        for (int e = 0; e < 4; ++e) sf[nt][e] = 0.f;

    for (int kc = 0; kc < K; kc += 64) {
        {
            int m = tid >> 2;
            #pragma unroll
            for (int k4 = (tid & 3) << 2; k4 < 64; k4 += 16) {
                float4 a4 = *(const float4*)&A[(size_t)(m0 + m) * K + kc + k4];
                Wt[(k4 + 0) * 72 + m] = tf32r(a4.x);
                Wt[(k4 + 1) * 72 + m] = tf32r(a4.y);
                Wt[(k4 + 2) * 72 + m] = tf32r(a4.z);
                Wt[(k4 + 3) * 72 + m] = tf32r(a4.w);
            }
        }
        {
            int n4 = (tid & 15) << 2;
            #pragma unroll
            for (int kk = tid >> 4; kk < 64; kk += 16) {
                float4 b4 = *(const float4*)&B[(size_t)(kc + kk) * HW + n0 + n4];
                float* bp = &Bt[kk * 72 + n4];
                bp[0] = tf32r(b4.x); bp[1] = tf32r(b4.y);
                bp[2] = tf32r(b4.z); bp[3] = tf32r(b4.w);
            }
        }
        __syncthreads();
        #pragma unroll
        for (int ks = 0; ks < 8; ++ks) {
            int k0 = ks * 8;
            uint32_t a0 = __float_as_uint(Wt[(k0 + lk) * 72 + i0w + lrow]);
            uint32_t a1 = __float_as_uint(Wt[(k0 + lk) * 72 + i0w + lrow + 8]);
            uint32_t a2 = __float_as_uint(Wt[(k0 + lk + 4) * 72 + i0w + lrow]);
            uint32_t a3 = __float_as_uint(Wt[(k0 + lk + 4) * 72 + i0w + lrow + 8]);
            #pragma unroll
            for (int np = 0; np < 4; ++np) {
                int ncol = jbase + np * 8 + lrow;
                uint32_t b0 = __float_as_uint(Bt[(k0 + lk) * 72 + ncol]);
                uint32_t b1 = __float_as_uint(Bt[(k0 + lk + 4) * 72 + ncol]);
                mma_tf32(sf[np], a0, a1, a2, a3, b0, b1);
            }
        }
        __syncthreads();
    }

    const int cc0 = 2 * lk;
    #pragma unroll
    for (int rr = 0; rr < 2; ++rr) {
        int gm = m0 + i0w + lrow + rr * 8;
        float sc = 0.f, sh = 0.f;
        if (EPI == 2) {
            sc = g[gm] * rsqrtf(vv[gm] + EPS);
            sh = bb[gm] - mm[gm] * sc;
        }
        #pragma unroll
        for (int nt = 0; nt < 4; ++nt) {
            float e0 = sf[nt][rr * 2 + 0];
            float e1 = sf[nt][rr * 2 + 1];
            if (EPI == 2) {
                e0 = e0 * sc + sh; e1 = e1 * sc + sh;
                e0 = e0 / (1.f + __expf(-e0));
                e1 = e1 / (1.f + __expf(-e1));
            }
            size_t idx = (size_t)gm * HW + n0 + jbase + nt * 8 + cc0;
            *(float2*)&C[idx] = make_float2(e0, e1);
        }
    }
}

// ---------------- fused q/k/v/p projection (z selects weight) ----------------
__global__ void __launch_bounds__(256) proj4(
    const float* __restrict__ x1,
    const float* __restrict__ wq, const float* __restrict__ bq,
    const float* __restrict__ wk, const float* __restrict__ bk,
    const float* __restrict__ wv, const float* __restrict__ bv,
    const float* __restrict__ wp, const float* __restrict__ bp,
    float* __restrict__ qf, __nv_bfloat16* __restrict__ qb,
    __nv_bfloat16* __restrict__ kb, __half* __restrict__ vh,
    float* __restrict__ pf)
{
    __shared__ float Wt[64 * 72];
    __shared__ float Bt[64 * 72];
    const int z = blockIdx.z;
    const float* A    = (z == 0) ? wq : (z == 1) ? wk : (z == 2) ? wv : wp;
    const float* bias = (z == 0) ? bq : (z == 1) ? bk : (z == 2) ? bv : bp;
    const int tid = threadIdx.x;
    const int wid = tid >> 5, lane = tid & 31;
    const int m0 = blockIdx.y * 64, n0 = blockIdx.x * 64;
    const int i0w = (wid & 3) * 16;
    const int jbase = (wid >> 2) * 32;
    const int lrow = lane >> 2, lk = lane & 3;

    float sf[4][4];
    #pragma unroll
    for (int nt = 0; nt < 4; ++nt)
        #pragma unroll
        for (int e = 0; e < 4; ++e) sf[nt][e] = 0.f;

    for (int kc = 0; kc < NC; kc += 64) {
        {
            int m = tid >> 2;
            #pragma unroll
            for (int k4 = (tid & 3) << 2; k4 < 64; k4 += 16) {
                float4 a4 = *(const float4*)&A[(size_t)(m0 + m) * NC + kc + k4];
                Wt[(k4 + 0) * 72 + m] = tf32r(a4.x);
                Wt[(k4 + 1) * 72 + m] = tf32r(a4.y);
                Wt[(k4 + 2) * 72 + m] = tf32r(a4.z);
                Wt[(k4 + 3) * 72 + m] = tf32r(a4.w);
            }
        }
        {
            int n4 = (tid & 15) << 2;
            #pragma unroll
            for (int kk = tid >> 4; kk < 64; kk += 16) {
                float4 b4 = *(const float4*)&x1[(size_t)(kc + kk) * HW + n0 + n4];
                float* bp2 = &Bt[kk * 72 + n4];
                bp2[0] = tf32r(b4.x); bp2[1] = tf32r(b4.y);
                bp2[2] = tf32r(b4.z); bp2[3] = tf32r(b4.w);
            }
        }
        __syncthreads();
        #pragma unroll
        for (int ks = 0; ks < 8; ++ks) {
            int k0 = ks * 8;
            uint32_t a0 = __float_as_uint(Wt[(k0 + lk) * 72 + i0w + lrow]);
            uint32_t a1 = __float_as_uint(Wt[(k0 + lk) * 72 + i0w + lrow + 8]);
            uint32_t a2 = __float_as_uint(Wt[(k0 + lk + 4) * 72 + i0w + lrow]);
            uint32_t a3 = __float_as_uint(Wt[(k0 + lk + 4) * 72 + i0w + lrow + 8]);
            #pragma unroll
            for (int np = 0; np < 4; ++np) {
                int ncol = jbase + np * 8 + lrow;
                uint32_t b0 = __float_as_uint(Bt[(k0 + lk) * 72 + ncol]);
                uint32_t b1 = __float_as_uint(Bt[(k0 + lk + 4) * 72 + ncol]);
                mma_tf32(sf[np], a0, a1, a2, a3, b0, b1);
            }
        }
        __syncthreads();
    }

    const int cc0 = 2 * lk;
    #pragma unroll
    for (int rr = 0; rr < 2; ++rr) {
        int gm = m0 + i0w + lrow + rr * 8;
        float bsv = bias[gm];
        #pragma unroll
        for (int nt = 0; nt < 4; ++nt) {
            float e0 = sf[nt][rr * 2 + 0] + bsv;
            float e1 = sf[nt][rr * 2 + 1] + bsv;
            size_t idx = (size_t)gm * HW + n0 + jbase + nt * 8 + cc0;
            if (z == 0) {
                *(float2*)&qf[idx] = make_float2(e0, e1);
                *(__nv_bfloat162*)&qb[idx] = __floats2bfloat162_rn(e0, e1);
            } else if (z == 1) {
                *(__nv_bfloat162*)&kb[idx] = __floats2bfloat162_rn(e0, e1);
            } else if (z == 2) {
                *(__half2*)&vh[idx] = __floats2half2_rn(e0, e1);
            } else {
                *(float2*)&pf[idx] = make_float2(e0, e1);
            }
        }
    }
}

// ---------------- stacked k-major GEMM: C[160][HW] ---------------------------
__global__ void __launch_bounds__(256) krgemm(
    const float* __restrict__ a_lo, const float* __restrict__ a_hi,
    const float* __restrict__ B, float* __restrict__ C)
{
    __shared__ float Wt[64 * 72];
    __shared__ float Bt[64 * 72];
    const int tid = threadIdx.x;
    const int wid = tid >> 5, lane = tid & 31;
    const int m0 = blockIdx.y * 64, n0 = blockIdx.x * 64;
    const int i0w = (wid & 3) * 16;
    const int jbase = (wid >> 2) * 32;
    const int lrow = lane >> 2, lk = lane & 3;
    const int M = 2 * NH;

    float sf[4][4];
    #pragma unroll
    for (int nt = 0; nt < 4; ++nt)
        #pragma unroll
        for (int e = 0; e < 4; ++e) sf[nt][e] = 0.f;

    for (int kc = 0; kc < NC; kc += 64) {
        {
            #pragma unroll
            for (int kk = tid >> 4; kk < 64; kk += 16) {
                #pragma unroll
                for (int mi = tid & 15; mi < 64; mi += 16) {
                    int gm = m0 + mi;
                    float vA = 0.f;
                    if (gm < NH)          vA = a_lo[(size_t)(kc + kk) * NH + gm];
                    else if (gm < 2 * NH) vA = a_hi[(size_t)(kc + kk) * NH + gm - NH];
                    Wt[kk * 72 + mi] = tf32r(vA);
                }
            }
        }
        {
            int n4 = (tid & 15) << 2;
            #pragma unroll
            for (int kk = tid >> 4; kk < 64; kk += 16) {
                float4 b4 = *(const float4*)&B[(size_t)(kc + kk) * HW + n0 + n4];
                float* bp = &Bt[kk * 72 + n4];
                bp[0] = tf32r(b4.x); bp[1] = tf32r(b4.y);
                bp[2] = tf32r(b4.z); bp[3] = tf32r(b4.w);
            }
        }
        __syncthreads();
        #pragma unroll
        for (int ks = 0; ks < 8; ++ks) {
            int k0 = ks * 8;
            uint32_t a0 = __float_as_uint(Wt[(k0 + lk) * 72 + i0w + lrow]);
            uint32_t a1 = __float_as_uint(Wt[(k0 + lk) * 72 + i0w + lrow + 8]);
            uint32_t a2 = __float_as_uint(Wt[(k0 + lk + 4) * 72 + i0w + lrow]);
            uint32_t a3 = __float_as_uint(Wt[(k0 + lk + 4) * 72 + i0w + lrow + 8]);
            #pragma unroll
            for (int np = 0; np < 4; ++np) {
                int ncol = jbase + np * 8 + lrow;
                uint32_t b0 = __float_as_uint(Bt[(k0 + lk) * 72 + ncol]);
                uint32_t b1 = __float_as_uint(Bt[(k0 + lk + 4) * 72 + ncol]);
                mma_tf32(sf[np], a0, a1, a2, a3, b0, b1);
            }
        }
        __syncthreads();
    }

    const int cc0 = 2 * lk;
    #pragma unroll
    for (int rr = 0; rr < 2; ++rr) {
        int gm = m0 + i0w + lrow + rr * 8;
        if (gm >= M) continue;
        #pragma unroll
        for (int nt = 0; nt < 4; ++nt) {
            size_t idx = (size_t)gm * HW + n0 + jbase + nt * 8 + cc0;
            *(float2*)&C[idx] = make_float2(sf[nt][rr * 2 + 0], sf[nt][rr * 2 + 1]);
        }
    }
}

// ---------------- expnorm: PAB = softmax over 80 rows (both halves) ----------
__global__ void expnorm(const float* __restrict__ AB, float* __restrict__ PAB)
{
    int gid = blockIdx.x * blockDim.x + threadIdx.x;
    if (gid >= 2 * HW) return;
    int h = (gid >= HW) ? 1 : 0;
    int i = gid - h * HW;
    const float* src = AB  + (size_t)h * NH * HW;
    float*       dst = PAB + (size_t)h * NH * HW;
    float s = 0.f;
    for (int t = 0; t < NH; ++t) {
        float e = __expf(src[t * HW + i]);
        dst[t * HW + i] = e;
        s += e;
    }
    float inv = 1.f / s;
    for (int t = 0; t < NH; ++t) dst[t * HW + i] *= inv;
}

// ---------------- W3 = [w3@efh | w3@efw]  ([256][160], m-major) --------------
__global__ void __launch_bounds__(256) w3eff_kernel(
    const float* __restrict__ w3, const float* __restrict__ efh,
    const float* __restrict__ efw, float* __restrict__ W)
{
    __shared__ float sef[8][132];
    const int tid = threadIdx.x;
    const int wid = tid >> 5, lane = tid & 31;
    const int t0 = blockIdx.x * 8;
    for (int e = tid; e < 8 * 128; e += 256) {
        int tt = e >> 7, c = e & 127;
        int t = t0 + tt;
        sef[tt][c] = (t < NH) ? efh[c * NH + t] : efw[c * NH + t - NH];
    }
    __syncthreads();
    float4 se[8];
    #pragma unroll
    for (int tt = 0; tt < 8; ++tt) se[tt] = *(float4*)&sef[tt][lane * 4];
    for (int mi = 0; mi < 32; ++mi) {
        int m = wid * 32 + mi;
        float4 a = *(const float4*)&w3[(size_t)m * NC + lane * 4];
        float acc[8];
        #pragma unroll
        for (int tt = 0; tt < 8; ++tt)
            acc[tt] = a.x * se[tt].x + a.y * se[tt].y + a.z * se[tt].z + a.w * se[tt].w;
        #pragma unroll
        for (int tt = 0; tt < 8; ++tt)
            #pragma unroll
            for (int off = 16; off; off >>= 1)
                acc[tt] += __shfl_xor_sync(0xffffffffu, acc[tt], off);
        if (lane == 0)
            #pragma unroll
            for (int tt = 0; tt < 8; ++tt)
                W[(size_t)m * 160 + t0 + tt] = acc[tt];
    }
}

// ---------------- fused final ------------------------------------------------
// out = x + SiLU(BN2(w2@o1)) + SiLU(BN3(W3@PAB))   (K = 128 then 160)
__global__ void __launch_bounds__(256) final_gemm(
    const float* __restrict__ w2, const float* __restrict__ o1,
    const float* __restrict__ g2, const float* __restrict__ b2,
    const float* __restrict__ m2, const float* __restrict__ v2,
    const float* __restrict__ W3, const float* __restrict__ PAB,
    const float* __restrict__ g3, const float* __restrict__ b3,
    const float* __restrict__ m3, const float* __restrict__ v3,
    const float* __restrict__ x, float* __restrict__ out)
{
    __shared__ float Wt[64 * 72];
    __shared__ float Bt[64 * 72];
    const int tid = threadIdx.x;
    const int wid = tid >> 5, lane = tid & 31;
    const int m0 = blockIdx.y * 64, n0 = blockIdx.x * 64;
    const int i0w = (wid & 3) * 16;
    const int jbase = (wid >> 2) * 32;
    const int lrow = lane >> 2, lk = lane & 3;

    float keep[4][4];
    float sf[4][4];
    #pragma unroll
    for (int nt = 0; nt < 4; ++nt)
        #pragma unroll
        for (int e = 0; e < 4; ++e) sf[nt][e] = 0.f;

    #pragma unroll
    for (int src = 0; src < 2; ++src) {
        const float* Ap = src ? W3 : w2;
        const float* Bp = src ? PAB : o1;
        const int Kp = src ? 160 : NC;
        for (int kc = 0; kc < Kp; kc += 64) {
            const int ck = (Kp - kc < 64) ? (Kp - kc) : 64;
            {
                int m = tid >> 2;
                for (int k4 = (tid & 3) << 2; k4 < ck; k4 += 16) {
                    float4 a4 = *(const float4*)&Ap[(size_t)(m0 + m) * Kp + kc + k4];
                    Wt[(k4 + 0) * 72 + m] = tf32r(a4.x);
                    Wt[(k4 + 1) * 72 + m] = tf32r(a4.y);
                    Wt[(k4 + 2) * 72 + m] = tf32r(a4.z);
                    Wt[(k4 + 3) * 72 + m] = tf32r(a4.w);
                }
            }
            {
                int n4 = (tid & 15) << 2;
                for (int kk = tid >> 4; kk < ck; kk += 16) {
                    float4 b4 = *(const float4*)&Bp[(size_t)(kc + kk) * HW + n0 + n4];
                    float* bp = &Bt[kk * 72 + n4];
                    bp[0] = tf32r(b4.x); bp[1] = tf32r(b4.y);
                    bp[2] = tf32r(b4.z); bp[3] = tf32r(b4.w);
                }
            }
            __syncthreads();
            const int nks = ck >> 3;
            for (int ks = 0; ks < nks; ++ks) {
                int k0 = ks * 8;
                uint32_t a0 = __float_as_uint(Wt[(k0 + lk) * 72 + i0w + lrow]);
                uint32_t a1 = __float_as_uint(Wt[(k0 + lk) * 72 + i0w + lrow + 8]);
                uint32_t a2 = __float_as_uint(Wt[(k0 + lk + 4) * 72 + i0w + lrow]);
                uint32_t a3 = __float_as_uint(Wt[(k0 + lk + 4) * 72 + i0w + lrow + 8]);
                #pragma unroll
                for (int np = 0; np < 4; ++np) {
                    int ncol = jbase + np * 8 + lrow;
                    uint32_t b0 = __float_as_uint(Bt[(k0 + lk) * 72 + ncol]);
                    uint32_t b1 = __float_as_uint(Bt[(k0 + lk + 4) * 72 + ncol]);
                    mma_tf32(sf[np], a0, a1, a2, a3, b0, b1);
                }
            }
            __syncthreads();
        }
        const float* gg  = src ? g3 : g2;
        const float* bbp = src ? b3 : b2;
        const float* mmp = src ? m3 : m2;
        const float* vvp = src ? v3 : v2;
        #pragma unroll
        for (int rr = 0; rr < 2; ++rr) {
            int gm = m0 + i0w + lrow + rr * 8;
            float sc = gg[gm] * rsqrtf(vvp[gm] + EPS);
            float sh = bbp[gm] - mmp[gm] * sc;
            #pragma unroll
            for (int nt = 0; nt < 4; ++nt) {
                #pragma unroll
                for (int e2 = 0; e2 < 2; ++e2) {
                    float val = sf[nt][rr * 2 + e2] * sc + sh;
                    val = val / (1.f + __expf(-val));
                    if (src == 0) { keep[nt][rr * 2 + e2] = val; sf[nt][rr * 2 + e2] = 0.f; }
                    else          { keep[nt][rr * 2 + e2] += val; }
                }
            }
        }
    }

    const int cc0 = 2 * lk;
    #pragma unroll
    for (int rr = 0; rr < 2; ++rr) {
        int gm = m0 + i0w + lrow + rr * 8;
        #pragma unroll
        for (int nt = 0; nt < 4; ++nt) {
            size_t idx = (size_t)gm * HW + n0 + jbase + nt * 8 + cc0;
            float2 x2 = *(const float2*)&x[idx];
            *(float2*)&out[idx] = make_float2(keep[nt][rr * 2 + 0] + x2.x,
                                              keep[nt][rr * 2 + 1] + x2.y);
        }
    }
}

// ---------------- branch-1 flash attention (bf16 QK, fp16 P/V, f16x2 exp) ----
#define QS_OFF   0               // bf16 [128][72]
#define KS_OFF   18432           // bf16 [128][72]
#define VS_OFF   36864           // f16  [128][72]
#define PS_OFF   55296           // f16  [64][72]
#define SS_OFF   64512           // f32  [64][72]
#define RWS_OFF  82944           // f32  [64][68]
#define RHS_OFF  100352          // f32  [2][68]
#define MR_OFF   100896          // f32  [64]
#define LR_OFF   101152
#define FR_OFF   101408
#define FL_SM_BYTES 101760

__global__ void __launch_bounds__(256, 2) flash_kernel(
    const __nv_bfloat16* __restrict__ q, const __nv_bfloat16* __restrict__ k,
    const __half* __restrict__ v, const float* __restrict__ Rh,
    const float* __restrict__ Rw, float* __restrict__ op,
    float* __restrict__ mp, float* __restrict__ lp)
{
    extern __shared__ char smc[];
    __nv_bfloat16* Qs = (__nv_bfloat16*)(smc + QS_OFF);
    __half* Ps = (__half*)(smc + PS_OFF);
    float* Ss   = (float*)(smc + SS_OFF);
    float* Rws  = (float*)(smc + RWS_OFF);
    float* Rhs  = (float*)(smc + RHS_OFF);
    float* mrow = (float*)(smc + MR_OFF);
    float* lrow = (float*)(smc + LR_OFF);
    float* frow = (float*)(smc + FR_OFF);

    const int tid  = threadIdx.x;
    const int wid  = tid >> 5, lane = tid & 31;
    const int lr   = lane & 7, gq = lane >> 3;
    const int i0   = blockIdx.x * 64;
    const int spl  = blockIdx.y;
    const int t0   = (spl * 100) / SPLIT;
    const int t1   = ((spl + 1) * 100) / SPLIT;
    const int h0   = i0 / 80;
    const int i0w  = (wid & 3) * 16;
    const int jbase = (wid >> 2) * 32;
    const int cbase = (wid >> 2) * 64;
    const float L2E = 1.4426950408889634f;

    const uint32_t qsb = (uint32_t)__cvta_generic_to_shared(Qs);
    const uint32_t ksb = (uint32_t)__cvta_generic_to_shared(smc + KS_OFF);
    const uint32_t vsb = (uint32_t)__cvta_generic_to_shared(smc + VS_OFF);
    const uint32_t psb = (uint32_t)__cvta_generic_to_shared(Ps);

    {   // prologue: K(t0), V(t0) via cp.async
        int j0n = t0 * 64;
        #pragma unroll
        for (int it = 0; it < 4; ++it) {
            int ch = tid + it * 256;
            int c = ch >> 3, j8 = (ch & 7) * 8;
            cpa16(ksb + (uint32_t)((c * 72 + j8) * 2), &k[(size_t)c * HW + j0n + j8]);
        }
        CPA_COMMIT();
        #pragma unroll
        for (int it = 0; it < 4; ++it) {
            int ch = tid + it * 256;
            int c = ch >> 3, j8 = (ch & 7) * 8;
            cpa16(vsb + (uint32_t)((c * 72 + j8) * 2), &v[(size_t)c * HW + j0n + j8]);
        }
        CPA_COMMIT();
    }
    {   // Q tile bf16 [c][i]
        int cr = tid >> 4, i4 = (tid & 15) << 2;
        #pragma unroll
        for (int it = 0; it < 8; ++it) {
            int c = cr + it * 16;
            *(uint2*)&Qs[c * 72 + i4] = *(const uint2*)&q[(size_t)c * HW + i0 + i4];
        }
    }
    if (tid < 64) { mrow[tid] = -1e30f; lrow[tid] = 0.f; }

    float d[8][4];
    #pragma unroll
    for (int nt = 0; nt < 8; ++nt)
        #pragma unroll
        for (int e = 0; e < 4; ++e) d[nt][e] = 0.f;

    for (int t = t0; t < t1; ++t) {
        const int j0 = t * 64;
        const bool more = (t + 1 < t1);
        #pragma unroll
        for (int e = 0; e < 4; ++e) {
            int ee = tid + e * 256;
            int row = ee >> 4, c4 = (ee & 15) << 2;
            int wr = (i0 + row) % 80;
            *(float4*)&Rws[row * 68 + c4] = *(const float4*)&Rw[wr * HW + j0 + c4];
        }
        if (tid < 128) {
            int sel = tid >> 6, col = tid & 63;
            int hh = sel ? (i0 + 63) / 80 : h0;
            Rhs[sel * 68 + col] = Rh[hh * HW + j0 + col];
        }
        asm volatile("cp.async.wait_group 1;");
        __syncthreads();

        // ---- QK^T (bf16) ----
        float sf[4][4];
        #pragma unroll
        for (int nt = 0; nt < 4; ++nt)
            #pragma unroll
            for (int e = 0; e < 4; ++e) sf[nt][e] = 0.f;

        #pragma unroll
        for (int ks = 0; ks < 8; ++ks) {
            int k0 = ks * 16;
            uint32_t a0, a1, a2, a3;
            ldsm4t(a0, a1, a2, a3,
                   qsb + (uint32_t)(((k0 + lr + (gq >> 1) * 8) * 72 + i0w + (gq & 1) * 8) * 2));
            #pragma unroll
            for (int np = 0; np < 2; ++np) {
                int jb = jbase + np * 16;
                uint32_t b0, b1, b2, b3;
                ldsm4t(b0, b1, b2, b3,
                       ksb + (uint32_t)(((k0 + lr + (gq & 1) * 8) * 72 + jb + (gq >> 1) * 8) * 2));
                mma_bf16(sf[np * 2],     a0, a1, a2, a3, b0, b1);
                mma_bf16(sf[np * 2 + 1], a0, a1, a2, a3, b2, b3);
            }
        }
        {
            int row = i0w + (lane >> 2);
            int cc = 2 * (lane & 3);
            #pragma unroll
            for (int nt = 0; nt < 4; ++nt) {
                int col = jbase + nt * 8 + cc;
                *(float2*)&Ss[row * 72 + col]       = make_float2(sf[nt][0], sf[nt][1]);
                *(float2*)&Ss[(row + 8) * 72 + col] = make_float2(sf[nt][2], sf[nt][3]);
            }
        }
        __syncthreads();

        if (more) {   // K(t+1) in place
            int j0n = (t + 1) * 64;
            #pragma unroll
            for (int it = 0; it < 4; ++it) {
                int ch = tid + it * 256;
                int c = ch >> 3, j8 = (ch & 7) * 8;
                cpa16(ksb + (uint32_t)((c * 72 + j8) * 2), &k[(size_t)c * HW + j0n + j8]);
            }
            CPA_COMMIT();
        }

        // ---- online softmax with f16x2 exp; P stored fp16 ----
        #pragma unroll
        for (int r8 = 0; r8 < 8; ++r8) {
            int r = wid * 8 + r8;
            int rs = (((i0 + r) / 80) != h0) ? 1 : 0;
            float v1 = Ss[r * 72 + lane]      + Rhs[rs * 68 + lane]      + Rws[r * 68 + lane];
            float v2 = Ss[r * 72 + 32 + lane] + Rhs[rs * 68 + 32 + lane] + Rws[r * 68 + 32 + lane];
            float tm = fmaxf(v1, v2);
            #pragma unroll
            for (int off = 16; off; off >>= 1)
                tm = fmaxf(tm, __shfl_xor_sync(0xffffffffu, tm, off));
            float mold = mrow[r];
            float nm = fmaxf(mold, tm);
            float u1 = (v1 - nm) * L2E, u2 = (v2 - nm) * L2E;
            uint32_t ph;
            asm("cvt.rn.f16x2.f32 %0, %1, %2;" : "=r"(ph) : "f"(u2), "f"(u1));
            asm("ex2.approx.f16x2 %0, %0;" : "+r"(ph));
            __half2 hh = *reinterpret_cast<__half2*>(&ph);
            float e1 = __half2float(hh.x), e2 = __half2float(hh.y);
            float ssum = e1 + e2;
            #pragma unroll
            for (int off = 16; off; off >>= 1)
                ssum += __shfl_xor_sync(0xffffffffu, ssum, off);
            Ps[r * 72 + lane]      = hh.x;
            Ps[r * 72 + 32 + lane] = hh.y;
            if (lane == 0) {
                float f = __expf(mold - nm);
                lrow[r] = lrow[r] * f + ssum;
                mrow[r] = nm;
                frow[r] = f;
            }
        }
        if (more) asm volatile("cp.async.wait_group 1;");
        else      asm volatile("cp.async.wait_group 0;");
        __syncthreads();

        // ---- rescale O, then P @ V^T (fp16) ----
        {
            float f0 = frow[i0w + (lane >> 2)];
            float f1 = frow[i0w + 8 + (lane >> 2)];
            #pragma unroll
            for (int nt = 0; nt < 8; ++nt) {
                d[nt][0] *= f0; d[nt][1] *= f0;
                d[nt][2] *= f1; d[nt][3] *= f1;
            }
        }
        #pragma unroll
        for (int ks = 0; ks < 4; ++ks) {
            int j0s = ks * 16;
            uint32_t a0, a1, a2, a3;
            ldsm4(a0, a1, a2, a3,
                  psb + (uint32_t)(((i0w + lr + (gq & 1) * 8) * 72 + j0s + (gq >> 1) * 8) * 2));
            #pragma unroll
            for (int np = 0; np < 4; ++np) {
                int cb = cbase + np * 16;
                uint32_t b0, b1, b2, b3;
                ldsm4(b0, b1, b2, b3,
                      vsb + (uint32_t)(((cb + lr + (gq >> 1) * 8) * 72 + j0s + (gq & 1) * 8) * 2));
                mma_f16(d[np * 2],     a0, a1, a2, a3, b0, b1);
                mma_f16(d[np * 2 + 1], a0, a1, a2, a3, b2, b3);
            }
        }
        __syncthreads();

        if (more) {   // V(t+1)
            int j0n = (t + 1) * 64;
            #pragma unroll
            for (int it = 0; it < 4; ++it) {
                int ch = tid + it * 256;
                int c = ch >> 3, j8 = (ch & 7) * 8;
                cpa16(vsb + (uint32_t)((c * 72 + j8) * 2), &v[(size_t)c * HW + j0n + j8]);
            }
            CPA_COMMIT();
        }
    }

    {   // emit partials
        int row0 = i0w + (lane >> 2);
        int cc = 2 * (lane & 3);
        #pragma unroll
        for (int nt = 0; nt < 8; ++nt) {
            int c = cbase + nt * 8 + cc;
            op[(spl * NC + c)     * HW + i0 + row0]     = d[nt][0];
            op[(spl * NC + c + 1) * HW + i0 + row0]     = d[nt][1];
            op[(spl * NC + c)     * HW + i0 + row0 + 8] = d[nt][2];
            op[(spl * NC + c + 1) * HW + i0 + row0 + 8] = d[nt][3];
        }
    }
    if (tid < 64) {
        mp[spl * HW + i0 + tid] = mrow[tid];
        lp[spl * HW + i0 + tid] = lrow[tid];
    }
}

// ---------------- split-j combine (channel-parallel) -------------------------
__global__ void combine_kernel(const float* __restrict__ op,
                               const float* __restrict__ mp,
                               const float* __restrict__ lp,
                               float* __restrict__ out1)
{
    int i = blockIdx.x * blockDim.x + threadIdx.x;
    if (i >= HW) return;
    int c0 = blockIdx.y * 8;
    float m[SPLIT], w[SPLIT];
    float M = -1e30f;
    #pragma unroll
    for (int s = 0; s < SPLIT; ++s) { m[s] = mp[s * HW + i]; M = fmaxf(M, m[s]); }
    float L = 0.f;
    #pragma unroll
    for (int s = 0; s < SPLIT; ++s) { w[s] = __expf(m[s] - M); L += lp[s * HW + i] * w[s]; }
    float inv = 1.f / L;
    for (int c = c0; c < c0 + 8; ++c) {
        float acc = 0.f;
        #pragma unroll
        for (int s = 0; s < SPLIT; ++s)
            acc += op[((size_t)(s * NC + c)) * HW + i] * w[s];
        out1[(size_t)c * HW + i] = acc * inv;
    }
}

// -------------------------------- launch -------------------------------------
extern "C" void kernel_launch(void* const* d_in, const int* in_sizes, int n_in,
                              void* d_out, int out_size)
{
    (void)in_sizes; (void)n_in; (void)out_size;
    const float* x    = (const float*)d_in[0];
    const float* w1   = (const float*)d_in[1];
    const float* g1   = (const float*)d_in[2];
    const float* b1   = (const float*)d_in[3];
    const float* m1   = (const float*)d_in[4];
    const float* v1   = (const float*)d_in[5];
    const float* w2   = (const float*)d_in[6];
    const float* g2   = (const float*)d_in[7];
    const float* b2   = (const float*)d_in[8];
    const float* m2   = (const float*)d_in[9];
    const float* v2   = (const float*)d_in[10];
    const float* w3   = (const float*)d_in[11];
    const float* g3   = (const float*)d_in[12];
    const float* b3   = (const float*)d_in[13];
    const float* m3   = (const float*)d_in[14];
    const float* v3   = (const float*)d_in[15];
    const float* wq   = (const float*)d_in[16];
    const float* bq   = (const float*)d_in[17];
    const float* wk   = (const float*)d_in[18];
    const float* bk   = (const float*)d_in[19];
    const float* wv   = (const float*)d_in[20];
    const float* bv   = (const float*)d_in[21];
    const float* wp   = (const float*)d_in[22];
    const float* bp   = (const float*)d_in[23];
    const float* relh = (const float*)d_in[24];
    const float* relw = (const float*)d_in[25];
    const float* efh  = (const float*)d_in[26];
    const float* efw  = (const float*)d_in[27];
    float* out = (float*)d_out;

    float *px1, *pq, *pp, *pRW, *pAB, *pPAB, *pW3, *po1, *pop, *pmp, *plp;
    __nv_bfloat16 *pqb, *pkb;
    __half *pvh;
    cudaGetSymbolAddress((void**)&px1, d_x1);
    cudaGetSymbolAddress((void**)&pq,  d_q);
    cudaGetSymbolAddress((void**)&pp,  d_p);
    cudaGetSymbolAddress((void**)&pqb, d_qb);
    cudaGetSymbolAddress((void**)&pkb, d_kb);
    cudaGetSymbolAddress((void**)&pvh, d_vh);
    cudaGetSymbolAddress((void**)&pRW, d_RW);
    cudaGetSymbolAddress((void**)&pAB, d_AB);
    cudaGetSymbolAddress((void**)&pPAB, d_PAB);
    cudaGetSymbolAddress((void**)&pW3, d_W3);
    cudaGetSymbolAddress((void**)&po1, d_o1);
    cudaGetSymbolAddress((void**)&pop, d_op);
    cudaGetSymbolAddress((void**)&pmp, d_mp);
    cudaGetSymbolAddress((void**)&plp, d_lp);

    cudaFuncSetAttribute(flash_kernel,
        cudaFuncAttributeMaxDynamicSharedMemorySize, FL_SM_BYTES);

    dim3 g100_2(100, 2), g100_3(100, 3), g100_4(100, 4);
    dim3 gproj(100, 2, 4), gfl(100, SPLIT), gcmb(25, 16);

    // [0] x1 = SiLU(BN(w1 @ x))
    tgemm<2><<<g100_2, 256>>>(w1, x, px1, NC, ND, g1, b1, m1, v1);
    // [1] fused q/k/v/p projections (fp32 q,p; bf16 q,k; fp16 v)
    proj4<<<gproj, 256>>>(px1, wq, bq, wk, bk, wv, bv, wp, bp,
        pq, pqb, pkb, pvh, pp);
    // [2] [Rh; Rw] = [rel_h; rel_w]^T q
    krgemm<<<g100_3, 256>>>(relh, relw, pq, pRW);
    // [3] flash attention (split-j = 6)
    flash_kernel<<<gfl, 256, FL_SM_BYTES>>>(pqb, pkb, pvh,
        pRW, pRW + NH * HW, pop, pmp, plp);
    // [4] [ABh; ABw] = [ef_h; ef_w]^T p
    krgemm<<<g100_3, 256>>>(efh, efw, pp, pAB);
    // [5] PAB = per-column softmax of both halves
    expnorm<<<50, 256>>>(pAB, pPAB);
    // [6] W3 = [w3@efh | w3@efw]
    w3eff_kernel<<<20, 256>>>(w3, efh, efw, pW3);
    // [7] combine split partials -> out1
    combine_kernel<<<gcmb, 256>>>(pop, pmp, plp, po1);
    // [8] out = x + SiLU(BN2(w2@o1)) + SiLU(BN3(W3@PAB))
    final_gemm<<<g100_4, 256>>>(w2, po1, g2, b2, m2, v2,
        pW3, pPAB, g3, b3, m3, v3, x, out);
}

// round 8
// speedup vs baseline: 5.4251x; 1.2423x over previous
#include <cuda_runtime.h>
#include <cuda_bf16.h>
#include <cuda_fp16.h>
#include <cstdint>

#define EPS 1e-5f
#define HW 6400
#define NC 128
#define ND 256
#define NH 80
#define SPLIT 8

// ---------------- tensor-core helpers ----------------------------------------
__device__ __forceinline__ void ldsm4(uint32_t& r0, uint32_t& r1,
                                      uint32_t& r2, uint32_t& r3, uint32_t a) {
    asm volatile("ldmatrix.sync.aligned.m8n8.x4.shared.b16 {%0,%1,%2,%3},[%4];"
        : "=r"(r0), "=r"(r1), "=r"(r2), "=r"(r3) : "r"(a));
}
__device__ __forceinline__ void ldsm4t(uint32_t& r0, uint32_t& r1,
                                       uint32_t& r2, uint32_t& r3, uint32_t a) {
    asm volatile("ldmatrix.sync.aligned.m8n8.x4.trans.shared.b16 {%0,%1,%2,%3},[%4];"
        : "=r"(r0), "=r"(r1), "=r"(r2), "=r"(r3) : "r"(a));
}
__device__ __forceinline__ void mma_bf16(float* d, uint32_t a0, uint32_t a1,
                                         uint32_t a2, uint32_t a3,
                                         uint32_t b0, uint32_t b1) {
    asm volatile("mma.sync.aligned.m16n8k16.row.col.f32.bf16.bf16.f32 "
        "{%0,%1,%2,%3},{%4,%5,%6,%7},{%8,%9},{%0,%1,%2,%3};"
        : "+f"(d[0]), "+f"(d[1]), "+f"(d[2]), "+f"(d[3])
        : "r"(a0), "r"(a1), "r"(a2), "r"(a3), "r"(b0), "r"(b1));
}
__device__ __forceinline__ void mma_f16(float* d, uint32_t a0, uint32_t a1,
                                        uint32_t a2, uint32_t a3,
                                        uint32_t b0, uint32_t b1) {
    asm volatile("mma.sync.aligned.m16n8k16.row.col.f32.f16.f16.f32 "
        "{%0,%1,%2,%3},{%4,%5,%6,%7},{%8,%9},{%0,%1,%2,%3};"
        : "+f"(d[0]), "+f"(d[1]), "+f"(d[2]), "+f"(d[3])
        : "r"(a0), "r"(a1), "r"(a2), "r"(a3), "r"(b0), "r"(b1));
}
__device__ __forceinline__ void mma_tf32(float* d, uint32_t a0, uint32_t a1,
                                         uint32_t a2, uint32_t a3,
                                         uint32_t b0, uint32_t b1) {
    asm volatile("mma.sync.aligned.m16n8k8.row.col.f32.tf32.tf32.f32 "
        "{%0,%1,%2,%3},{%4,%5,%6,%7},{%8,%9},{%0,%1,%2,%3};"
        : "+f"(d[0]), "+f"(d[1]), "+f"(d[2]), "+f"(d[3])
        : "r"(a0), "r"(a1), "r"(a2), "r"(a3), "r"(b0), "r"(b1));
}
__device__ __forceinline__ float tf32r(float x) {
    uint32_t r;
    asm("cvt.rna.tf32.f32 %0, %1;" : "=r"(r) : "f"(x));
    return __uint_as_float(r);
}
__device__ __forceinline__ void cpa16(uint32_t s, const void* g) {
    asm volatile("cp.async.cg.shared.global [%0], [%1], 16;" :: "r"(s), "l"(g));
}
#define CPA_COMMIT() asm volatile("cp.async.commit_group;")

// ---------------- scratch (static device globals; no allocation) -------------
__device__ float d_x1 [NC*HW];
__device__ float d_q  [NC*HW];
__device__ float d_p  [NC*HW];
__device__ __nv_bfloat16 d_qb[NC*HW];
__device__ __nv_bfloat16 d_kb[NC*HW];
__device__ __half d_vh[NC*HW];
__device__ float d_RW  [2*NH*HW];   // [Rh(80); Rw(80)]
__device__ float d_AB  [2*NH*HW];   // [ABh(80); ABw(80)]
__device__ float d_PAB [2*NH*HW];   // normalized [PA(80); PB(80)]
__device__ float d_W3  [ND*2*NH];   // [w3@efh | w3@efw]  m-major [256][160]
__device__ float d_o1  [NC*HW];
__device__ float d_op  [SPLIT*NC*HW];
__device__ float d_mp  [SPLIT*HW];
__device__ float d_lp  [SPLIT*HW];

// ---------------- tf32 GEMM (x1 conv) -----------------------------------------
template<int EPI>
__global__ void __launch_bounds__(256) tgemm(
    const float* __restrict__ A, const float* __restrict__ B,
    float* __restrict__ C, int M, int K,
    const float* __restrict__ g, const float* __restrict__ bb,
    const float* __restrict__ mm, const float* __restrict__ vv)
{
    __shared__ float Wt[64 * 72];
    __shared__ float Bt[64 * 72];
    const int tid = threadIdx.x;
    const int wid = tid >> 5, lane = tid & 31;
    const int m0 = blockIdx.y * 64, n0 = blockIdx.x * 64;
    const int i0w = (wid & 3) * 16;
    const int jbase = (wid >> 2) * 32;
    const int lrow = lane >> 2, lk = lane & 3;

    float sf[4][4];
    #pragma unroll
    for (int nt = 0; nt < 4; ++nt)
        #pragma unroll
        for (int e = 0; e < 4; ++e) sf[nt][e] = 0.f;

    for (int kc = 0; kc < K; kc += 64) {
        {
            int m = tid >> 2;
            #pragma unroll
            for (int k4 = (tid & 3) << 2; k4 < 64; k4 += 16) {
                float4 a4 = *(const float4*)&A[(size_t)(m0 + m) * K + kc + k4];
                Wt[(k4 + 0) * 72 + m] = tf32r(a4.x);
                Wt[(k4 + 1) * 72 + m] = tf32r(a4.y);
                Wt[(k4 + 2) * 72 + m] = tf32r(a4.z);
                Wt[(k4 + 3) * 72 + m] = tf32r(a4.w);
            }
        }
        {
            int n4 = (tid & 15) << 2;
            #pragma unroll
            for (int kk = tid >> 4; kk < 64; kk += 16) {
                float4 b4 = *(const float4*)&B[(size_t)(kc + kk) * HW + n0 + n4];
                float* bp = &Bt[kk * 72 + n4];
                bp[0] = tf32r(b4.x); bp[1] = tf32r(b4.y);
                bp[2] = tf32r(b4.z); bp[3] = tf32r(b4.w);
            }
        }
        __syncthreads();
        #pragma unroll
        for (int ks = 0; ks < 8; ++ks) {
            int k0 = ks * 8;
            uint32_t a0 = __float_as_uint(Wt[(k0 + lk) * 72 + i0w + lrow]);
            uint32_t a1 = __float_as_uint(Wt[(k0 + lk) * 72 + i0w + lrow + 8]);
            uint32_t a2 = __float_as_uint(Wt[(k0 + lk + 4) * 72 + i0w + lrow]);
            uint32_t a3 = __float_as_uint(Wt[(k0 + lk + 4) * 72 + i0w + lrow + 8]);
            #pragma unroll
            for (int np = 0; np < 4; ++np) {
                int ncol = jbase + np * 8 + lrow;
                uint32_t b0 = __float_as_uint(Bt[(k0 + lk) * 72 + ncol]);
                uint32_t b1 = __float_as_uint(Bt[(k0 + lk + 4) * 72 + ncol]);
                mma_tf32(sf[np], a0, a1, a2, a3, b0, b1);
            }
        }
        __syncthreads();
    }

    const int cc0 = 2 * lk;
    #pragma unroll
    for (int rr = 0; rr < 2; ++rr) {
        int gm = m0 + i0w + lrow + rr * 8;
        float sc = 0.f, sh = 0.f;
        if (EPI == 2) {
            sc = g[gm] * rsqrtf(vv[gm] + EPS);
            sh = bb[gm] - mm[gm] * sc;
        }
        #pragma unroll
        for (int nt = 0; nt < 4; ++nt) {
            float e0 = sf[nt][rr * 2 + 0];
            float e1 = sf[nt][rr * 2 + 1];
            if (EPI == 2) {
                e0 = e0 * sc + sh; e1 = e1 * sc + sh;
                e0 = e0 / (1.f + __expf(-e0));
                e1 = e1 / (1.f + __expf(-e1));
            }
            size_t idx = (size_t)gm * HW + n0 + jbase + nt * 8 + cc0;
            *(float2*)&C[idx] = make_float2(e0, e1);
        }
    }
}

// ---------------- fused q/k/v/p projection (z selects weight) ----------------
__global__ void __launch_bounds__(256) proj4(
    const float* __restrict__ x1,
    const float* __restrict__ wq, const float* __restrict__ bq,
    const float* __restrict__ wk, const float* __restrict__ bk,
    const float* __restrict__ wv, const float* __restrict__ bv,
    const float* __restrict__ wp, const float* __restrict__ bp,
    float* __restrict__ qf, __nv_bfloat16* __restrict__ qb,
    __nv_bfloat16* __restrict__ kb, __half* __restrict__ vh,
    float* __restrict__ pf)
{
    __shared__ float Wt[64 * 72];
    __shared__ float Bt[64 * 72];
    const int z = blockIdx.z;
    const float* A    = (z == 0) ? wq : (z == 1) ? wk : (z == 2) ? wv : wp;
    const float* bias = (z == 0) ? bq : (z == 1) ? bk : (z == 2) ? bv : bp;
    const int tid = threadIdx.x;
    const int wid = tid >> 5, lane = tid & 31;
    const int m0 = blockIdx.y * 64, n0 = blockIdx.x * 64;
    const int i0w = (wid & 3) * 16;
    const int jbase = (wid >> 2) * 32;
    const int lrow = lane >> 2, lk = lane & 3;

    float sf[4][4];
    #pragma unroll
    for (int nt = 0; nt < 4; ++nt)
        #pragma unroll
        for (int e = 0; e < 4; ++e) sf[nt][e] = 0.f;

    for (int kc = 0; kc < NC; kc += 64) {
        {
            int m = tid >> 2;
            #pragma unroll
            for (int k4 = (tid & 3) << 2; k4 < 64; k4 += 16) {
                float4 a4 = *(const float4*)&A[(size_t)(m0 + m) * NC + kc + k4];
                Wt[(k4 + 0) * 72 + m] = tf32r(a4.x);
                Wt[(k4 + 1) * 72 + m] = tf32r(a4.y);
                Wt[(k4 + 2) * 72 + m] = tf32r(a4.z);
                Wt[(k4 + 3) * 72 + m] = tf32r(a4.w);
            }
        }
        {
            int n4 = (tid & 15) << 2;
            #pragma unroll
            for (int kk = tid >> 4; kk < 64; kk += 16) {
                float4 b4 = *(const float4*)&x1[(size_t)(kc + kk) * HW + n0 + n4];
                float* bp2 = &Bt[kk * 72 + n4];
                bp2[0] = tf32r(b4.x); bp2[1] = tf32r(b4.y);
                bp2[2] = tf32r(b4.z); bp2[3] = tf32r(b4.w);
            }
        }
        __syncthreads();
        #pragma unroll
        for (int ks = 0; ks < 8; ++ks) {
            int k0 = ks * 8;
            uint32_t a0 = __float_as_uint(Wt[(k0 + lk) * 72 + i0w + lrow]);
            uint32_t a1 = __float_as_uint(Wt[(k0 + lk) * 72 + i0w + lrow + 8]);
            uint32_t a2 = __float_as_uint(Wt[(k0 + lk + 4) * 72 + i0w + lrow]);
            uint32_t a3 = __float_as_uint(Wt[(k0 + lk + 4) * 72 + i0w + lrow + 8]);
            #pragma unroll
            for (int np = 0; np < 4; ++np) {
                int ncol = jbase + np * 8 + lrow;
                uint32_t b0 = __float_as_uint(Bt[(k0 + lk) * 72 + ncol]);
                uint32_t b1 = __float_as_uint(Bt[(k0 + lk + 4) * 72 + ncol]);
                mma_tf32(sf[np], a0, a1, a2, a3, b0, b1);
            }
        }
        __syncthreads();
    }

    const int cc0 = 2 * lk;
    #pragma unroll
    for (int rr = 0; rr < 2; ++rr) {
        int gm = m0 + i0w + lrow + rr * 8;
        float bsv = bias[gm];
        #pragma unroll
        for (int nt = 0; nt < 4; ++nt) {
            float e0 = sf[nt][rr * 2 + 0] + bsv;
            float e1 = sf[nt][rr * 2 + 1] + bsv;
            size_t idx = (size_t)gm * HW + n0 + jbase + nt * 8 + cc0;
            if (z == 0) {
                *(float2*)&qf[idx] = make_float2(e0, e1);
                *(__nv_bfloat162*)&qb[idx] = __floats2bfloat162_rn(e0, e1);
            } else if (z == 1) {
                *(__nv_bfloat162*)&kb[idx] = __floats2bfloat162_rn(e0, e1);
            } else if (z == 2) {
                *(__half2*)&vh[idx] = __floats2half2_rn(e0, e1);
            } else {
                *(float2*)&pf[idx] = make_float2(e0, e1);
            }
        }
    }
}

// ---------------- stacked k-major GEMM: C[160][HW] ---------------------------
__global__ void __launch_bounds__(256) krgemm(
    const float* __restrict__ a_lo, const float* __restrict__ a_hi,
    const float* __restrict__ B, float* __restrict__ C)
{
    __shared__ float Wt[64 * 72];
    __shared__ float Bt[64 * 72];
    const int tid = threadIdx.x;
    const int wid = tid >> 5, lane = tid & 31;
    const int m0 = blockIdx.y * 64, n0 = blockIdx.x * 64;
    const int i0w = (wid & 3) * 16;
    const int jbase = (wid >> 2) * 32;
    const int lrow = lane >> 2, lk = lane & 3;
    const int M = 2 * NH;

    float sf[4][4];
    #pragma unroll
    for (int nt = 0; nt < 4; ++nt)
        #pragma unroll
        for (int e = 0; e < 4; ++e) sf[nt][e] = 0.f;

    for (int kc = 0; kc < NC; kc += 64) {
        {   // A stage: vectorized (80 % 4 == 0, so float4 never straddles)
            int m4 = (tid & 15) << 2;
            int gm = m0 + m4;
            #pragma unroll
            for (int kk = tid >> 4; kk < 64; kk += 16) {
                float4 a4 = make_float4(0.f, 0.f, 0.f, 0.f);
                if (gm < NH)          a4 = *(const float4*)&a_lo[(size_t)(kc + kk) * NH + gm];
                else if (gm < 2 * NH) a4 = *(const float4*)&a_hi[(size_t)(kc + kk) * NH + gm - NH];
                float* wp = &Wt[kk * 72 + m4];
                wp[0] = tf32r(a4.x); wp[1] = tf32r(a4.y);
                wp[2] = tf32r(a4.z); wp[3] = tf32r(a4.w);
            }
        }
        {
            int n4 = (tid & 15) << 2;
            #pragma unroll
            for (int kk = tid >> 4; kk < 64; kk += 16) {
                float4 b4 = *(const float4*)&B[(size_t)(kc + kk) * HW + n0 + n4];
                float* bp = &Bt[kk * 72 + n4];
                bp[0] = tf32r(b4.x); bp[1] = tf32r(b4.y);
                bp[2] = tf32r(b4.z); bp[3] = tf32r(b4.w);
            }
        }
        __syncthreads();
        #pragma unroll
        for (int ks = 0; ks < 8; ++ks) {
            int k0 = ks * 8;
            uint32_t a0 = __float_as_uint(Wt[(k0 + lk) * 72 + i0w + lrow]);
            uint32_t a1 = __float_as_uint(Wt[(k0 + lk) * 72 + i0w + lrow + 8]);
            uint32_t a2 = __float_as_uint(Wt[(k0 + lk + 4) * 72 + i0w + lrow]);
            uint32_t a3 = __float_as_uint(Wt[(k0 + lk + 4) * 72 + i0w + lrow + 8]);
            #pragma unroll
            for (int np = 0; np < 4; ++np) {
                int ncol = jbase + np * 8 + lrow;
                uint32_t b0 = __float_as_uint(Bt[(k0 + lk) * 72 + ncol]);
                uint32_t b1 = __float_as_uint(Bt[(k0 + lk + 4) * 72 + ncol]);
                mma_tf32(sf[np], a0, a1, a2, a3, b0, b1);
            }
        }
        __syncthreads();
    }

    const int cc0 = 2 * lk;
    #pragma unroll
    for (int rr = 0; rr < 2; ++rr) {
        int gm = m0 + i0w + lrow + rr * 8;
        if (gm >= M) continue;
        #pragma unroll
        for (int nt = 0; nt < 4; ++nt) {
            size_t idx = (size_t)gm * HW + n0 + jbase + nt * 8 + cc0;
            *(float2*)&C[idx] = make_float2(sf[nt][rr * 2 + 0], sf[nt][rr * 2 + 1]);
        }
    }
}

// ---------------- expnorm: PAB = softmax over 80 rows (both halves) ----------
__global__ void expnorm(const float* __restrict__ AB, float* __restrict__ PAB)
{
    int gid = blockIdx.x * blockDim.x + threadIdx.x;
    if (gid >= 2 * HW) return;
    int h = (gid >= HW) ? 1 : 0;
    int i = gid - h * HW;
    const float* src = AB  + (size_t)h * NH * HW;
    float*       dst = PAB + (size_t)h * NH * HW;
    float s = 0.f;
    for (int t = 0; t < NH; ++t) {
        float e = __expf(src[t * HW + i]);
        dst[t * HW + i] = e;
        s += e;
    }
    float inv = 1.f / s;
    for (int t = 0; t < NH; ++t) dst[t * HW + i] *= inv;
}

// ---------------- W3 = [w3@efh | w3@efw]  ([256][160], m-major) --------------
__global__ void __launch_bounds__(256) w3eff_kernel(
    const float* __restrict__ w3, const float* __restrict__ efh,
    const float* __restrict__ efw, float* __restrict__ W)
{
    __shared__ float sef[8][132];
    const int tid = threadIdx.x;
    const int wid = tid >> 5, lane = tid & 31;
    const int t0 = blockIdx.x * 8;
    for (int e = tid; e < 8 * 128; e += 256) {
        int tt = e >> 7, c = e & 127;
        int t = t0 + tt;
        sef[tt][c] = (t < NH) ? efh[c * NH + t] : efw[c * NH + t - NH];
    }
    __syncthreads();
    float4 se[8];
    #pragma unroll
    for (int tt = 0; tt < 8; ++tt) se[tt] = *(float4*)&sef[tt][lane * 4];
    for (int mi = 0; mi < 32; ++mi) {
        int m = wid * 32 + mi;
        float4 a = *(const float4*)&w3[(size_t)m * NC + lane * 4];
        float acc[8];
        #pragma unroll
        for (int tt = 0; tt < 8; ++tt)
            acc[tt] = a.x * se[tt].x + a.y * se[tt].y + a.z * se[tt].z + a.w * se[tt].w;
        #pragma unroll
        for (int tt = 0; tt < 8; ++tt)
            #pragma unroll
            for (int off = 16; off; off >>= 1)
                acc[tt] += __shfl_xor_sync(0xffffffffu, acc[tt], off);
        if (lane == 0)
            #pragma unroll
            for (int tt = 0; tt < 8; ++tt)
                W[(size_t)m * 160 + t0 + tt] = acc[tt];
    }
}

// ---------------- fused final ------------------------------------------------
__global__ void __launch_bounds__(256) final_gemm(
    const float* __restrict__ w2, const float* __restrict__ o1,
    const float* __restrict__ g2, const float* __restrict__ b2,
    const float* __restrict__ m2, const float* __restrict__ v2,
    const float* __restrict__ W3, const float* __restrict__ PAB,
    const float* __restrict__ g3, const float* __restrict__ b3,
    const float* __restrict__ m3, const float* __restrict__ v3,
    const float* __restrict__ x, float* __restrict__ out)
{
    __shared__ float Wt[64 * 72];
    __shared__ float Bt[64 * 72];
    const int tid = threadIdx.x;
    const int wid = tid >> 5, lane = tid & 31;
    const int m0 = blockIdx.y * 64, n0 = blockIdx.x * 64;
    const int i0w = (wid & 3) * 16;
    const int jbase = (wid >> 2) * 32;
    const int lrow = lane >> 2, lk = lane & 3;

    float keep[4][4];
    float sf[4][4];
    #pragma unroll
    for (int nt = 0; nt < 4; ++nt)
        #pragma unroll
        for (int e = 0; e < 4; ++e) sf[nt][e] = 0.f;

    #pragma unroll
    for (int src = 0; src < 2; ++src) {
        const float* Ap = src ? W3 : w2;
        const float* Bp = src ? PAB : o1;
        const int Kp = src ? 160 : NC;
        for (int kc = 0; kc < Kp; kc += 64) {
            const int ck = (Kp - kc < 64) ? (Kp - kc) : 64;
            {
                int m = tid >> 2;
                for (int k4 = (tid & 3) << 2; k4 < ck; k4 += 16) {
                    float4 a4 = *(const float4*)&Ap[(size_t)(m0 + m) * Kp + kc + k4];
                    Wt[(k4 + 0) * 72 + m] = tf32r(a4.x);
                    Wt[(k4 + 1) * 72 + m] = tf32r(a4.y);
                    Wt[(k4 + 2) * 72 + m] = tf32r(a4.z);
                    Wt[(k4 + 3) * 72 + m] = tf32r(a4.w);
                }
            }
            {
                int n4 = (tid & 15) << 2;
                for (int kk = tid >> 4; kk < ck; kk += 16) {
                    float4 b4 = *(const float4*)&Bp[(size_t)(kc + kk) * HW + n0 + n4];
                    float* bp = &Bt[kk * 72 + n4];
                    bp[0] = tf32r(b4.x); bp[1] = tf32r(b4.y);
                    bp[2] = tf32r(b4.z); bp[3] = tf32r(b4.w);
                }
            }
            __syncthreads();
            const int nks = ck >> 3;
            for (int ks = 0; ks < nks; ++ks) {
                int k0 = ks * 8;
                uint32_t a0 = __float_as_uint(Wt[(k0 + lk) * 72 + i0w + lrow]);
                uint32_t a1 = __float_as_uint(Wt[(k0 + lk) * 72 + i0w + lrow + 8]);
                uint32_t a2 = __float_as_uint(Wt[(k0 + lk + 4) * 72 + i0w + lrow]);
                uint32_t a3 = __float_as_uint(Wt[(k0 + lk + 4) * 72 + i0w + lrow + 8]);
                #pragma unroll
                for (int np = 0; np < 4; ++np) {
                    int ncol = jbase + np * 8 + lrow;
                    uint32_t b0 = __float_as_uint(Bt[(k0 + lk) * 72 + ncol]);
                    uint32_t b1 = __float_as_uint(Bt[(k0 + lk + 4) * 72 + ncol]);
                    mma_tf32(sf[np], a0, a1, a2, a3, b0, b1);
                }
            }
            __syncthreads();
        }
        const float* gg  = src ? g3 : g2;
        const float* bbp = src ? b3 : b2;
        const float* mmp = src ? m3 : m2;
        const float* vvp = src ? v3 : v2;
        #pragma unroll
        for (int rr = 0; rr < 2; ++rr) {
            int gm = m0 + i0w + lrow + rr * 8;
            float sc = gg[gm] * rsqrtf(vvp[gm] + EPS);
            float sh = bbp[gm] - mmp[gm] * sc;
            #pragma unroll
            for (int nt = 0; nt < 4; ++nt) {
                #pragma unroll
                for (int e2 = 0; e2 < 2; ++e2) {
                    float val = sf[nt][rr * 2 + e2] * sc + sh;
                    val = val / (1.f + __expf(-val));
                    if (src == 0) { keep[nt][rr * 2 + e2] = val; sf[nt][rr * 2 + e2] = 0.f; }
                    else          { keep[nt][rr * 2 + e2] += val; }
                }
            }
        }
    }

    const int cc0 = 2 * lk;
    #pragma unroll
    for (int rr = 0; rr < 2; ++rr) {
        int gm = m0 + i0w + lrow + rr * 8;
        #pragma unroll
        for (int nt = 0; nt < 4; ++nt) {
            size_t idx = (size_t)gm * HW + n0 + jbase + nt * 8 + cc0;
            float2 x2 = *(const float2*)&x[idx];
            *(float2*)&out[idx] = make_float2(keep[nt][rr * 2 + 0] + x2.x,
                                              keep[nt][rr * 2 + 1] + x2.y);
        }
    }
}

// ---------------- branch-1 flash attention (register-resident P) -------------
#define QS_OFF   0               // bf16 [128][72]
#define KS_OFF   18432           // bf16 [128][72]
#define VS_OFF   36864           // f16  [128][72]
#define RB_OFF   55296           // f32  [64][68]  fused Rw+Rh bias
#define PMAX_OFF 72704           // f32  [2][64]
#define PSUM_OFF 73216           // f32  [2][64]
#define MR_OFF   73728           // f32  [64]
#define LR_OFF   73984           // f32  [64]
#define FL_SM_BYTES 74240

__global__ void __launch_bounds__(256, 2) flash_kernel(
    const __nv_bfloat16* __restrict__ q, const __nv_bfloat16* __restrict__ k,
    const __half* __restrict__ v, const float* __restrict__ Rh,
    const float* __restrict__ Rw, float* __restrict__ op,
    float* __restrict__ mp, float* __restrict__ lp)
{
    extern __shared__ char smc[];
    __nv_bfloat16* Qs = (__nv_bfloat16*)(smc + QS_OFF);
    float* Rb   = (float*)(smc + RB_OFF);
    float* pmax = (float*)(smc + PMAX_OFF);
    float* psum = (float*)(smc + PSUM_OFF);
    float* mrow = (float*)(smc + MR_OFF);
    float* lrow = (float*)(smc + LR_OFF);

    const int tid  = threadIdx.x;
    const int wid  = tid >> 5, lane = tid & 31;
    const int lr   = lane & 7, gq = lane >> 3;
    const int lrowq = lane >> 2, lk = lane & 3;
    const int i0   = blockIdx.x * 64;
    const int spl  = blockIdx.y;
    const int t0   = (spl * 100) / SPLIT;
    const int t1   = ((spl + 1) * 100) / SPLIT;
    const int i0w  = (wid & 3) * 16;
    const int jhalf = wid >> 2;
    const int jbase = jhalf * 32;
    const float L2E = 1.4426950408889634f;

    const uint32_t qsb = (uint32_t)__cvta_generic_to_shared(Qs);
    const uint32_t ksb = (uint32_t)__cvta_generic_to_shared(smc + KS_OFF);
    const uint32_t vsb = (uint32_t)__cvta_generic_to_shared(smc + VS_OFF);

    {   // prologue: K(t0), V(t0) via cp.async
        int j0n = t0 * 64;
        #pragma unroll
        for (int it = 0; it < 4; ++it) {
            int ch = tid + it * 256;
            int c = ch >> 3, j8 = (ch & 7) * 8;
            cpa16(ksb + (uint32_t)((c * 72 + j8) * 2), &k[(size_t)c * HW + j0n + j8]);
        }
        CPA_COMMIT();
        #pragma unroll
        for (int it = 0; it < 4; ++it) {
            int ch = tid + it * 256;
            int c = ch >> 3, j8 = (ch & 7) * 8;
            cpa16(vsb + (uint32_t)((c * 72 + j8) * 2), &v[(size_t)c * HW + j0n + j8]);
        }
        CPA_COMMIT();
    }
    {   // Q tile bf16 [c][i]
        int cr = tid >> 4, i4 = (tid & 15) << 2;
        #pragma unroll
        for (int it = 0; it < 8; ++it) {
            int c = cr + it * 16;
            *(uint2*)&Qs[c * 72 + i4] = *(const uint2*)&q[(size_t)c * HW + i0 + i4];
        }
    }
    if (tid < 64) { mrow[tid] = -1e30f; lrow[tid] = 0.f; }

    float d[16][4];   // O partial: all 128 channels, this warp's 32 j's
    #pragma unroll
    for (int nt = 0; nt < 16; ++nt)
        #pragma unroll
        for (int e = 0; e < 4; ++e) d[nt][e] = 0.f;

    const int r0 = i0w + lrowq, r1 = r0 + 8;

    for (int t = t0; t < t1; ++t) {
        const int j0 = t * 64;
        const bool more = (t + 1 < t1);

        // stage fused bias tile Rb[row][col] = Rw[(i0+row)%80] + Rh[(i0+row)/80]
        #pragma unroll
        for (int e = 0; e < 4; ++e) {
            int ee = tid + e * 256;
            int row = ee >> 4, c4 = (ee & 15) << 2;
            int gi = i0 + row;
            float4 a = *(const float4*)&Rw[(gi % 80) * HW + j0 + c4];
            float4 b = *(const float4*)&Rh[(gi / 80) * HW + j0 + c4];
            *(float4*)&Rb[row * 68 + c4] =
                make_float4(a.x + b.x, a.y + b.y, a.z + b.z, a.w + b.w);
        }
        asm volatile("cp.async.wait_group 1;");   // K(t) landed
        __syncthreads();

        // ---- QK^T (bf16) ----
        float sf[4][4];
        #pragma unroll
        for (int nt = 0; nt < 4; ++nt)
            #pragma unroll
            for (int e = 0; e < 4; ++e) sf[nt][e] = 0.f;

        #pragma unroll
        for (int ks = 0; ks < 8; ++ks) {
            int k0 = ks * 16;
            uint32_t a0, a1, a2, a3;
            ldsm4t(a0, a1, a2, a3,
                   qsb + (uint32_t)(((k0 + lr + (gq >> 1) * 8) * 72 + i0w + (gq & 1) * 8) * 2));
            #pragma unroll
            for (int np = 0; np < 2; ++np) {
                int jb = jbase + np * 16;
                uint32_t b0, b1, b2, b3;
                ldsm4t(b0, b1, b2, b3,
                       ksb + (uint32_t)(((k0 + lr + (gq & 1) * 8) * 72 + jb + (gq >> 1) * 8) * 2));
                mma_bf16(sf[np * 2],     a0, a1, a2, a3, b0, b1);
                mma_bf16(sf[np * 2 + 1], a0, a1, a2, a3, b2, b3);
            }
        }

        // ---- bias add + warp-partial row max (registers + quad shfl) ----
        #pragma unroll
        for (int nt = 0; nt < 4; ++nt) {
            int col = jbase + nt * 8 + 2 * lk;
            float2 b0 = *(float2*)&Rb[r0 * 68 + col];
            float2 b1 = *(float2*)&Rb[r1 * 68 + col];
            sf[nt][0] += b0.x; sf[nt][1] += b0.y;
            sf[nt][2] += b1.x; sf[nt][3] += b1.y;
        }
        float mx0 = fmaxf(fmaxf(sf[0][0], sf[0][1]), fmaxf(sf[1][0], sf[1][1]));
        mx0 = fmaxf(mx0, fmaxf(fmaxf(sf[2][0], sf[2][1]), fmaxf(sf[3][0], sf[3][1])));
        float mx1 = fmaxf(fmaxf(sf[0][2], sf[0][3]), fmaxf(sf[1][2], sf[1][3]));
        mx1 = fmaxf(mx1, fmaxf(fmaxf(sf[2][2], sf[2][3]), fmaxf(sf[3][2], sf[3][3])));
        mx0 = fmaxf(mx0, __shfl_xor_sync(0xffffffffu, mx0, 1));
        mx0 = fmaxf(mx0, __shfl_xor_sync(0xffffffffu, mx0, 2));
        mx1 = fmaxf(mx1, __shfl_xor_sync(0xffffffffu, mx1, 1));
        mx1 = fmaxf(mx1, __shfl_xor_sync(0xffffffffu, mx1, 2));
        if (lk == 0) {
            pmax[jhalf * 64 + r0] = mx0;
            pmax[jhalf * 64 + r1] = mx1;
        }
        __syncthreads();                          // pmax ready; Ks fully read

        if (more) {                               // K(t+1) in place
            int j0n = (t + 1) * 64;
            #pragma unroll
            for (int it = 0; it < 4; ++it) {
                int ch = tid + it * 256;
                int c = ch >> 3, j8 = (ch & 7) * 8;
                cpa16(ksb + (uint32_t)((c * 72 + j8) * 2), &k[(size_t)c * HW + j0n + j8]);
            }
            CPA_COMMIT();
        }

        // ---- exp in f16x2 -> P fragments in registers ----
        float mold0 = mrow[r0], mold1 = mrow[r1];
        float nm0 = fmaxf(mold0, fmaxf(pmax[r0], pmax[64 + r0]));
        float nm1 = fmaxf(mold1, fmaxf(pmax[r1], pmax[64 + r1]));
        float f0 = exp2f((mold0 - nm0) * L2E);
        float f1 = exp2f((mold1 - nm1) * L2E);
        uint32_t ph[4][2];
        float s0 = 0.f, s1 = 0.f;
        #pragma unroll
        for (int nt = 0; nt < 4; ++nt) {
            float u0 = (sf[nt][0] - nm0) * L2E, u1 = (sf[nt][1] - nm0) * L2E;
            float u2 = (sf[nt][2] - nm1) * L2E, u3 = (sf[nt][3] - nm1) * L2E;
            uint32_t p0, p1;
            asm("cvt.rn.f16x2.f32 %0, %1, %2;" : "=r"(p0) : "f"(u1), "f"(u0));
            asm("ex2.approx.f16x2 %0, %0;" : "+r"(p0));
            asm("cvt.rn.f16x2.f32 %0, %1, %2;" : "=r"(p1) : "f"(u3), "f"(u2));
            asm("ex2.approx.f16x2 %0, %0;" : "+r"(p1));
            ph[nt][0] = p0; ph[nt][1] = p1;
            float2 e0 = __half22float2(*reinterpret_cast<__half2*>(&p0));
            float2 e1 = __half22float2(*reinterpret_cast<__half2*>(&p1));
            s0 += e0.x + e0.y;
            s1 += e1.x + e1.y;
        }
        s0 += __shfl_xor_sync(0xffffffffu, s0, 1);
        s0 += __shfl_xor_sync(0xffffffffu, s0, 2);
        s1 += __shfl_xor_sync(0xffffffffu, s1, 1);
        s1 += __shfl_xor_sync(0xffffffffu, s1, 2);
        if (lk == 0) {
            psum[jhalf * 64 + r0] = s0;
            psum[jhalf * 64 + r1] = s1;
        }
        // rescale O partials
        #pragma unroll
        for (int nt = 0; nt < 16; ++nt) {
            d[nt][0] *= f0; d[nt][1] *= f0;
            d[nt][2] *= f1; d[nt][3] *= f1;
        }
        if (more) asm volatile("cp.async.wait_group 1;");  // V(t) landed
        else      asm volatile("cp.async.wait_group 0;");
        __syncthreads();                          // psum + Vs ready

        if (tid < 64) {                           // update running stats
            int r = tid;
            float mo = mrow[r];
            float nm = fmaxf(mo, fmaxf(pmax[r], pmax[64 + r]));
            float f = exp2f((mo - nm) * L2E);
            lrow[r] = lrow[r] * f + psum[r] + psum[64 + r];
            mrow[r] = nm;
        }

        // ---- P @ V^T : A = register P fragments, B = V (fp16) ----
        #pragma unroll
        for (int ks = 0; ks < 2; ++ks) {
            int j0s = jbase + ks * 16;
            uint32_t a0 = ph[2 * ks][0], a1 = ph[2 * ks][1];
            uint32_t a2 = ph[2 * ks + 1][0], a3 = ph[2 * ks + 1][1];
            #pragma unroll
            for (int np = 0; np < 8; ++np) {
                int cb = np * 16;
                uint32_t b0, b1, b2, b3;
                ldsm4(b0, b1, b2, b3,
                      vsb + (uint32_t)(((cb + lr + (gq >> 1) * 8) * 72 + j0s + (gq & 1) * 8) * 2));
                mma_f16(d[np * 2],     a0, a1, a2, a3, b0, b1);
                mma_f16(d[np * 2 + 1], a0, a1, a2, a3, b2, b3);
            }
        }

        if (more) {
            __syncthreads();                      // Vs fully read
            int j0n = (t + 1) * 64;
            #pragma unroll
            for (int it = 0; it < 4; ++it) {
                int ch = tid + it * 256;
                int c = ch >> 3, j8 = (ch & 7) * 8;
                cpa16(vsb + (uint32_t)((c * 72 + j8) * 2), &v[(size_t)c * HW + j0n + j8]);
            }
            CPA_COMMIT();
        }
    }

    // ---- epilogue: combine j-half warp pairs, emit partials ----
    __syncthreads();
    float* fbuf = (float*)smc;   // [64][132] reuse of Q/K smem
    if (jhalf == 1) {
        #pragma unroll
        for (int nt = 0; nt < 16; ++nt) {
            int c = nt * 8 + 2 * lk;
            *(float2*)&fbuf[r0 * 132 + c] = make_float2(d[nt][0], d[nt][1]);
            *(float2*)&fbuf[r1 * 132 + c] = make_float2(d[nt][2], d[nt][3]);
        }
    }
    __syncthreads();
    if (jhalf == 0) {
        #pragma unroll
        for (int nt = 0; nt < 16; ++nt) {
            int c = nt * 8 + 2 * lk;
            float2 o0 = *(float2*)&fbuf[r0 * 132 + c];
            float2 o1 = *(float2*)&fbuf[r1 * 132 + c];
            op[(size_t)(spl * NC + c)     * HW + i0 + r0] = d[nt][0] + o0.x;
            op[(size_t)(spl * NC + c + 1) * HW + i0 + r0] = d[nt][1] + o0.y;
            op[(size_t)(spl * NC + c)     * HW + i0 + r1] = d[nt][2] + o1.x;
            op[(size_t)(spl * NC + c + 1) * HW + i0 + r1] = d[nt][3] + o1.y;
        }
    }
    if (tid < 64) {
        mp[spl * HW + i0 + tid] = mrow[tid];
        lp[spl * HW + i0 + tid] = lrow[tid];
    }
}

// ---------------- split-j combine (channel-parallel) -------------------------
__global__ void combine_kernel(const float* __restrict__ op,
                               const float* __restrict__ mp,
                               const float* __restrict__ lp,
                               float* __restrict__ out1)
{
    int i = blockIdx.x * blockDim.x + threadIdx.x;
    if (i >= HW) return;
    int c0 = blockIdx.y * 8;
    float m[SPLIT], w[SPLIT];
    float M = -1e30f;
    #pragma unroll
    for (int s = 0; s < SPLIT; ++s) { m[s] = mp[s * HW + i]; M = fmaxf(M, m[s]); }
    float L = 0.f;
    #pragma unroll
    for (int s = 0; s < SPLIT; ++s) { w[s] = __expf(m[s] - M); L += lp[s * HW + i] * w[s]; }
    float inv = 1.f / L;
    for (int c = c0; c < c0 + 8; ++c) {
        float acc = 0.f;
        #pragma unroll
        for (int s = 0; s < SPLIT; ++s)
            acc += op[((size_t)(s * NC + c)) * HW + i] * w[s];
        out1[(size_t)c * HW + i] = acc * inv;
    }
}

// -------------------------------- launch -------------------------------------
extern "C" void kernel_launch(void* const* d_in, const int* in_sizes, int n_in,
                              void* d_out, int out_size)
{
    (void)in_sizes; (void)n_in; (void)out_size;
    const float* x    = (const float*)d_in[0];
    const float* w1   = (const float*)d_in[1];
    const float* g1   = (const float*)d_in[2];
    const float* b1   = (const float*)d_in[3];
    const float* m1   = (const float*)d_in[4];
    const float* v1   = (const float*)d_in[5];
    const float* w2   = (const float*)d_in[6];
    const float* g2   = (const float*)d_in[7];
    const float* b2   = (const float*)d_in[8];
    const float* m2   = (const float*)d_in[9];
    const float* v2   = (const float*)d_in[10];
    const float* w3   = (const float*)d_in[11];
    const float* g3   = (const float*)d_in[12];
    const float* b3   = (const float*)d_in[13];
    const float* m3   = (const float*)d_in[14];
    const float* v3   = (const float*)d_in[15];
    const float* wq   = (const float*)d_in[16];
    const float* bq   = (const float*)d_in[17];
    const float* wk   = (const float*)d_in[18];
    const float* bk   = (const float*)d_in[19];
    const float* wv   = (const float*)d_in[20];
    const float* bv   = (const float*)d_in[21];
    const float* wp   = (const float*)d_in[22];
    const float* bp   = (const float*)d_in[23];
    const float* relh = (const float*)d_in[24];
    const float* relw = (const float*)d_in[25];
    const float* efh  = (const float*)d_in[26];
    const float* efw  = (const float*)d_in[27];
    float* out = (float*)d_out;

    float *px1, *pq, *pp, *pRW, *pAB, *pPAB, *pW3, *po1, *pop, *pmp, *plp;
    __nv_bfloat16 *pqb, *pkb;
    __half *pvh;
    cudaGetSymbolAddress((void**)&px1, d_x1);
    cudaGetSymbolAddress((void**)&pq,  d_q);
    cudaGetSymbolAddress((void**)&pp,  d_p);
    cudaGetSymbolAddress((void**)&pqb, d_qb);
    cudaGetSymbolAddress((void**)&pkb, d_kb);
    cudaGetSymbolAddress((void**)&pvh, d_vh);
    cudaGetSymbolAddress((void**)&pRW, d_RW);
    cudaGetSymbolAddress((void**)&pAB, d_AB);
    cudaGetSymbolAddress((void**)&pPAB, d_PAB);
    cudaGetSymbolAddress((void**)&pW3, d_W3);
    cudaGetSymbolAddress((void**)&po1, d_o1);
    cudaGetSymbolAddress((void**)&pop, d_op);
    cudaGetSymbolAddress((void**)&pmp, d_mp);
    cudaGetSymbolAddress((void**)&plp, d_lp);

    cudaFuncSetAttribute(flash_kernel,
        cudaFuncAttributeMaxDynamicSharedMemorySize, FL_SM_BYTES);

    dim3 g100_2(100, 2), g100_3(100, 3), g100_4(100, 4);
    dim3 gproj(100, 2, 4), gfl(100, SPLIT), gcmb(25, 16);

    // [0] x1 = SiLU(BN(w1 @ x))
    tgemm<2><<<g100_2, 256>>>(w1, x, px1, NC, ND, g1, b1, m1, v1);
    // [1] fused q/k/v/p projections (fp32 q,p; bf16 q,k; fp16 v)
    proj4<<<gproj, 256>>>(px1, wq, bq, wk, bk, wv, bv, wp, bp,
        pq, pqb, pkb, pvh, pp);
    // [2] [Rh; Rw] = [rel_h; rel_w]^T q
    krgemm<<<g100_3, 256>>>(relh, relw, pq, pRW);
    // [3] flash attention (register-P, split-j = 8)
    flash_kernel<<<gfl, 256, FL_SM_BYTES>>>(pqb, pkb, pvh,
        pRW, pRW + NH * HW, pop, pmp, plp);
    // [4] [ABh; ABw] = [ef_h; ef_w]^T p
    krgemm<<<g100_3, 256>>>(efh, efw, pp, pAB);
    // [5] PAB = per-column softmax of both halves
    expnorm<<<50, 256>>>(pAB, pPAB);
    // [6] W3 = [w3@efh | w3@efw]
    w3eff_kernel<<<20, 256>>>(w3, efh, efw, pW3);
    // [7] combine split partials -> out1
    combine_kernel<<<gcmb, 256>>>(pop, pmp, plp, po1);
    // [8] out = x + SiLU(BN2(w2@o1)) + SiLU(BN3(W3@PAB))
    final_gemm<<<g100_4, 256>>>(w2, po1, g2, b2, m2, v2,
        pW3, pPAB, g3, b3, m3, v3, x, out);
}

// round 9
// speedup vs baseline: 5.6660x; 1.0444x over previous
#include <cuda_runtime.h>
#include <cuda_bf16.h>
#include <cuda_fp16.h>
#include <cstdint>

#define EPS 1e-5f
#define HW 6400
#define NC 128
#define ND 256
#define NH 80
#define SPLIT 8

// ---------------- tensor-core helpers ----------------------------------------
__device__ __forceinline__ void ldsm4(uint32_t& r0, uint32_t& r1,
                                      uint32_t& r2, uint32_t& r3, uint32_t a) {
    asm volatile("ldmatrix.sync.aligned.m8n8.x4.shared.b16 {%0,%1,%2,%3},[%4];"
        : "=r"(r0), "=r"(r1), "=r"(r2), "=r"(r3) : "r"(a));
}
__device__ __forceinline__ void ldsm4t(uint32_t& r0, uint32_t& r1,
                                       uint32_t& r2, uint32_t& r3, uint32_t a) {
    asm volatile("ldmatrix.sync.aligned.m8n8.x4.trans.shared.b16 {%0,%1,%2,%3},[%4];"
        : "=r"(r0), "=r"(r1), "=r"(r2), "=r"(r3) : "r"(a));
}
__device__ __forceinline__ void mma_bf16(float* d, uint32_t a0, uint32_t a1,
                                         uint32_t a2, uint32_t a3,
                                         uint32_t b0, uint32_t b1) {
    asm volatile("mma.sync.aligned.m16n8k16.row.col.f32.bf16.bf16.f32 "
        "{%0,%1,%2,%3},{%4,%5,%6,%7},{%8,%9},{%0,%1,%2,%3};"
        : "+f"(d[0]), "+f"(d[1]), "+f"(d[2]), "+f"(d[3])
        : "r"(a0), "r"(a1), "r"(a2), "r"(a3), "r"(b0), "r"(b1));
}
__device__ __forceinline__ void mma_f16(float* d, uint32_t a0, uint32_t a1,
                                        uint32_t a2, uint32_t a3,
                                        uint32_t b0, uint32_t b1) {
    asm volatile("mma.sync.aligned.m16n8k16.row.col.f32.f16.f16.f32 "
        "{%0,%1,%2,%3},{%4,%5,%6,%7},{%8,%9},{%0,%1,%2,%3};"
        : "+f"(d[0]), "+f"(d[1]), "+f"(d[2]), "+f"(d[3])
        : "r"(a0), "r"(a1), "r"(a2), "r"(a3), "r"(b0), "r"(b1));
}
__device__ __forceinline__ void mma_tf32(float* d, uint32_t a0, uint32_t a1,
                                         uint32_t a2, uint32_t a3,
                                         uint32_t b0, uint32_t b1) {
    asm volatile("mma.sync.aligned.m16n8k8.row.col.f32.tf32.tf32.f32 "
        "{%0,%1,%2,%3},{%4,%5,%6,%7},{%8,%9},{%0,%1,%2,%3};"
        : "+f"(d[0]), "+f"(d[1]), "+f"(d[2]), "+f"(d[3])
        : "r"(a0), "r"(a1), "r"(a2), "r"(a3), "r"(b0), "r"(b1));
}
__device__ __forceinline__ float tf32r(float x) {
    uint32_t r;
    asm("cvt.rna.tf32.f32 %0, %1;" : "=r"(r) : "f"(x));
    return __uint_as_float(r);
}
__device__ __forceinline__ void cpa16(uint32_t s, const void* g) {
    asm volatile("cp.async.cg.shared.global [%0], [%1], 16;" :: "r"(s), "l"(g));
}
#define CPA_COMMIT() asm volatile("cp.async.commit_group;")

// ---------------- scratch (static device globals; no allocation) -------------
__device__ float d_x1 [NC*HW];
__device__ float d_q  [NC*HW];
__device__ float d_p  [NC*HW];
__device__ __nv_bfloat16 d_qb[NC*HW];
__device__ __nv_bfloat16 d_kb[NC*HW];
__device__ __half d_vh[NC*HW];
__device__ float d_RW  [2*NH*HW];   // [Rh(80); Rw(80)]
__device__ float d_AB  [2*NH*HW];   // [ABh(80); ABw(80)]
__device__ float d_PAB [2*NH*HW];   // normalized [PA(80); PB(80)]
__device__ float d_W3  [ND*2*NH];   // [w3@efh | w3@efw]  m-major [256][160]
__device__ float d_o1  [NC*HW];
__device__ float d_op  [SPLIT*NC*HW];
__device__ float d_mp  [SPLIT*HW];
__device__ float d_lp  [SPLIT*HW];

// ---------------- tf32 GEMM (x1 conv) with register-prefetch pipeline --------
template<int EPI>
__global__ void __launch_bounds__(256) tgemm(
    const float* __restrict__ A, const float* __restrict__ B,
    float* __restrict__ C, int M, int K,
    const float* __restrict__ g, const float* __restrict__ bb,
    const float* __restrict__ mm, const float* __restrict__ vv)
{
    __shared__ float Wt[64 * 72];
    __shared__ float Bt[64 * 72];
    const int tid = threadIdx.x;
    const int wid = tid >> 5, lane = tid & 31;
    const int m0 = blockIdx.y * 64, n0 = blockIdx.x * 64;
    const int i0w = (wid & 3) * 16;
    const int jbase = (wid >> 2) * 32;
    const int lrow = lane >> 2, lk = lane & 3;
    const int mA = tid >> 2, kqA = (tid & 3) << 2;
    const int kkB = tid >> 4, n4B = (tid & 15) << 2;

    float sf[4][4];
    #pragma unroll
    for (int nt = 0; nt < 4; ++nt)
        #pragma unroll
        for (int e = 0; e < 4; ++e) sf[nt][e] = 0.f;

    float4 ar[4], br[4];
    #pragma unroll
    for (int i = 0; i < 4; ++i) {
        ar[i] = *(const float4*)&A[(size_t)(m0 + mA) * K + kqA + 16 * i];
        br[i] = *(const float4*)&B[(size_t)(kkB + 16 * i) * HW + n0 + n4B];
    }

    for (int kc = 0; kc < K; kc += 64) {
        #pragma unroll
        for (int i = 0; i < 4; ++i) {
            int k4 = kqA + 16 * i;
            Wt[(k4 + 0) * 72 + mA] = tf32r(ar[i].x);
            Wt[(k4 + 1) * 72 + mA] = tf32r(ar[i].y);
            Wt[(k4 + 2) * 72 + mA] = tf32r(ar[i].z);
            Wt[(k4 + 3) * 72 + mA] = tf32r(ar[i].w);
            int kk = kkB + 16 * i;
            float* bp = &Bt[kk * 72 + n4B];
            bp[0] = tf32r(br[i].x); bp[1] = tf32r(br[i].y);
            bp[2] = tf32r(br[i].z); bp[3] = tf32r(br[i].w);
        }
        __syncthreads();
        if (kc + 64 < K) {
            #pragma unroll
            for (int i = 0; i < 4; ++i) {
                ar[i] = *(const float4*)&A[(size_t)(m0 + mA) * K + kc + 64 + kqA + 16 * i];
                br[i] = *(const float4*)&B[(size_t)(kc + 64 + kkB + 16 * i) * HW + n0 + n4B];
            }
        }
        #pragma unroll
        for (int ks = 0; ks < 8; ++ks) {
            int k0 = ks * 8;
            uint32_t a0 = __float_as_uint(Wt[(k0 + lk) * 72 + i0w + lrow]);
            uint32_t a1 = __float_as_uint(Wt[(k0 + lk) * 72 + i0w + lrow + 8]);
            uint32_t a2 = __float_as_uint(Wt[(k0 + lk + 4) * 72 + i0w + lrow]);
            uint32_t a3 = __float_as_uint(Wt[(k0 + lk + 4) * 72 + i0w + lrow + 8]);
            #pragma unroll
            for (int np = 0; np < 4; ++np) {
                int ncol = jbase + np * 8 + lrow;
                uint32_t b0 = __float_as_uint(Bt[(k0 + lk) * 72 + ncol]);
                uint32_t b1 = __float_as_uint(Bt[(k0 + lk + 4) * 72 + ncol]);
                mma_tf32(sf[np], a0, a1, a2, a3, b0, b1);
            }
        }
        __syncthreads();
    }

    const int cc0 = 2 * lk;
    #pragma unroll
    for (int rr = 0; rr < 2; ++rr) {
        int gm = m0 + i0w + lrow + rr * 8;
        float sc = 0.f, sh = 0.f;
        if (EPI == 2) {
            sc = g[gm] * rsqrtf(vv[gm] + EPS);
            sh = bb[gm] - mm[gm] * sc;
        }
        #pragma unroll
        for (int nt = 0; nt < 4; ++nt) {
            float e0 = sf[nt][rr * 2 + 0];
            float e1 = sf[nt][rr * 2 + 1];
            if (EPI == 2) {
                e0 = e0 * sc + sh; e1 = e1 * sc + sh;
                e0 = e0 / (1.f + __expf(-e0));
                e1 = e1 / (1.f + __expf(-e1));
            }
            size_t idx = (size_t)gm * HW + n0 + jbase + nt * 8 + cc0;
            *(float2*)&C[idx] = make_float2(e0, e1);
        }
    }
}

// ---------------- fused q/k/v/p projection (z selects weight; prefetch) ------
__global__ void __launch_bounds__(256) proj4(
    const float* __restrict__ x1,
    const float* __restrict__ wq, const float* __restrict__ bq,
    const float* __restrict__ wk, const float* __restrict__ bk,
    const float* __restrict__ wv, const float* __restrict__ bv,
    const float* __restrict__ wp, const float* __restrict__ bp,
    float* __restrict__ qf, __nv_bfloat16* __restrict__ qb,
    __nv_bfloat16* __restrict__ kb, __half* __restrict__ vh,
    float* __restrict__ pf)
{
    __shared__ float Wt[64 * 72];
    __shared__ float Bt[64 * 72];
    const int z = blockIdx.z;
    const float* A    = (z == 0) ? wq : (z == 1) ? wk : (z == 2) ? wv : wp;
    const float* bias = (z == 0) ? bq : (z == 1) ? bk : (z == 2) ? bv : bp;
    const int tid = threadIdx.x;
    const int wid = tid >> 5, lane = tid & 31;
    const int m0 = blockIdx.y * 64, n0 = blockIdx.x * 64;
    const int i0w = (wid & 3) * 16;
    const int jbase = (wid >> 2) * 32;
    const int lrow = lane >> 2, lk = lane & 3;
    const int mA = tid >> 2, kqA = (tid & 3) << 2;
    const int kkB = tid >> 4, n4B = (tid & 15) << 2;

    float sf[4][4];
    #pragma unroll
    for (int nt = 0; nt < 4; ++nt)
        #pragma unroll
        for (int e = 0; e < 4; ++e) sf[nt][e] = 0.f;

    float4 ar[4], br[4];
    #pragma unroll
    for (int i = 0; i < 4; ++i) {
        ar[i] = *(const float4*)&A[(size_t)(m0 + mA) * NC + kqA + 16 * i];
        br[i] = *(const float4*)&x1[(size_t)(kkB + 16 * i) * HW + n0 + n4B];
    }

    for (int kc = 0; kc < NC; kc += 64) {
        #pragma unroll
        for (int i = 0; i < 4; ++i) {
            int k4 = kqA + 16 * i;
            Wt[(k4 + 0) * 72 + mA] = tf32r(ar[i].x);
            Wt[(k4 + 1) * 72 + mA] = tf32r(ar[i].y);
            Wt[(k4 + 2) * 72 + mA] = tf32r(ar[i].z);
            Wt[(k4 + 3) * 72 + mA] = tf32r(ar[i].w);
            int kk = kkB + 16 * i;
            float* bp2 = &Bt[kk * 72 + n4B];
            bp2[0] = tf32r(br[i].x); bp2[1] = tf32r(br[i].y);
            bp2[2] = tf32r(br[i].z); bp2[3] = tf32r(br[i].w);
        }
        __syncthreads();
        if (kc + 64 < NC) {
            #pragma unroll
            for (int i = 0; i < 4; ++i) {
                ar[i] = *(const float4*)&A[(size_t)(m0 + mA) * NC + kc + 64 + kqA + 16 * i];
                br[i] = *(const float4*)&x1[(size_t)(kc + 64 + kkB + 16 * i) * HW + n0 + n4B];
            }
        }
        #pragma unroll
        for (int ks = 0; ks < 8; ++ks) {
            int k0 = ks * 8;
            uint32_t a0 = __float_as_uint(Wt[(k0 + lk) * 72 + i0w + lrow]);
            uint32_t a1 = __float_as_uint(Wt[(k0 + lk) * 72 + i0w + lrow + 8]);
            uint32_t a2 = __float_as_uint(Wt[(k0 + lk + 4) * 72 + i0w + lrow]);
            uint32_t a3 = __float_as_uint(Wt[(k0 + lk + 4) * 72 + i0w + lrow + 8]);
            #pragma unroll
            for (int np = 0; np < 4; ++np) {
                int ncol = jbase + np * 8 + lrow;
                uint32_t b0 = __float_as_uint(Bt[(k0 + lk) * 72 + ncol]);
                uint32_t b1 = __float_as_uint(Bt[(k0 + lk + 4) * 72 + ncol]);
                mma_tf32(sf[np], a0, a1, a2, a3, b0, b1);
            }
        }
        __syncthreads();
    }

    const int cc0 = 2 * lk;
    #pragma unroll
    for (int rr = 0; rr < 2; ++rr) {
        int gm = m0 + i0w + lrow + rr * 8;
        float bsv = bias[gm];
        #pragma unroll
        for (int nt = 0; nt < 4; ++nt) {
            float e0 = sf[nt][rr * 2 + 0] + bsv;
            float e1 = sf[nt][rr * 2 + 1] + bsv;
            size_t idx = (size_t)gm * HW + n0 + jbase + nt * 8 + cc0;
            if (z == 0) {
                *(float2*)&qf[idx] = make_float2(e0, e1);
                *(__nv_bfloat162*)&qb[idx] = __floats2bfloat162_rn(e0, e1);
            } else if (z == 1) {
                *(__nv_bfloat162*)&kb[idx] = __floats2bfloat162_rn(e0, e1);
            } else if (z == 2) {
                *(__half2*)&vh[idx] = __floats2half2_rn(e0, e1);
            } else {
                *(float2*)&pf[idx] = make_float2(e0, e1);
            }
        }
    }
}

// ---------------- stacked k-major GEMM (z=0: RW, z=1: AB; prefetch) ----------
__global__ void __launch_bounds__(256) krgemm(
    const float* __restrict__ lo0, const float* __restrict__ hi0,
    const float* __restrict__ B0, float* __restrict__ C0,
    const float* __restrict__ lo1, const float* __restrict__ hi1,
    const float* __restrict__ B1, float* __restrict__ C1)
{
    __shared__ float Wt[64 * 72];
    __shared__ float Bt[64 * 72];
    const int z = blockIdx.z;
    const float* a_lo = z ? lo1 : lo0;
    const float* a_hi = z ? hi1 : hi0;
    const float* B    = z ? B1  : B0;
    float*       C    = z ? C1  : C0;
    const int tid = threadIdx.x;
    const int wid = tid >> 5, lane = tid & 31;
    const int m0 = blockIdx.y * 64, n0 = blockIdx.x * 64;
    const int i0w = (wid & 3) * 16;
    const int jbase = (wid >> 2) * 32;
    const int lrow = lane >> 2, lk = lane & 3;
    const int M = 2 * NH;
    const int kkB = tid >> 4, n4B = (tid & 15) << 2;
    const int m4A = (tid & 15) << 2;
    const int gmA = m0 + m4A;

    float sf[4][4];
    #pragma unroll
    for (int nt = 0; nt < 4; ++nt)
        #pragma unroll
        for (int e = 0; e < 4; ++e) sf[nt][e] = 0.f;

    float4 ar[4], br[4];
    #pragma unroll
    for (int i = 0; i < 4; ++i) {
        int kk = kkB + 16 * i;
        float4 a4 = make_float4(0.f, 0.f, 0.f, 0.f);
        if (gmA < NH)          a4 = *(const float4*)&a_lo[(size_t)kk * NH + gmA];
        else if (gmA < 2 * NH) a4 = *(const float4*)&a_hi[(size_t)kk * NH + gmA - NH];
        ar[i] = a4;
        br[i] = *(const float4*)&B[(size_t)kk * HW + n0 + n4B];
    }

    for (int kc = 0; kc < NC; kc += 64) {
        #pragma unroll
        for (int i = 0; i < 4; ++i) {
            int kk = kkB + 16 * i;
            float* wp = &Wt[kk * 72 + m4A];
            wp[0] = tf32r(ar[i].x); wp[1] = tf32r(ar[i].y);
            wp[2] = tf32r(ar[i].z); wp[3] = tf32r(ar[i].w);
            float* bp = &Bt[kk * 72 + n4B];
            bp[0] = tf32r(br[i].x); bp[1] = tf32r(br[i].y);
            bp[2] = tf32r(br[i].z); bp[3] = tf32r(br[i].w);
        }
        __syncthreads();
        if (kc + 64 < NC) {
            #pragma unroll
            for (int i = 0; i < 4; ++i) {
                int kk = kc + 64 + kkB + 16 * i;
                float4 a4 = make_float4(0.f, 0.f, 0.f, 0.f);
                if (gmA < NH)          a4 = *(const float4*)&a_lo[(size_t)kk * NH + gmA];
                else if (gmA < 2 * NH) a4 = *(const float4*)&a_hi[(size_t)kk * NH + gmA - NH];
                ar[i] = a4;
                br[i] = *(const float4*)&B[(size_t)kk * HW + n0 + n4B];
            }
        }
        #pragma unroll
        for (int ks = 0; ks < 8; ++ks) {
            int k0 = ks * 8;
            uint32_t a0 = __float_as_uint(Wt[(k0 + lk) * 72 + i0w + lrow]);
            uint32_t a1 = __float_as_uint(Wt[(k0 + lk) * 72 + i0w + lrow + 8]);
            uint32_t a2 = __float_as_uint(Wt[(k0 + lk + 4) * 72 + i0w + lrow]);
            uint32_t a3 = __float_as_uint(Wt[(k0 + lk + 4) * 72 + i0w + lrow + 8]);
            #pragma unroll
            for (int np = 0; np < 4; ++np) {
                int ncol = jbase + np * 8 + lrow;
                uint32_t b0 = __float_as_uint(Bt[(k0 + lk) * 72 + ncol]);
                uint32_t b1 = __float_as_uint(Bt[(k0 + lk + 4) * 72 + ncol]);
                mma_tf32(sf[np], a0, a1, a2, a3, b0, b1);
            }
        }
        __syncthreads();
    }

    const int cc0 = 2 * lk;
    #pragma unroll
    for (int rr = 0; rr < 2; ++rr) {
        int gm = m0 + i0w + lrow + rr * 8;
        if (gm >= M) continue;
        #pragma unroll
        for (int nt = 0; nt < 4; ++nt) {
            size_t idx = (size_t)gm * HW + n0 + jbase + nt * 8 + cc0;
            *(float2*)&C[idx] = make_float2(sf[nt][rr * 2 + 0], sf[nt][rr * 2 + 1]);
        }
    }
}

// ---------------- expnorm: PAB = softmax over 80 rows (both halves) ----------
__global__ void expnorm(const float* __restrict__ AB, float* __restrict__ PAB)
{
    int gid = blockIdx.x * blockDim.x + threadIdx.x;
    if (gid >= 2 * HW) return;
    int h = (gid >= HW) ? 1 : 0;
    int i = gid - h * HW;
    const float* src = AB  + (size_t)h * NH * HW;
    float*       dst = PAB + (size_t)h * NH * HW;
    float s = 0.f;
    for (int t = 0; t < NH; ++t) {
        float e = __expf(src[t * HW + i]);
        dst[t * HW + i] = e;
        s += e;
    }
    float inv = 1.f / s;
    for (int t = 0; t < NH; ++t) dst[t * HW + i] *= inv;
}

// ---------------- W3 = [w3@efh | w3@efw]  ([256][160], m-major) --------------
__global__ void __launch_bounds__(256) w3eff_kernel(
    const float* __restrict__ w3, const float* __restrict__ efh,
    const float* __restrict__ efw, float* __restrict__ W)
{
    __shared__ float sef[8][132];
    const int tid = threadIdx.x;
    const int wid = tid >> 5, lane = tid & 31;
    const int t0 = blockIdx.x * 8;
    for (int e = tid; e < 8 * 128; e += 256) {
        int tt = e >> 7, c = e & 127;
        int t = t0 + tt;
        sef[tt][c] = (t < NH) ? efh[c * NH + t] : efw[c * NH + t - NH];
    }
    __syncthreads();
    float4 se[8];
    #pragma unroll
    for (int tt = 0; tt < 8; ++tt) se[tt] = *(float4*)&sef[tt][lane * 4];
    for (int mi = 0; mi < 32; ++mi) {
        int m = wid * 32 + mi;
        float4 a = *(const float4*)&w3[(size_t)m * NC + lane * 4];
        float acc[8];
        #pragma unroll
        for (int tt = 0; tt < 8; ++tt)
            acc[tt] = a.x * se[tt].x + a.y * se[tt].y + a.z * se[tt].z + a.w * se[tt].w;
        #pragma unroll
        for (int tt = 0; tt < 8; ++tt)
            #pragma unroll
            for (int off = 16; off; off >>= 1)
                acc[tt] += __shfl_xor_sync(0xffffffffu, acc[tt], off);
        if (lane == 0)
            #pragma unroll
            for (int tt = 0; tt < 8; ++tt)
                W[(size_t)m * 160 + t0 + tt] = acc[tt];
    }
}

// ---------------- fused final (prefetched, dual source) ----------------------
__global__ void __launch_bounds__(256) final_gemm(
    const float* __restrict__ w2, const float* __restrict__ o1,
    const float* __restrict__ g2, const float* __restrict__ b2,
    const float* __restrict__ m2, const float* __restrict__ v2,
    const float* __restrict__ W3, const float* __restrict__ PAB,
    const float* __restrict__ g3, const float* __restrict__ b3,
    const float* __restrict__ m3, const float* __restrict__ v3,
    const float* __restrict__ x, float* __restrict__ out)
{
    __shared__ float Wt[64 * 72];
    __shared__ float Bt[64 * 72];
    const int tid = threadIdx.x;
    const int wid = tid >> 5, lane = tid & 31;
    const int m0 = blockIdx.y * 64, n0 = blockIdx.x * 64;
    const int i0w = (wid & 3) * 16;
    const int jbase = (wid >> 2) * 32;
    const int lrow = lane >> 2, lk = lane & 3;
    const int mA = tid >> 2, kqA = (tid & 3) << 2;
    const int kkB = tid >> 4, n4B = (tid & 15) << 2;

    float keep[4][4];
    float sf[4][4];
    #pragma unroll
    for (int nt = 0; nt < 4; ++nt)
        #pragma unroll
        for (int e = 0; e < 4; ++e) sf[nt][e] = 0.f;

    float4 ar[4], br[4];
    #pragma unroll
    for (int i = 0; i < 4; ++i) {
        ar[i] = *(const float4*)&w2[(size_t)(m0 + mA) * NC + kqA + 16 * i];
        br[i] = *(const float4*)&o1[(size_t)(kkB + 16 * i) * HW + n0 + n4B];
    }

    #pragma unroll
    for (int src = 0; src < 2; ++src) {
        const int Kp = src ? 160 : NC;
        for (int kc = 0; kc < Kp; kc += 64) {
            const int ck = (Kp - kc < 64) ? (Kp - kc) : 64;
            #pragma unroll
            for (int i = 0; i < 4; ++i) {
                int k4 = kqA + 16 * i;
                if (k4 < ck) {
                    Wt[(k4 + 0) * 72 + mA] = tf32r(ar[i].x);
                    Wt[(k4 + 1) * 72 + mA] = tf32r(ar[i].y);
                    Wt[(k4 + 2) * 72 + mA] = tf32r(ar[i].z);
                    Wt[(k4 + 3) * 72 + mA] = tf32r(ar[i].w);
                }
                int kk = kkB + 16 * i;
                if (kk < ck) {
                    float* bp = &Bt[kk * 72 + n4B];
                    bp[0] = tf32r(br[i].x); bp[1] = tf32r(br[i].y);
                    bp[2] = tf32r(br[i].z); bp[3] = tf32r(br[i].w);
                }
            }
            __syncthreads();
            {   // prefetch next chunk (possibly next source)
                int srcN = src, kcN = kc + 64;
                if (kcN >= Kp) { srcN = src + 1; kcN = 0; }
                if (srcN < 2) {
                    const float* ApN = srcN ? W3 : w2;
                    const float* BpN = srcN ? PAB : o1;
                    int KpN = srcN ? 160 : NC;
                    int ckN = (KpN - kcN < 64) ? (KpN - kcN) : 64;
                    #pragma unroll
                    for (int i = 0; i < 4; ++i) {
                        int k4 = kqA + 16 * i;
                        if (k4 < ckN)
                            ar[i] = *(const float4*)&ApN[(size_t)(m0 + mA) * KpN + kcN + k4];
                        int kk = kkB + 16 * i;
                        if (kk < ckN)
                            br[i] = *(const float4*)&BpN[(size_t)(kcN + kk) * HW + n0 + n4B];
                    }
                }
            }
            const int nks = ck >> 3;
            for (int ks = 0; ks < nks; ++ks) {
                int k0 = ks * 8;
                uint32_t a0 = __float_as_uint(Wt[(k0 + lk) * 72 + i0w + lrow]);
                uint32_t a1 = __float_as_uint(Wt[(k0 + lk) * 72 + i0w + lrow + 8]);
                uint32_t a2 = __float_as_uint(Wt[(k0 + lk + 4) * 72 + i0w + lrow]);
                uint32_t a3 = __float_as_uint(Wt[(k0 + lk + 4) * 72 + i0w + lrow + 8]);
                #pragma unroll
                for (int np = 0; np < 4; ++np) {
                    int ncol = jbase + np * 8 + lrow;
                    uint32_t b0 = __float_as_uint(Bt[(k0 + lk) * 72 + ncol]);
                    uint32_t b1 = __float_as_uint(Bt[(k0 + lk + 4) * 72 + ncol]);
                    mma_tf32(sf[np], a0, a1, a2, a3, b0, b1);
                }
            }
            __syncthreads();
        }
        const float* gg  = src ? g3 : g2;
        const float* bbp = src ? b3 : b2;
        const float* mmp = src ? m3 : m2;
        const float* vvp = src ? v3 : v2;
        #pragma unroll
        for (int rr = 0; rr < 2; ++rr) {
            int gm = m0 + i0w + lrow + rr * 8;
            float sc = gg[gm] * rsqrtf(vvp[gm] + EPS);
            float sh = bbp[gm] - mmp[gm] * sc;
            #pragma unroll
            for (int nt = 0; nt < 4; ++nt) {
                #pragma unroll
                for (int e2 = 0; e2 < 2; ++e2) {
                    float val = sf[nt][rr * 2 + e2] * sc + sh;
                    val = val / (1.f + __expf(-val));
                    if (src == 0) { keep[nt][rr * 2 + e2] = val; sf[nt][rr * 2 + e2] = 0.f; }
                    else          { keep[nt][rr * 2 + e2] += val; }
                }
            }
        }
    }

    const int cc0 = 2 * lk;
    #pragma unroll
    for (int rr = 0; rr < 2; ++rr) {
        int gm = m0 + i0w + lrow + rr * 8;
        #pragma unroll
        for (int nt = 0; nt < 4; ++nt) {
            size_t idx = (size_t)gm * HW + n0 + jbase + nt * 8 + cc0;
            float2 x2 = *(const float2*)&x[idx];
            *(float2*)&out[idx] = make_float2(keep[nt][rr * 2 + 0] + x2.x,
                                              keep[nt][rr * 2 + 1] + x2.y);
        }
    }
}

// ---------------- branch-1 flash attention (register-P, fp16 bias tile) ------
#define QS_OFF   0               // bf16 [128][72]
#define KS_OFF   18432           // bf16 [128][72]
#define VS_OFF   36864           // f16  [128][72]
#define RB_OFF   55296           // f16  [64][72] fused Rw+Rh bias
#define PMAX_OFF 64512           // f32  [2][64]
#define PSUM_OFF 65024           // f32  [2][64]
#define MR_OFF   65536           // f32  [64]
#define LR_OFF   65792           // f32  [64]
#define FL_SM_BYTES 66048

__global__ void __launch_bounds__(256, 2) flash_kernel(
    const __nv_bfloat16* __restrict__ q, const __nv_bfloat16* __restrict__ k,
    const __half* __restrict__ v, const float* __restrict__ Rh,
    const float* __restrict__ Rw, float* __restrict__ op,
    float* __restrict__ mp, float* __restrict__ lp)
{
    extern __shared__ char smc[];
    __nv_bfloat16* Qs = (__nv_bfloat16*)(smc + QS_OFF);
    __half* RbH = (__half*)(smc + RB_OFF);
    float* pmax = (float*)(smc + PMAX_OFF);
    float* psum = (float*)(smc + PSUM_OFF);
    float* mrow = (float*)(smc + MR_OFF);
    float* lrow = (float*)(smc + LR_OFF);

    const int tid  = threadIdx.x;
    const int wid  = tid >> 5, lane = tid & 31;
    const int lr   = lane & 7, gq = lane >> 3;
    const int lrowq = lane >> 2, lk = lane & 3;
    const int i0   = blockIdx.x * 64;
    const int spl  = blockIdx.y;
    const int t0   = (spl * 100) / SPLIT;
    const int t1   = ((spl + 1) * 100) / SPLIT;
    const int i0w  = (wid & 3) * 16;
    const int jhalf = wid >> 2;
    const int jbase = jhalf * 32;
    const float L2E = 1.4426950408889634f;

    const uint32_t qsb = (uint32_t)__cvta_generic_to_shared(Qs);
    const uint32_t ksb = (uint32_t)__cvta_generic_to_shared(smc + KS_OFF);
    const uint32_t vsb = (uint32_t)__cvta_generic_to_shared(smc + VS_OFF);

    {   // prologue: K(t0), V(t0) via cp.async
        int j0n = t0 * 64;
        #pragma unroll
        for (int it = 0; it < 4; ++it) {
            int ch = tid + it * 256;
            int c = ch >> 3, j8 = (ch & 7) * 8;
            cpa16(ksb + (uint32_t)((c * 72 + j8) * 2), &k[(size_t)c * HW + j0n + j8]);
        }
        CPA_COMMIT();
        #pragma unroll
        for (int it = 0; it < 4; ++it) {
            int ch = tid + it * 256;
            int c = ch >> 3, j8 = (ch & 7) * 8;
            cpa16(vsb + (uint32_t)((c * 72 + j8) * 2), &v[(size_t)c * HW + j0n + j8]);
        }
        CPA_COMMIT();
    }
    {   // Q tile bf16 [c][i]
        int cr = tid >> 4, i4 = (tid & 15) << 2;
        #pragma unroll
        for (int it = 0; it < 8; ++it) {
            int c = cr + it * 16;
            *(uint2*)&Qs[c * 72 + i4] = *(const uint2*)&q[(size_t)c * HW + i0 + i4];
        }
    }
    if (tid < 64) { mrow[tid] = -1e30f; lrow[tid] = 0.f; }

    float d[16][4];   // O partial: all 128 channels, this warp's 32 j's
    #pragma unroll
    for (int nt = 0; nt < 16; ++nt)
        #pragma unroll
        for (int e = 0; e < 4; ++e) d[nt][e] = 0.f;

    const int r0 = i0w + lrowq, r1 = r0 + 8;

    for (int t = t0; t < t1; ++t) {
        const int j0 = t * 64;
        const bool more = (t + 1 < t1);

        // stage fused bias tile in fp16: Rb[row][col] = Rw[(i0+row)%80] + Rh[(i0+row)/80]
        #pragma unroll
        for (int e = 0; e < 4; ++e) {
            int ee = tid + e * 256;
            int row = ee >> 4, c4 = (ee & 15) << 2;
            int gi = i0 + row;
            float4 a = *(const float4*)&Rw[(gi % 80) * HW + j0 + c4];
            float4 b = *(const float4*)&Rh[(gi / 80) * HW + j0 + c4];
            __half2* dst = (__half2*)&RbH[row * 72 + c4];
            dst[0] = __floats2half2_rn(a.x + b.x, a.y + b.y);
            dst[1] = __floats2half2_rn(a.z + b.z, a.w + b.w);
        }
        asm volatile("cp.async.wait_group 1;");   // K(t) landed
        __syncthreads();

        // ---- QK^T (bf16) ----
        float sf[4][4];
        #pragma unroll
        for (int nt = 0; nt < 4; ++nt)
            #pragma unroll
            for (int e = 0; e < 4; ++e) sf[nt][e] = 0.f;

        #pragma unroll
        for (int ks = 0; ks < 8; ++ks) {
            int k0 = ks * 16;
            uint32_t a0, a1, a2, a3;
            ldsm4t(a0, a1, a2, a3,
                   qsb + (uint32_t)(((k0 + lr + (gq >> 1) * 8) * 72 + i0w + (gq & 1) * 8) * 2));
            #pragma unroll
            for (int np = 0; np < 2; ++np) {
                int jb = jbase + np * 16;
                uint32_t b0, b1, b2, b3;
                ldsm4t(b0, b1, b2, b3,
                       ksb + (uint32_t)(((k0 + lr + (gq & 1) * 8) * 72 + jb + (gq >> 1) * 8) * 2));
                mma_bf16(sf[np * 2],     a0, a1, a2, a3, b0, b1);
                mma_bf16(sf[np * 2 + 1], a0, a1, a2, a3, b2, b3);
            }
        }

        // ---- bias add (fp16 tile) + warp-partial row max ----
        #pragma unroll
        for (int nt = 0; nt < 4; ++nt) {
            int col = jbase + nt * 8 + 2 * lk;
            float2 b0 = __half22float2(*(__half2*)&RbH[r0 * 72 + col]);
            float2 b1 = __half22float2(*(__half2*)&RbH[r1 * 72 + col]);
            sf[nt][0] += b0.x; sf[nt][1] += b0.y;
            sf[nt][2] += b1.x; sf[nt][3] += b1.y;
        }
        float mx0 = fmaxf(fmaxf(sf[0][0], sf[0][1]), fmaxf(sf[1][0], sf[1][1]));
        mx0 = fmaxf(mx0, fmaxf(fmaxf(sf[2][0], sf[2][1]), fmaxf(sf[3][0], sf[3][1])));
        float mx1 = fmaxf(fmaxf(sf[0][2], sf[0][3]), fmaxf(sf[1][2], sf[1][3]));
        mx1 = fmaxf(mx1, fmaxf(fmaxf(sf[2][2], sf[2][3]), fmaxf(sf[3][2], sf[3][3])));
        mx0 = fmaxf(mx0, __shfl_xor_sync(0xffffffffu, mx0, 1));
        mx0 = fmaxf(mx0, __shfl_xor_sync(0xffffffffu, mx0, 2));
        mx1 = fmaxf(mx1, __shfl_xor_sync(0xffffffffu, mx1, 1));
        mx1 = fmaxf(mx1, __shfl_xor_sync(0xffffffffu, mx1, 2));
        if (lk == 0) {
            pmax[jhalf * 64 + r0] = mx0;
            pmax[jhalf * 64 + r1] = mx1;
        }
        __syncthreads();                          // pmax ready; Ks fully read

        if (more) {                               // K(t+1) in place
            int j0n = (t + 1) * 64;
            #pragma unroll
            for (int it = 0; it < 4; ++it) {
                int ch = tid + it * 256;
                int c = ch >> 3, j8 = (ch & 7) * 8;
                cpa16(ksb + (uint32_t)((c * 72 + j8) * 2), &k[(size_t)c * HW + j0n + j8]);
            }
            CPA_COMMIT();
        }

        // ---- exp in f16x2 -> P fragments in registers ----
        float mold0 = mrow[r0], mold1 = mrow[r1];
        float nm0 = fmaxf(mold0, fmaxf(pmax[r0], pmax[64 + r0]));
        float nm1 = fmaxf(mold1, fmaxf(pmax[r1], pmax[64 + r1]));
        float f0 = exp2f((mold0 - nm0) * L2E);
        float f1 = exp2f((mold1 - nm1) * L2E);
        uint32_t ph[4][2];
        float s0 = 0.f, s1 = 0.f;
        #pragma unroll
        for (int nt = 0; nt < 4; ++nt) {
            float u0 = (sf[nt][0] - nm0) * L2E, u1 = (sf[nt][1] - nm0) * L2E;
            float u2 = (sf[nt][2] - nm1) * L2E, u3 = (sf[nt][3] - nm1) * L2E;
            uint32_t p0, p1;
            asm("cvt.rn.f16x2.f32 %0, %1, %2;" : "=r"(p0) : "f"(u1), "f"(u0));
            asm("ex2.approx.f16x2 %0, %0;" : "+r"(p0));
            asm("cvt.rn.f16x2.f32 %0, %1, %2;" : "=r"(p1) : "f"(u3), "f"(u2));
            asm("ex2.approx.f16x2 %0, %0;" : "+r"(p1));
            ph[nt][0] = p0; ph[nt][1] = p1;
            float2 e0 = __half22float2(*reinterpret_cast<__half2*>(&p0));
            float2 e1 = __half22float2(*reinterpret_cast<__half2*>(&p1));
            s0 += e0.x + e0.y;
            s1 += e1.x + e1.y;
        }
        s0 += __shfl_xor_sync(0xffffffffu, s0, 1);
        s0 += __shfl_xor_sync(0xffffffffu, s0, 2);
        s1 += __shfl_xor_sync(0xffffffffu, s1, 1);
        s1 += __shfl_xor_sync(0xffffffffu, s1, 2);
        if (lk == 0) {
            psum[jhalf * 64 + r0] = s0;
            psum[jhalf * 64 + r1] = s1;
        }
        // rescale O partials
        #pragma unroll
        for (int nt = 0; nt < 16; ++nt) {
            d[nt][0] *= f0; d[nt][1] *= f0;
            d[nt][2] *= f1; d[nt][3] *= f1;
        }
        if (more) asm volatile("cp.async.wait_group 1;");  // V(t) landed
        else      asm volatile("cp.async.wait_group 0;");
        __syncthreads();                          // psum + Vs ready

        if (tid < 64) {                           // update running stats
            int r = tid;
            float mo = mrow[r];
            float nm = fmaxf(mo, fmaxf(pmax[r], pmax[64 + r]));
            float f = exp2f((mo - nm) * L2E);
            lrow[r] = lrow[r] * f + psum[r] + psum[64 + r];
            mrow[r] = nm;
        }

        // ---- P @ V^T : A = register P fragments, B = V (fp16) ----
        #pragma unroll
        for (int ks = 0; ks < 2; ++ks) {
            int j0s = jbase + ks * 16;
            uint32_t a0 = ph[2 * ks][0], a1 = ph[2 * ks][1];
            uint32_t a2 = ph[2 * ks + 1][0], a3 = ph[2 * ks + 1][1];
            #pragma unroll
            for (int np = 0; np < 8; ++np) {
                int cb = np * 16;
                uint32_t b0, b1, b2, b3;
                ldsm4(b0, b1, b2, b3,
                      vsb + (uint32_t)(((cb + lr + (gq >> 1) * 8) * 72 + j0s + (gq & 1) * 8) * 2));
                mma_f16(d[np * 2],     a0, a1, a2, a3, b0, b1);
                mma_f16(d[np * 2 + 1], a0, a1, a2, a3, b2, b3);
            }
        }

        if (more) {
            __syncthreads();                      // Vs fully read
            int j0n = (t + 1) * 64;
            #pragma unroll
            for (int it = 0; it < 4; ++it) {
                int ch = tid + it * 256;
                int c = ch >> 3, j8 = (ch & 7) * 8;
                cpa16(vsb + (uint32_t)((c * 72 + j8) * 2), &v[(size_t)c * HW + j0n + j8]);
            }
            CPA_COMMIT();
        }
    }

    // ---- epilogue: combine j-half warp pairs, emit partials ----
    __syncthreads();
    float* fbuf = (float*)smc;   // [64][132] reuse of Q/K smem
    if (jhalf == 1) {
        #pragma unroll
        for (int nt = 0; nt < 16; ++nt) {
            int c = nt * 8 + 2 * lk;
            *(float2*)&fbuf[r0 * 132 + c] = make_float2(d[nt][0], d[nt][1]);
            *(float2*)&fbuf[r1 * 132 + c] = make_float2(d[nt][2], d[nt][3]);
        }
    }
    __syncthreads();
    if (jhalf == 0) {
        #pragma unroll
        for (int nt = 0; nt < 16; ++nt) {
            int c = nt * 8 + 2 * lk;
            float2 o0 = *(float2*)&fbuf[r0 * 132 + c];
            float2 o1 = *(float2*)&fbuf[r1 * 132 + c];
            op[(size_t)(spl * NC + c)     * HW + i0 + r0] = d[nt][0] + o0.x;
            op[(size_t)(spl * NC + c + 1) * HW + i0 + r0] = d[nt][1] + o0.y;
            op[(size_t)(spl * NC + c)     * HW + i0 + r1] = d[nt][2] + o1.x;
            op[(size_t)(spl * NC + c + 1) * HW + i0 + r1] = d[nt][3] + o1.y;
        }
    }
    if (tid < 64) {
        mp[spl * HW + i0 + tid] = mrow[tid];
        lp[spl * HW + i0 + tid] = lrow[tid];
    }
}

// ---------------- split-j combine (channel-parallel) -------------------------
__global__ void combine_kernel(const float* __restrict__ op,
                               const float* __restrict__ mp,
                               const float* __restrict__ lp,
                               float* __restrict__ out1)
{
    int i = blockIdx.x * blockDim.x + threadIdx.x;
    if (i >= HW) return;
    int c0 = blockIdx.y * 8;
    float m[SPLIT], w[SPLIT];
    float M = -1e30f;
    #pragma unroll
    for (int s = 0; s < SPLIT; ++s) { m[s] = mp[s * HW + i]; M = fmaxf(M, m[s]); }
    float L = 0.f;
    #pragma unroll
    for (int s = 0; s < SPLIT; ++s) { w[s] = __expf(m[s] - M); L += lp[s * HW + i] * w[s]; }
    float inv = 1.f / L;
    for (int c = c0; c < c0 + 8; ++c) {
        float acc = 0.f;
        #pragma unroll
        for (int s = 0; s < SPLIT; ++s)
            acc += op[((size_t)(s * NC + c)) * HW + i] * w[s];
        out1[(size_t)c * HW + i] = acc * inv;
    }
}

// -------------------------------- launch -------------------------------------
extern "C" void kernel_launch(void* const* d_in, const int* in_sizes, int n_in,
                              void* d_out, int out_size)
{
    (void)in_sizes; (void)n_in; (void)out_size;
    const float* x    = (const float*)d_in[0];
    const float* w1   = (const float*)d_in[1];
    const float* g1   = (const float*)d_in[2];
    const float* b1   = (const float*)d_in[3];
    const float* m1   = (const float*)d_in[4];
    const float* v1   = (const float*)d_in[5];
    const float* w2   = (const float*)d_in[6];
    const float* g2   = (const float*)d_in[7];
    const float* b2   = (const float*)d_in[8];
    const float* m2   = (const float*)d_in[9];
    const float* v2   = (const float*)d_in[10];
    const float* w3   = (const float*)d_in[11];
    const float* g3   = (const float*)d_in[12];
    const float* b3   = (const float*)d_in[13];
    const float* m3   = (const float*)d_in[14];
    const float* v3   = (const float*)d_in[15];
    const float* wq   = (const float*)d_in[16];
    const float* bq   = (const float*)d_in[17];
    const float* wk   = (const float*)d_in[18];
    const float* bk   = (const float*)d_in[19];
    const float* wv   = (const float*)d_in[20];
    const float* bv   = (const float*)d_in[21];
    const float* wp   = (const float*)d_in[22];
    const float* bp   = (const float*)d_in[23];
    const float* relh = (const float*)d_in[24];
    const float* relw = (const float*)d_in[25];
    const float* efh  = (const float*)d_in[26];
    const float* efw  = (const float*)d_in[27];
    float* out = (float*)d_out;

    float *px1, *pq, *pp, *pRW, *pAB, *pPAB, *pW3, *po1, *pop, *pmp, *plp;
    __nv_bfloat16 *pqb, *pkb;
    __half *pvh;
    cudaGetSymbolAddress((void**)&px1, d_x1);
    cudaGetSymbolAddress((void**)&pq,  d_q);
    cudaGetSymbolAddress((void**)&pp,  d_p);
    cudaGetSymbolAddress((void**)&pqb, d_qb);
    cudaGetSymbolAddress((void**)&pkb, d_kb);
    cudaGetSymbolAddress((void**)&pvh, d_vh);
    cudaGetSymbolAddress((void**)&pRW, d_RW);
    cudaGetSymbolAddress((void**)&pAB, d_AB);
    cudaGetSymbolAddress((void**)&pPAB, d_PAB);
    cudaGetSymbolAddress((void**)&pW3, d_W3);
    cudaGetSymbolAddress((void**)&po1, d_o1);
    cudaGetSymbolAddress((void**)&pop, d_op);
    cudaGetSymbolAddress((void**)&pmp, d_mp);
    cudaGetSymbolAddress((void**)&plp, d_lp);

    cudaFuncSetAttribute(flash_kernel,
        cudaFuncAttributeMaxDynamicSharedMemorySize, FL_SM_BYTES);

    dim3 g100_2(100, 2), g100_4(100, 4);
    dim3 gproj(100, 2, 4), gkr(100, 3, 2), gfl(100, SPLIT), gcmb(25, 16);

    // [0] x1 = SiLU(BN(w1 @ x))
    tgemm<2><<<g100_2, 256>>>(w1, x, px1, NC, ND, g1, b1, m1, v1);
    // [1] fused q/k/v/p projections (fp32 q,p; bf16 q,k; fp16 v)
    proj4<<<gproj, 256>>>(px1, wq, bq, wk, bk, wv, bv, wp, bp,
        pq, pqb, pkb, pvh, pp);
    // [2] z=0: [Rh;Rw] = [rel_h;rel_w]^T q;  z=1: [ABh;ABw] = [ef_h;ef_w]^T p
    krgemm<<<gkr, 256>>>(relh, relw, pq, pRW, efh, efw, pp, pAB);
    // [3] W3 = [w3@efh | w3@efw]
    w3eff_kernel<<<20, 256>>>(w3, efh, efw, pW3);
    // [4] PAB = per-column softmax of both halves
    expnorm<<<50, 256>>>(pAB, pPAB);
    // [5] flash attention (register-P, fp16 bias tile, split-j = 8)
    flash_kernel<<<gfl, 256, FL_SM_BYTES>>>(pqb, pkb, pvh,
        pRW, pRW + NH * HW, pop, pmp, plp);
    // [6] combine split partials -> out1
    combine_kernel<<<gcmb, 256>>>(pop, pmp, plp, po1);
    // [7] out = x + SiLU(BN2(w2@o1)) + SiLU(BN3(W3@PAB))
    final_gemm<<<g100_4, 256>>>(w2, po1, g2, b2, m2, v2,
        pW3, pPAB, g3, b3, m3, v3, x, out);
}

// round 10
// speedup vs baseline: 6.0215x; 1.0628x over previous
#include <cuda_runtime.h>
#include <cuda_bf16.h>
#include <cuda_fp16.h>
#include <cstdint>

#define EPS 1e-5f
#define HW 6400
#define NC 128
#define ND 256
#define NH 80
#define SPLIT 8

// ---------------- tensor-core helpers ----------------------------------------
__device__ __forceinline__ void ldsm4(uint32_t& r0, uint32_t& r1,
                                      uint32_t& r2, uint32_t& r3, uint32_t a) {
    asm volatile("ldmatrix.sync.aligned.m8n8.x4.shared.b16 {%0,%1,%2,%3},[%4];"
        : "=r"(r0), "=r"(r1), "=r"(r2), "=r"(r3) : "r"(a));
}
__device__ __forceinline__ void ldsm4t(uint32_t& r0, uint32_t& r1,
                                       uint32_t& r2, uint32_t& r3, uint32_t a) {
    asm volatile("ldmatrix.sync.aligned.m8n8.x4.trans.shared.b16 {%0,%1,%2,%3},[%4];"
        : "=r"(r0), "=r"(r1), "=r"(r2), "=r"(r3) : "r"(a));
}
__device__ __forceinline__ void mma_bf16(float* d, uint32_t a0, uint32_t a1,
                                         uint32_t a2, uint32_t a3,
                                         uint32_t b0, uint32_t b1) {
    asm volatile("mma.sync.aligned.m16n8k16.row.col.f32.bf16.bf16.f32 "
        "{%0,%1,%2,%3},{%4,%5,%6,%7},{%8,%9},{%0,%1,%2,%3};"
        : "+f"(d[0]), "+f"(d[1]), "+f"(d[2]), "+f"(d[3])
        : "r"(a0), "r"(a1), "r"(a2), "r"(a3), "r"(b0), "r"(b1));
}
__device__ __forceinline__ void mma_f16(float* d, uint32_t a0, uint32_t a1,
                                        uint32_t a2, uint32_t a3,
                                        uint32_t b0, uint32_t b1) {
    asm volatile("mma.sync.aligned.m16n8k16.row.col.f32.f16.f16.f32 "
        "{%0,%1,%2,%3},{%4,%5,%6,%7},{%8,%9},{%0,%1,%2,%3};"
        : "+f"(d[0]), "+f"(d[1]), "+f"(d[2]), "+f"(d[3])
        : "r"(a0), "r"(a1), "r"(a2), "r"(a3), "r"(b0), "r"(b1));
}
__device__ __forceinline__ void mma_tf32(float* d, uint32_t a0, uint32_t a1,
                                         uint32_t a2, uint32_t a3,
                                         uint32_t b0, uint32_t b1) {
    asm volatile("mma.sync.aligned.m16n8k8.row.col.f32.tf32.tf32.f32 "
        "{%0,%1,%2,%3},{%4,%5,%6,%7},{%8,%9},{%0,%1,%2,%3};"
        : "+f"(d[0]), "+f"(d[1]), "+f"(d[2]), "+f"(d[3])
        : "r"(a0), "r"(a1), "r"(a2), "r"(a3), "r"(b0), "r"(b1));
}
__device__ __forceinline__ float tf32r(float x) {
    uint32_t r;
    asm("cvt.rna.tf32.f32 %0, %1;" : "=r"(r) : "f"(x));
    return __uint_as_float(r);
}
__device__ __forceinline__ void cpa16(uint32_t s, const void* g) {
    asm volatile("cp.async.cg.shared.global [%0], [%1], 16;" :: "r"(s), "l"(g));
}
#define CPA_COMMIT() asm volatile("cp.async.commit_group;")

// ---------------- scratch (static device globals; no allocation) -------------
__device__ float d_x1 [NC*HW];
__device__ float d_q  [NC*HW];
__device__ float d_p  [NC*HW];
__device__ __nv_bfloat16 d_qb[NC*HW];
__device__ __nv_bfloat16 d_kb[NC*HW];
__device__ __half d_vh[NC*HW];
__device__ float d_RW  [2*NH*HW];   // [Rh(80); Rw(80)]
__device__ float d_AB  [2*NH*HW];   // [ABh(80); ABw(80)]
__device__ float d_PAB [2*NH*HW];   // normalized [PA(80); PB(80)]
__device__ float d_W3  [ND*2*NH];   // [w3@efh | w3@efw]  m-major [256][160]
__device__ float d_o1  [NC*HW];
__device__ float d_op  [SPLIT*NC*HW];
__device__ float d_mp  [SPLIT*HW];
__device__ float d_lp  [SPLIT*HW];

// ---------------- tf32 GEMM (x1 conv) with register-prefetch pipeline --------
template<int EPI>
__global__ void __launch_bounds__(256) tgemm(
    const float* __restrict__ A, const float* __restrict__ B,
    float* __restrict__ C, int M, int K,
    const float* __restrict__ g, const float* __restrict__ bb,
    const float* __restrict__ mm, const float* __restrict__ vv)
{
    __shared__ float Wt[64 * 72];
    __shared__ float Bt[64 * 72];
    const int tid = threadIdx.x;
    const int wid = tid >> 5, lane = tid & 31;
    const int m0 = blockIdx.y * 64, n0 = blockIdx.x * 64;
    const int i0w = (wid & 3) * 16;
    const int jbase = (wid >> 2) * 32;
    const int lrow = lane >> 2, lk = lane & 3;
    const int mA = tid >> 2, kqA = (tid & 3) << 2;
    const int kkB = tid >> 4, n4B = (tid & 15) << 2;

    float sf[4][4];
    #pragma unroll
    for (int nt = 0; nt < 4; ++nt)
        #pragma unroll
        for (int e = 0; e < 4; ++e) sf[nt][e] = 0.f;

    float4 ar[4], br[4];
    #pragma unroll
    for (int i = 0; i < 4; ++i) {
        ar[i] = *(const float4*)&A[(size_t)(m0 + mA) * K + kqA + 16 * i];
        br[i] = *(const float4*)&B[(size_t)(kkB + 16 * i) * HW + n0 + n4B];
    }

    for (int kc = 0; kc < K; kc += 64) {
        #pragma unroll
        for (int i = 0; i < 4; ++i) {
            int k4 = kqA + 16 * i;
            Wt[(k4 + 0) * 72 + mA] = tf32r(ar[i].x);
            Wt[(k4 + 1) * 72 + mA] = tf32r(ar[i].y);
            Wt[(k4 + 2) * 72 + mA] = tf32r(ar[i].z);
            Wt[(k4 + 3) * 72 + mA] = tf32r(ar[i].w);
            int kk = kkB + 16 * i;
            float* bp = &Bt[kk * 72 + n4B];
            bp[0] = tf32r(br[i].x); bp[1] = tf32r(br[i].y);
            bp[2] = tf32r(br[i].z); bp[3] = tf32r(br[i].w);
        }
        __syncthreads();
        if (kc + 64 < K) {
            #pragma unroll
            for (int i = 0; i < 4; ++i) {
                ar[i] = *(const float4*)&A[(size_t)(m0 + mA) * K + kc + 64 + kqA + 16 * i];
                br[i] = *(const float4*)&B[(size_t)(kc + 64 + kkB + 16 * i) * HW + n0 + n4B];
            }
        }
        #pragma unroll
        for (int ks = 0; ks < 8; ++ks) {
            int k0 = ks * 8;
            uint32_t a0 = __float_as_uint(Wt[(k0 + lk) * 72 + i0w + lrow]);
            uint32_t a1 = __float_as_uint(Wt[(k0 + lk) * 72 + i0w + lrow + 8]);
            uint32_t a2 = __float_as_uint(Wt[(k0 + lk + 4) * 72 + i0w + lrow]);
            uint32_t a3 = __float_as_uint(Wt[(k0 + lk + 4) * 72 + i0w + lrow + 8]);
            #pragma unroll
            for (int np = 0; np < 4; ++np) {
                int ncol = jbase + np * 8 + lrow;
                uint32_t b0 = __float_as_uint(Bt[(k0 + lk) * 72 + ncol]);
                uint32_t b1 = __float_as_uint(Bt[(k0 + lk + 4) * 72 + ncol]);
                mma_tf32(sf[np], a0, a1, a2, a3, b0, b1);
            }
        }
        __syncthreads();
    }

    const int cc0 = 2 * lk;
    #pragma unroll
    for (int rr = 0; rr < 2; ++rr) {
        int gm = m0 + i0w + lrow + rr * 8;
        float sc = 0.f, sh = 0.f;
        if (EPI == 2) {
            sc = g[gm] * rsqrtf(vv[gm] + EPS);
            sh = bb[gm] - mm[gm] * sc;
        }
        #pragma unroll
        for (int nt = 0; nt < 4; ++nt) {
            float e0 = sf[nt][rr * 2 + 0];
            float e1 = sf[nt][rr * 2 + 1];
            if (EPI == 2) {
                e0 = e0 * sc + sh; e1 = e1 * sc + sh;
                e0 = e0 / (1.f + __expf(-e0));
                e1 = e1 / (1.f + __expf(-e1));
            }
            size_t idx = (size_t)gm * HW + n0 + jbase + nt * 8 + cc0;
            *(float2*)&C[idx] = make_float2(e0, e1);
        }
    }
}

// ---------------- fused q/k/v/p projection (z selects weight; prefetch) ------
__global__ void __launch_bounds__(256) proj4(
    const float* __restrict__ x1,
    const float* __restrict__ wq, const float* __restrict__ bq,
    const float* __restrict__ wk, const float* __restrict__ bk,
    const float* __restrict__ wv, const float* __restrict__ bv,
    const float* __restrict__ wp, const float* __restrict__ bp,
    float* __restrict__ qf, __nv_bfloat16* __restrict__ qb,
    __nv_bfloat16* __restrict__ kb, __half* __restrict__ vh,
    float* __restrict__ pf)
{
    __shared__ float Wt[64 * 72];
    __shared__ float Bt[64 * 72];
    const int z = blockIdx.z;
    const float* A    = (z == 0) ? wq : (z == 1) ? wk : (z == 2) ? wv : wp;
    const float* bias = (z == 0) ? bq : (z == 1) ? bk : (z == 2) ? bv : bp;
    const int tid = threadIdx.x;
    const int wid = tid >> 5, lane = tid & 31;
    const int m0 = blockIdx.y * 64, n0 = blockIdx.x * 64;
    const int i0w = (wid & 3) * 16;
    const int jbase = (wid >> 2) * 32;
    const int lrow = lane >> 2, lk = lane & 3;
    const int mA = tid >> 2, kqA = (tid & 3) << 2;
    const int kkB = tid >> 4, n4B = (tid & 15) << 2;

    float sf[4][4];
    #pragma unroll
    for (int nt = 0; nt < 4; ++nt)
        #pragma unroll
        for (int e = 0; e < 4; ++e) sf[nt][e] = 0.f;

    float4 ar[4], br[4];
    #pragma unroll
    for (int i = 0; i < 4; ++i) {
        ar[i] = *(const float4*)&A[(size_t)(m0 + mA) * NC + kqA + 16 * i];
        br[i] = *(const float4*)&x1[(size_t)(kkB + 16 * i) * HW + n0 + n4B];
    }

    for (int kc = 0; kc < NC; kc += 64) {
        #pragma unroll
        for (int i = 0; i < 4; ++i) {
            int k4 = kqA + 16 * i;
            Wt[(k4 + 0) * 72 + mA] = tf32r(ar[i].x);
            Wt[(k4 + 1) * 72 + mA] = tf32r(ar[i].y);
            Wt[(k4 + 2) * 72 + mA] = tf32r(ar[i].z);
            Wt[(k4 + 3) * 72 + mA] = tf32r(ar[i].w);
            int kk = kkB + 16 * i;
            float* bp2 = &Bt[kk * 72 + n4B];
            bp2[0] = tf32r(br[i].x); bp2[1] = tf32r(br[i].y);
            bp2[2] = tf32r(br[i].z); bp2[3] = tf32r(br[i].w);
        }
        __syncthreads();
        if (kc + 64 < NC) {
            #pragma unroll
            for (int i = 0; i < 4; ++i) {
                ar[i] = *(const float4*)&A[(size_t)(m0 + mA) * NC + kc + 64 + kqA + 16 * i];
                br[i] = *(const float4*)&x1[(size_t)(kc + 64 + kkB + 16 * i) * HW + n0 + n4B];
            }
        }
        #pragma unroll
        for (int ks = 0; ks < 8; ++ks) {
            int k0 = ks * 8;
            uint32_t a0 = __float_as_uint(Wt[(k0 + lk) * 72 + i0w + lrow]);
            uint32_t a1 = __float_as_uint(Wt[(k0 + lk) * 72 + i0w + lrow + 8]);
            uint32_t a2 = __float_as_uint(Wt[(k0 + lk + 4) * 72 + i0w + lrow]);
            uint32_t a3 = __float_as_uint(Wt[(k0 + lk + 4) * 72 + i0w + lrow + 8]);
            #pragma unroll
            for (int np = 0; np < 4; ++np) {
                int ncol = jbase + np * 8 + lrow;
                uint32_t b0 = __float_as_uint(Bt[(k0 + lk) * 72 + ncol]);
                uint32_t b1 = __float_as_uint(Bt[(k0 + lk + 4) * 72 + ncol]);
                mma_tf32(sf[np], a0, a1, a2, a3, b0, b1);
            }
        }
        __syncthreads();
    }

    const int cc0 = 2 * lk;
    #pragma unroll
    for (int rr = 0; rr < 2; ++rr) {
        int gm = m0 + i0w + lrow + rr * 8;
        float bsv = bias[gm];
        #pragma unroll
        for (int nt = 0; nt < 4; ++nt) {
            float e0 = sf[nt][rr * 2 + 0] + bsv;
            float e1 = sf[nt][rr * 2 + 1] + bsv;
            size_t idx = (size_t)gm * HW + n0 + jbase + nt * 8 + cc0;
            if (z == 0) {
                *(float2*)&qf[idx] = make_float2(e0, e1);
                *(__nv_bfloat162*)&qb[idx] = __floats2bfloat162_rn(e0, e1);
            } else if (z == 1) {
                *(__nv_bfloat162*)&kb[idx] = __floats2bfloat162_rn(e0, e1);
            } else if (z == 2) {
                *(__half2*)&vh[idx] = __floats2half2_rn(e0, e1);
            } else {
                *(float2*)&pf[idx] = make_float2(e0, e1);
            }
        }
    }
}

// ---------------- stacked k-major GEMM (z=0: RW, z=1: AB; prefetch) ----------
__global__ void __launch_bounds__(256) krgemm(
    const float* __restrict__ lo0, const float* __restrict__ hi0,
    const float* __restrict__ B0, float* __restrict__ C0,
    const float* __restrict__ lo1, const float* __restrict__ hi1,
    const float* __restrict__ B1, float* __restrict__ C1)
{
    __shared__ float Wt[64 * 72];
    __shared__ float Bt[64 * 72];
    const int z = blockIdx.z;
    const float* a_lo = z ? lo1 : lo0;
    const float* a_hi = z ? hi1 : hi0;
    const float* B    = z ? B1  : B0;
    float*       C    = z ? C1  : C0;
    const int tid = threadIdx.x;
    const int wid = tid >> 5, lane = tid & 31;
    const int m0 = blockIdx.y * 64, n0 = blockIdx.x * 64;
    const int i0w = (wid & 3) * 16;
    const int jbase = (wid >> 2) * 32;
    const int lrow = lane >> 2, lk = lane & 3;
    const int M = 2 * NH;
    const int kkB = tid >> 4, n4B = (tid & 15) << 2;
    const int m4A = (tid & 15) << 2;
    const int gmA = m0 + m4A;

    float sf[4][4];
    #pragma unroll
    for (int nt = 0; nt < 4; ++nt)
        #pragma unroll
        for (int e = 0; e < 4; ++e) sf[nt][e] = 0.f;

    float4 ar[4], br[4];
    #pragma unroll
    for (int i = 0; i < 4; ++i) {
        int kk = kkB + 16 * i;
        float4 a4 = make_float4(0.f, 0.f, 0.f, 0.f);
        if (gmA < NH)          a4 = *(const float4*)&a_lo[(size_t)kk * NH + gmA];
        else if (gmA < 2 * NH) a4 = *(const float4*)&a_hi[(size_t)kk * NH + gmA - NH];
        ar[i] = a4;
        br[i] = *(const float4*)&B[(size_t)kk * HW + n0 + n4B];
    }

    for (int kc = 0; kc < NC; kc += 64) {
        #pragma unroll
        for (int i = 0; i < 4; ++i) {
            int kk = kkB + 16 * i;
            float* wp = &Wt[kk * 72 + m4A];
            wp[0] = tf32r(ar[i].x); wp[1] = tf32r(ar[i].y);
            wp[2] = tf32r(ar[i].z); wp[3] = tf32r(ar[i].w);
            float* bp = &Bt[kk * 72 + n4B];
            bp[0] = tf32r(br[i].x); bp[1] = tf32r(br[i].y);
            bp[2] = tf32r(br[i].z); bp[3] = tf32r(br[i].w);
        }
        __syncthreads();
        if (kc + 64 < NC) {
            #pragma unroll
            for (int i = 0; i < 4; ++i) {
                int kk = kc + 64 + kkB + 16 * i;
                float4 a4 = make_float4(0.f, 0.f, 0.f, 0.f);
                if (gmA < NH)          a4 = *(const float4*)&a_lo[(size_t)kk * NH + gmA];
                else if (gmA < 2 * NH) a4 = *(const float4*)&a_hi[(size_t)kk * NH + gmA - NH];
                ar[i] = a4;
                br[i] = *(const float4*)&B[(size_t)kk * HW + n0 + n4B];
            }
        }
        #pragma unroll
        for (int ks = 0; ks < 8; ++ks) {
            int k0 = ks * 8;
            uint32_t a0 = __float_as_uint(Wt[(k0 + lk) * 72 + i0w + lrow]);
            uint32_t a1 = __float_as_uint(Wt[(k0 + lk) * 72 + i0w + lrow + 8]);
            uint32_t a2 = __float_as_uint(Wt[(k0 + lk + 4) * 72 + i0w + lrow]);
            uint32_t a3 = __float_as_uint(Wt[(k0 + lk + 4) * 72 + i0w + lrow + 8]);
            #pragma unroll
            for (int np = 0; np < 4; ++np) {
                int ncol = jbase + np * 8 + lrow;
                uint32_t b0 = __float_as_uint(Bt[(k0 + lk) * 72 + ncol]);
                uint32_t b1 = __float_as_uint(Bt[(k0 + lk + 4) * 72 + ncol]);
                mma_tf32(sf[np], a0, a1, a2, a3, b0, b1);
            }
        }
        __syncthreads();
    }

    const int cc0 = 2 * lk;
    #pragma unroll
    for (int rr = 0; rr < 2; ++rr) {
        int gm = m0 + i0w + lrow + rr * 8;
        if (gm >= M) continue;
        #pragma unroll
        for (int nt = 0; nt < 4; ++nt) {
            size_t idx = (size_t)gm * HW + n0 + jbase + nt * 8 + cc0;
            *(float2*)&C[idx] = make_float2(sf[nt][rr * 2 + 0], sf[nt][rr * 2 + 1]);
        }
    }
}

// ---------------- expnorm: single-store softmax over 80 rows ------------------
__global__ void expnorm(const float* __restrict__ AB, float* __restrict__ PAB)
{
    int gid = blockIdx.x * blockDim.x + threadIdx.x;
    if (gid >= 2 * HW) return;
    int h = (gid >= HW) ? 1 : 0;
    int i = gid - h * HW;
    const float* src = AB  + (size_t)h * NH * HW;
    float*       dst = PAB + (size_t)h * NH * HW;
    float s = 0.f;
    #pragma unroll 8
    for (int t = 0; t < NH; ++t) s += __expf(src[t * HW + i]);
    float inv = 1.f / s;
    #pragma unroll 8
    for (int t = 0; t < NH; ++t)
        dst[t * HW + i] = __expf(src[t * HW + i]) * inv;   // src re-read is L2-hot
}

// ---------------- W3 = [w3@efh | w3@efw]  ([256][160], m-major) --------------
// One CTA per output row m; 160 active threads each produce one W[m][t].
__global__ void __launch_bounds__(192) w3eff_kernel(
    const float* __restrict__ w3, const float* __restrict__ efh,
    const float* __restrict__ efw, float* __restrict__ W)
{
    __shared__ float sw3[NC];
    const int m = blockIdx.x;
    const int t = threadIdx.x;
    if (t < NC) sw3[t] = w3[(size_t)m * NC + t];
    __syncthreads();
    if (t >= 2 * NH) return;
    const float* ef = (t < NH) ? (efh + t) : (efw + t - NH);
    float sum = 0.f;
    #pragma unroll 16
    for (int c = 0; c < NC; ++c)
        sum += sw3[c] * ef[(size_t)c * NH];
    W[(size_t)m * 160 + t] = sum;
}

// ---------------- fused final (prefetched, dual source) ----------------------
__global__ void __launch_bounds__(256) final_gemm(
    const float* __restrict__ w2, const float* __restrict__ o1,
    const float* __restrict__ g2, const float* __restrict__ b2,
    const float* __restrict__ m2, const float* __restrict__ v2,
    const float* __restrict__ W3, const float* __restrict__ PAB,
    const float* __restrict__ g3, const float* __restrict__ b3,
    const float* __restrict__ m3, const float* __restrict__ v3,
    const float* __restrict__ x, float* __restrict__ out)
{
    __shared__ float Wt[64 * 72];
    __shared__ float Bt[64 * 72];
    const int tid = threadIdx.x;
    const int wid = tid >> 5, lane = tid & 31;
    const int m0 = blockIdx.y * 64, n0 = blockIdx.x * 64;
    const int i0w = (wid & 3) * 16;
    const int jbase = (wid >> 2) * 32;
    const int lrow = lane >> 2, lk = lane & 3;
    const int mA = tid >> 2, kqA = (tid & 3) << 2;
    const int kkB = tid >> 4, n4B = (tid & 15) << 2;

    float keep[4][4];
    float sf[4][4];
    #pragma unroll
    for (int nt = 0; nt < 4; ++nt)
        #pragma unroll
        for (int e = 0; e < 4; ++e) sf[nt][e] = 0.f;

    float4 ar[4], br[4];
    #pragma unroll
    for (int i = 0; i < 4; ++i) {
        ar[i] = *(const float4*)&w2[(size_t)(m0 + mA) * NC + kqA + 16 * i];
        br[i] = *(const float4*)&o1[(size_t)(kkB + 16 * i) * HW + n0 + n4B];
    }

    #pragma unroll
    for (int src = 0; src < 2; ++src) {
        const int Kp = src ? 160 : NC;
        for (int kc = 0; kc < Kp; kc += 64) {
            const int ck = (Kp - kc < 64) ? (Kp - kc) : 64;
            #pragma unroll
            for (int i = 0; i < 4; ++i) {
                int k4 = kqA + 16 * i;
                if (k4 < ck) {
                    Wt[(k4 + 0) * 72 + mA] = tf32r(ar[i].x);
                    Wt[(k4 + 1) * 72 + mA] = tf32r(ar[i].y);
                    Wt[(k4 + 2) * 72 + mA] = tf32r(ar[i].z);
                    Wt[(k4 + 3) * 72 + mA] = tf32r(ar[i].w);
                }
                int kk = kkB + 16 * i;
                if (kk < ck) {
                    float* bp = &Bt[kk * 72 + n4B];
                    bp[0] = tf32r(br[i].x); bp[1] = tf32r(br[i].y);
                    bp[2] = tf32r(br[i].z); bp[3] = tf32r(br[i].w);
                }
            }
            __syncthreads();
            {   // prefetch next chunk (possibly next source)
                int srcN = src, kcN = kc + 64;
                if (kcN >= Kp) { srcN = src + 1; kcN = 0; }
                if (srcN < 2) {
                    const float* ApN = srcN ? W3 : w2;
                    const float* BpN = srcN ? PAB : o1;
                    int KpN = srcN ? 160 : NC;
                    int ckN = (KpN - kcN < 64) ? (KpN - kcN) : 64;
                    #pragma unroll
                    for (int i = 0; i < 4; ++i) {
                        int k4 = kqA + 16 * i;
                        if (k4 < ckN)
                            ar[i] = *(const float4*)&ApN[(size_t)(m0 + mA) * KpN + kcN + k4];
                        int kk = kkB + 16 * i;
                        if (kk < ckN)
                            br[i] = *(const float4*)&BpN[(size_t)(kcN + kk) * HW + n0 + n4B];
                    }
                }
            }
            const int nks = ck >> 3;
            for (int ks = 0; ks < nks; ++ks) {
                int k0 = ks * 8;
                uint32_t a0 = __float_as_uint(Wt[(k0 + lk) * 72 + i0w + lrow]);
                uint32_t a1 = __float_as_uint(Wt[(k0 + lk) * 72 + i0w + lrow + 8]);
                uint32_t a2 = __float_as_uint(Wt[(k0 + lk + 4) * 72 + i0w + lrow]);
                uint32_t a3 = __float_as_uint(Wt[(k0 + lk + 4) * 72 + i0w + lrow + 8]);
                #pragma unroll
                for (int np = 0; np < 4; ++np) {
                    int ncol = jbase + np * 8 + lrow;
                    uint32_t b0 = __float_as_uint(Bt[(k0 + lk) * 72 + ncol]);
                    uint32_t b1 = __float_as_uint(Bt[(k0 + lk + 4) * 72 + ncol]);
                    mma_tf32(sf[np], a0, a1, a2, a3, b0, b1);
                }
            }
            __syncthreads();
        }
        const float* gg  = src ? g3 : g2;
        const float* bbp = src ? b3 : b2;
        const float* mmp = src ? m3 : m2;
        const float* vvp = src ? v3 : v2;
        #pragma unroll
        for (int rr = 0; rr < 2; ++rr) {
            int gm = m0 + i0w + lrow + rr * 8;
            float sc = gg[gm] * rsqrtf(vvp[gm] + EPS);
            float sh = bbp[gm] - mmp[gm] * sc;
            #pragma unroll
            for (int nt = 0; nt < 4; ++nt) {
                #pragma unroll
                for (int e2 = 0; e2 < 2; ++e2) {
                    float val = sf[nt][rr * 2 + e2] * sc + sh;
                    val = val / (1.f + __expf(-val));
                    if (src == 0) { keep[nt][rr * 2 + e2] = val; sf[nt][rr * 2 + e2] = 0.f; }
                    else          { keep[nt][rr * 2 + e2] += val; }
                }
            }
        }
    }

    const int cc0 = 2 * lk;
    #pragma unroll
    for (int rr = 0; rr < 2; ++rr) {
        int gm = m0 + i0w + lrow + rr * 8;
        #pragma unroll
        for (int nt = 0; nt < 4; ++nt) {
            size_t idx = (size_t)gm * HW + n0 + jbase + nt * 8 + cc0;
            float2 x2 = *(const float2*)&x[idx];
            *(float2*)&out[idx] = make_float2(keep[nt][rr * 2 + 0] + x2.x,
                                              keep[nt][rr * 2 + 1] + x2.y);
        }
    }
}

// ---------------- branch-1 flash attention (register-P, fp16 bias tile) ------
#define QS_OFF   0               // bf16 [128][72]
#define KS_OFF   18432           // bf16 [128][72]
#define VS_OFF   36864           // f16  [128][72]
#define RB_OFF   55296           // f16  [64][72] fused Rw+Rh bias
#define PMAX_OFF 64512           // f32  [2][64]
#define PSUM_OFF 65024           // f32  [2][64]
#define MR_OFF   65536           // f32  [64]
#define LR_OFF   65792           // f32  [64]
#define FL_SM_BYTES 66048

__global__ void __launch_bounds__(256, 2) flash_kernel(
    const __nv_bfloat16* __restrict__ q, const __nv_bfloat16* __restrict__ k,
    const __half* __restrict__ v, const float* __restrict__ Rh,
    const float* __restrict__ Rw, float* __restrict__ op,
    float* __restrict__ mp, float* __restrict__ lp)
{
    extern __shared__ char smc[];
    __nv_bfloat16* Qs = (__nv_bfloat16*)(smc + QS_OFF);
    __half* RbH = (__half*)(smc + RB_OFF);
    float* pmax = (float*)(smc + PMAX_OFF);
    float* psum = (float*)(smc + PSUM_OFF);
    float* mrow = (float*)(smc + MR_OFF);
    float* lrow = (float*)(smc + LR_OFF);

    const int tid  = threadIdx.x;
    const int wid  = tid >> 5, lane = tid & 31;
    const int lr   = lane & 7, gq = lane >> 3;
    const int lrowq = lane >> 2, lk = lane & 3;
    const int i0   = blockIdx.x * 64;
    const int spl  = blockIdx.y;
    const int t0   = (spl * 100) / SPLIT;
    const int t1   = ((spl + 1) * 100) / SPLIT;
    const int i0w  = (wid & 3) * 16;
    const int jhalf = wid >> 2;
    const int jbase = jhalf * 32;
    const float L2E = 1.4426950408889634f;

    const uint32_t qsb = (uint32_t)__cvta_generic_to_shared(Qs);
    const uint32_t ksb = (uint32_t)__cvta_generic_to_shared(smc + KS_OFF);
    const uint32_t vsb = (uint32_t)__cvta_generic_to_shared(smc + VS_OFF);

    {   // prologue: K(t0), V(t0) via cp.async
        int j0n = t0 * 64;
        #pragma unroll
        for (int it = 0; it < 4; ++it) {
            int ch = tid + it * 256;
            int c = ch >> 3, j8 = (ch & 7) * 8;
            cpa16(ksb + (uint32_t)((c * 72 + j8) * 2), &k[(size_t)c * HW + j0n + j8]);
        }
        CPA_COMMIT();
        #pragma unroll
        for (int it = 0; it < 4; ++it) {
            int ch = tid + it * 256;
            int c = ch >> 3, j8 = (ch & 7) * 8;
            cpa16(vsb + (uint32_t)((c * 72 + j8) * 2), &v[(size_t)c * HW + j0n + j8]);
        }
        CPA_COMMIT();
    }
    {   // Q tile bf16 [c][i]
        int cr = tid >> 4, i4 = (tid & 15) << 2;
        #pragma unroll
        for (int it = 0; it < 8; ++it) {
            int c = cr + it * 16;
            *(uint2*)&Qs[c * 72 + i4] = *(const uint2*)&q[(size_t)c * HW + i0 + i4];
        }
    }
    if (tid < 64) { mrow[tid] = -1e30f; lrow[tid] = 0.f; }

    float d[16][4];   // O partial: all 128 channels, this warp's 32 j's
    #pragma unroll
    for (int nt = 0; nt < 16; ++nt)
        #pragma unroll
        for (int e = 0; e < 4; ++e) d[nt][e] = 0.f;

    const int r0 = i0w + lrowq, r1 = r0 + 8;

    for (int t = t0; t < t1; ++t) {
        const int j0 = t * 64;
        const bool more = (t + 1 < t1);

        // stage fused bias tile in fp16: Rb[row][col] = Rw[(i0+row)%80] + Rh[(i0+row)/80]
        #pragma unroll
        for (int e = 0; e < 4; ++e) {
            int ee = tid + e * 256;
            int row = ee >> 4, c4 = (ee & 15) << 2;
            int gi = i0 + row;
            float4 a = *(const float4*)&Rw[(gi % 80) * HW + j0 + c4];
            float4 b = *(const float4*)&Rh[(gi / 80) * HW + j0 + c4];
            __half2* dst = (__half2*)&RbH[row * 72 + c4];
            dst[0] = __floats2half2_rn(a.x + b.x, a.y + b.y);
            dst[1] = __floats2half2_rn(a.z + b.z, a.w + b.w);
        }
        asm volatile("cp.async.wait_group 1;");   // K(t) landed
        __syncthreads();

        // ---- QK^T (bf16) ----
        float sf[4][4];
        #pragma unroll
        for (int nt = 0; nt < 4; ++nt)
            #pragma unroll
            for (int e = 0; e < 4; ++e) sf[nt][e] = 0.f;

        #pragma unroll
        for (int ks = 0; ks < 8; ++ks) {
            int k0 = ks * 16;
            uint32_t a0, a1, a2, a3;
            ldsm4t(a0, a1, a2, a3,
                   qsb + (uint32_t)(((k0 + lr + (gq >> 1) * 8) * 72 + i0w + (gq & 1) * 8) * 2));
            #pragma unroll
            for (int np = 0; np < 2; ++np) {
                int jb = jbase + np * 16;
                uint32_t b0, b1, b2, b3;
                ldsm4t(b0, b1, b2, b3,
                       ksb + (uint32_t)(((k0 + lr + (gq & 1) * 8) * 72 + jb + (gq >> 1) * 8) * 2));
                mma_bf16(sf[np * 2],     a0, a1, a2, a3, b0, b1);
                mma_bf16(sf[np * 2 + 1], a0, a1, a2, a3, b2, b3);
            }
        }

        // ---- bias add (fp16 tile) + warp-partial row max ----
        #pragma unroll
        for (int nt = 0; nt < 4; ++nt) {
            int col = jbase + nt * 8 + 2 * lk;
            float2 b0 = __half22float2(*(__half2*)&RbH[r0 * 72 + col]);
            float2 b1 = __half22float2(*(__half2*)&RbH[r1 * 72 + col]);
            sf[nt][0] += b0.x; sf[nt][1] += b0.y;
            sf[nt][2] += b1.x; sf[nt][3] += b1.y;
        }
        float mx0 = fmaxf(fmaxf(sf[0][0], sf[0][1]), fmaxf(sf[1][0], sf[1][1]));
        mx0 = fmaxf(mx0, fmaxf(fmaxf(sf[2][0], sf[2][1]), fmaxf(sf[3][0], sf[3][1])));
        float mx1 = fmaxf(fmaxf(sf[0][2], sf[0][3]), fmaxf(sf[1][2], sf[1][3]));
        mx1 = fmaxf(mx1, fmaxf(fmaxf(sf[2][2], sf[2][3]), fmaxf(sf[3][2], sf[3][3])));
        mx0 = fmaxf(mx0, __shfl_xor_sync(0xffffffffu, mx0, 1));
        mx0 = fmaxf(mx0, __shfl_xor_sync(0xffffffffu, mx0, 2));
        mx1 = fmaxf(mx1, __shfl_xor_sync(0xffffffffu, mx1, 1));
        mx1 = fmaxf(mx1, __shfl_xor_sync(0xffffffffu, mx1, 2));
        if (lk == 0) {
            pmax[jhalf * 64 + r0] = mx0;
            pmax[jhalf * 64 + r1] = mx1;
        }
        __syncthreads();                          // pmax ready; Ks fully read

        if (more) {                               // K(t+1) in place
            int j0n = (t + 1) * 64;
            #pragma unroll
            for (int it = 0; it < 4; ++it) {
                int ch = tid + it * 256;
                int c = ch >> 3, j8 = (ch & 7) * 8;
                cpa16(ksb + (uint32_t)((c * 72 + j8) * 2), &k[(size_t)c * HW + j0n + j8]);
            }
            CPA_COMMIT();
        }

        // ---- exp in f16x2 -> P fragments in registers ----
        float mold0 = mrow[r0], mold1 = mrow[r1];
        float nm0 = fmaxf(mold0, fmaxf(pmax[r0], pmax[64 + r0]));
        float nm1 = fmaxf(mold1, fmaxf(pmax[r1], pmax[64 + r1]));
        float f0 = exp2f((mold0 - nm0) * L2E);
        float f1 = exp2f((mold1 - nm1) * L2E);
        uint32_t ph[4][2];
        float s0 = 0.f, s1 = 0.f;
        #pragma unroll
        for (int nt = 0; nt < 4; ++nt) {
            float u0 = (sf[nt][0] - nm0) * L2E, u1 = (sf[nt][1] - nm0) * L2E;
            float u2 = (sf[nt][2] - nm1) * L2E, u3 = (sf[nt][3] - nm1) * L2E;
            uint32_t p0, p1;
            asm("cvt.rn.f16x2.f32 %0, %1, %2;" : "=r"(p0) : "f"(u1), "f"(u0));
            asm("ex2.approx.f16x2 %0, %0;" : "+r"(p0));
            asm("cvt.rn.f16x2.f32 %0, %1, %2;" : "=r"(p1) : "f"(u3), "f"(u2));
            asm("ex2.approx.f16x2 %0, %0;" : "+r"(p1));
            ph[nt][0] = p0; ph[nt][1] = p1;
            float2 e0 = __half22float2(*reinterpret_cast<__half2*>(&p0));
            float2 e1 = __half22float2(*reinterpret_cast<__half2*>(&p1));
            s0 += e0.x + e0.y;
            s1 += e1.x + e1.y;
        }
        s0 += __shfl_xor_sync(0xffffffffu, s0, 1);
        s0 += __shfl_xor_sync(0xffffffffu, s0, 2);
        s1 += __shfl_xor_sync(0xffffffffu, s1, 1);
        s1 += __shfl_xor_sync(0xffffffffu, s1, 2);
        if (lk == 0) {
            psum[jhalf * 64 + r0] = s0;
            psum[jhalf * 64 + r1] = s1;
        }
        // rescale O partials
        #pragma unroll
        for (int nt = 0; nt < 16; ++nt) {
            d[nt][0] *= f0; d[nt][1] *= f0;
            d[nt][2] *= f1; d[nt][3] *= f1;
        }
        if (more) asm volatile("cp.async.wait_group 1;");  // V(t) landed
        else      asm volatile("cp.async.wait_group 0;");
        __syncthreads();                          // psum + Vs ready

        if (tid < 64) {                           // update running stats
            int r = tid;
            float mo = mrow[r];
            float nm = fmaxf(mo, fmaxf(pmax[r], pmax[64 + r]));
            float f = exp2f((mo - nm) * L2E);
            lrow[r] = lrow[r] * f + psum[r] + psum[64 + r];
            mrow[r] = nm;
        }

        // ---- P @ V^T : A = register P fragments, B = V (fp16) ----
        #pragma unroll
        for (int ks = 0; ks < 2; ++ks) {
            int j0s = jbase + ks * 16;
            uint32_t a0 = ph[2 * ks][0], a1 = ph[2 * ks][1];
            uint32_t a2 = ph[2 * ks + 1][0], a3 = ph[2 * ks + 1][1];
            #pragma unroll
            for (int np = 0; np < 8; ++np) {
                int cb = np * 16;
                uint32_t b0, b1, b2, b3;
                ldsm4(b0, b1, b2, b3,
                      vsb + (uint32_t)(((cb + lr + (gq >> 1) * 8) * 72 + j0s + (gq & 1) * 8) * 2));
                mma_f16(d[np * 2],     a0, a1, a2, a3, b0, b1);
                mma_f16(d[np * 2 + 1], a0, a1, a2, a3, b2, b3);
            }
        }

        if (more) {
            __syncthreads();                      // Vs fully read
            int j0n = (t + 1) * 64;
            #pragma unroll
            for (int it = 0; it < 4; ++it) {
                int ch = tid + it * 256;
                int c = ch >> 3, j8 = (ch & 7) * 8;
                cpa16(vsb + (uint32_t)((c * 72 + j8) * 2), &v[(size_t)c * HW + j0n + j8]);
            }
            CPA_COMMIT();
        }
    }

    // ---- epilogue: combine j-half warp pairs, emit partials ----
    __syncthreads();
    float* fbuf = (float*)smc;   // [64][132] reuse of Q/K smem
    if (jhalf == 1) {
        #pragma unroll
        for (int nt = 0; nt < 16; ++nt) {
            int c = nt * 8 + 2 * lk;
            *(float2*)&fbuf[r0 * 132 + c] = make_float2(d[nt][0], d[nt][1]);
            *(float2*)&fbuf[r1 * 132 + c] = make_float2(d[nt][2], d[nt][3]);
        }
    }
    __syncthreads();
    if (jhalf == 0) {
        #pragma unroll
        for (int nt = 0; nt < 16; ++nt) {
            int c = nt * 8 + 2 * lk;
            float2 o0 = *(float2*)&fbuf[r0 * 132 + c];
            float2 o1 = *(float2*)&fbuf[r1 * 132 + c];
            op[(size_t)(spl * NC + c)     * HW + i0 + r0] = d[nt][0] + o0.x;
            op[(size_t)(spl * NC + c + 1) * HW + i0 + r0] = d[nt][1] + o0.y;
            op[(size_t)(spl * NC + c)     * HW + i0 + r1] = d[nt][2] + o1.x;
            op[(size_t)(spl * NC + c + 1) * HW + i0 + r1] = d[nt][3] + o1.y;
        }
    }
    if (tid < 64) {
        mp[spl * HW + i0 + tid] = mrow[tid];
        lp[spl * HW + i0 + tid] = lrow[tid];
    }
}

// ---------------- split-j combine (channel-parallel) -------------------------
__global__ void combine_kernel(const float* __restrict__ op,
                               const float* __restrict__ mp,
                               const float* __restrict__ lp,
                               float* __restrict__ out1)
{
    int i = blockIdx.x * blockDim.x + threadIdx.x;
    if (i >= HW) return;
    int c0 = blockIdx.y * 8;
    float m[SPLIT], w[SPLIT];
    float M = -1e30f;
    #pragma unroll
    for (int s = 0; s < SPLIT; ++s) { m[s] = mp[s * HW + i]; M = fmaxf(M, m[s]); }
    float L = 0.f;
    #pragma unroll
    for (int s = 0; s < SPLIT; ++s) { w[s] = __expf(m[s] - M); L += lp[s * HW + i] * w[s]; }
    float inv = 1.f / L;
    for (int c = c0; c < c0 + 8; ++c) {
        float acc = 0.f;
        #pragma unroll
        for (int s = 0; s < SPLIT; ++s)
            acc += op[((size_t)(s * NC + c)) * HW + i] * w[s];
        out1[(size_t)c * HW + i] = acc * inv;
    }
}

// -------------------------------- launch -------------------------------------
extern "C" void kernel_launch(void* const* d_in, const int* in_sizes, int n_in,
                              void* d_out, int out_size)
{
    (void)in_sizes; (void)n_in; (void)out_size;
    const float* x    = (const float*)d_in[0];
    const float* w1   = (const float*)d_in[1];
    const float* g1   = (const float*)d_in[2];
    const float* b1   = (const float*)d_in[3];
    const float* m1   = (const float*)d_in[4];
    const float* v1   = (const float*)d_in[5];
    const float* w2   = (const float*)d_in[6];
    const float* g2   = (const float*)d_in[7];
    const float* b2   = (const float*)d_in[8];
    const float* m2   = (const float*)d_in[9];
    const float* v2   = (const float*)d_in[10];
    const float* w3   = (const float*)d_in[11];
    const float* g3   = (const float*)d_in[12];
    const float* b3   = (const float*)d_in[13];
    const float* m3   = (const float*)d_in[14];
    const float* v3   = (const float*)d_in[15];
    const float* wq   = (const float*)d_in[16];
    const float* bq   = (const float*)d_in[17];
    const float* wk   = (const float*)d_in[18];
    const float* bk   = (const float*)d_in[19];
    const float* wv   = (const float*)d_in[20];
    const float* bv   = (const float*)d_in[21];
    const float* wp   = (const float*)d_in[22];
    const float* bp   = (const float*)d_in[23];
    const float* relh = (const float*)d_in[24];
    const float* relw = (const float*)d_in[25];
    const float* efh  = (const float*)d_in[26];
    const float* efw  = (const float*)d_in[27];
    float* out = (float*)d_out;

    float *px1, *pq, *pp, *pRW, *pAB, *pPAB, *pW3, *po1, *pop, *pmp, *plp;
    __nv_bfloat16 *pqb, *pkb;
    __half *pvh;
    cudaGetSymbolAddress((void**)&px1, d_x1);
    cudaGetSymbolAddress((void**)&pq,  d_q);
    cudaGetSymbolAddress((void**)&pp,  d_p);
    cudaGetSymbolAddress((void**)&pqb, d_qb);
    cudaGetSymbolAddress((void**)&pkb, d_kb);
    cudaGetSymbolAddress((void**)&pvh, d_vh);
    cudaGetSymbolAddress((void**)&pRW, d_RW);
    cudaGetSymbolAddress((void**)&pAB, d_AB);
    cudaGetSymbolAddress((void**)&pPAB, d_PAB);
    cudaGetSymbolAddress((void**)&pW3, d_W3);
    cudaGetSymbolAddress((void**)&po1, d_o1);
    cudaGetSymbolAddress((void**)&pop, d_op);
    cudaGetSymbolAddress((void**)&pmp, d_mp);
    cudaGetSymbolAddress((void**)&plp, d_lp);

    cudaFuncSetAttribute(flash_kernel,
        cudaFuncAttributeMaxDynamicSharedMemorySize, FL_SM_BYTES);

    dim3 g100_2(100, 2), g100_4(100, 4);
    dim3 gproj(100, 2, 4), gkr(100, 3, 2), gfl(100, SPLIT), gcmb(25, 16);

    // [0] W3 = [w3@efh | w3@efw]  (inputs only; fast parallel version)
    w3eff_kernel<<<ND, 192>>>(w3, efh, efw, pW3);
    // [1] x1 = SiLU(BN(w1 @ x))
    tgemm<2><<<g100_2, 256>>>(w1, x, px1, NC, ND, g1, b1, m1, v1);
    // [2] fused q/k/v/p projections (fp32 q,p; bf16 q,k; fp16 v)
    proj4<<<gproj, 256>>>(px1, wq, bq, wk, bk, wv, bv, wp, bp,
        pq, pqb, pkb, pvh, pp);
    // [3] z=0: [Rh;Rw] = [rel_h;rel_w]^T q;  z=1: [ABh;ABw] = [ef_h;ef_w]^T p
    krgemm<<<gkr, 256>>>(relh, relw, pq, pRW, efh, efw, pp, pAB);
    // [4] PAB = per-column softmax of both halves (single-store)
    expnorm<<<50, 256>>>(pAB, pPAB);
    // [5] flash attention (register-P, fp16 bias tile, split-j = 8)
    flash_kernel<<<gfl, 256, FL_SM_BYTES>>>(pqb, pkb, pvh,
        pRW, pRW + NH * HW, pop, pmp, plp);
    // [6] combine split partials -> out1
    combine_kernel<<<gcmb, 256>>>(pop, pmp, plp, po1);
    // [7] out = x + SiLU(BN2(w2@o1)) + SiLU(BN3(W3@PAB))
    final_gemm<<<g100_4, 256>>>(w2, po1, g2, b2, m2, v2,
        pW3, pPAB, g3, b3, m3, v3, x, out);
}

// round 11
// speedup vs baseline: 6.6750x; 1.1085x over previous
#include <cuda_runtime.h>
#include <cuda_bf16.h>
#include <cuda_fp16.h>
#include <cstdint>

#define EPS 1e-5f
#define HW 6400
#define NC 128
#define ND 256
#define NH 80
#define SPLIT 8

// ---------------- tensor-core helpers ----------------------------------------
__device__ __forceinline__ void ldsm4(uint32_t& r0, uint32_t& r1,
                                      uint32_t& r2, uint32_t& r3, uint32_t a) {
    asm volatile("ldmatrix.sync.aligned.m8n8.x4.shared.b16 {%0,%1,%2,%3},[%4];"
        : "=r"(r0), "=r"(r1), "=r"(r2), "=r"(r3) : "r"(a));
}
__device__ __forceinline__ void ldsm4t(uint32_t& r0, uint32_t& r1,
                                       uint32_t& r2, uint32_t& r3, uint32_t a) {
    asm volatile("ldmatrix.sync.aligned.m8n8.x4.trans.shared.b16 {%0,%1,%2,%3},[%4];"
        : "=r"(r0), "=r"(r1), "=r"(r2), "=r"(r3) : "r"(a));
}
__device__ __forceinline__ void mma_bf16(float* d, uint32_t a0, uint32_t a1,
                                         uint32_t a2, uint32_t a3,
                                         uint32_t b0, uint32_t b1) {
    asm volatile("mma.sync.aligned.m16n8k16.row.col.f32.bf16.bf16.f32 "
        "{%0,%1,%2,%3},{%4,%5,%6,%7},{%8,%9},{%0,%1,%2,%3};"
        : "+f"(d[0]), "+f"(d[1]), "+f"(d[2]), "+f"(d[3])
        : "r"(a0), "r"(a1), "r"(a2), "r"(a3), "r"(b0), "r"(b1));
}
__device__ __forceinline__ void mma_f16(float* d, uint32_t a0, uint32_t a1,
                                        uint32_t a2, uint32_t a3,
                                        uint32_t b0, uint32_t b1) {
    asm volatile("mma.sync.aligned.m16n8k16.row.col.f32.f16.f16.f32 "
        "{%0,%1,%2,%3},{%4,%5,%6,%7},{%8,%9},{%0,%1,%2,%3};"
        : "+f"(d[0]), "+f"(d[1]), "+f"(d[2]), "+f"(d[3])
        : "r"(a0), "r"(a1), "r"(a2), "r"(a3), "r"(b0), "r"(b1));
}
__device__ __forceinline__ void mma_tf32(float* d, uint32_t a0, uint32_t a1,
                                         uint32_t a2, uint32_t a3,
                                         uint32_t b0, uint32_t b1) {
    asm volatile("mma.sync.aligned.m16n8k8.row.col.f32.tf32.tf32.f32 "
        "{%0,%1,%2,%3},{%4,%5,%6,%7},{%8,%9},{%0,%1,%2,%3};"
        : "+f"(d[0]), "+f"(d[1]), "+f"(d[2]), "+f"(d[3])
        : "r"(a0), "r"(a1), "r"(a2), "r"(a3), "r"(b0), "r"(b1));
}
__device__ __forceinline__ float tf32r(float x) {
    uint32_t r;
    asm("cvt.rna.tf32.f32 %0, %1;" : "=r"(r) : "f"(x));
    return __uint_as_float(r);
}
__device__ __forceinline__ void cpa16(uint32_t s, const void* g) {
    asm volatile("cp.async.cg.shared.global [%0], [%1], 16;" :: "r"(s), "l"(g));
}
#define CPA_COMMIT() asm volatile("cp.async.commit_group;")

// ---------------- scratch (static device globals; no allocation) -------------
__device__ float d_x1 [NC*HW];
__device__ float d_q  [NC*HW];
__device__ float d_p  [NC*HW];
__device__ __nv_bfloat16 d_qb[NC*HW];
__device__ __nv_bfloat16 d_kb[NC*HW];
__device__ __half d_vh[NC*HW];
__device__ float d_RW  [2*NH*HW];   // [Rh(80); Rw(80)]
__device__ float d_AB  [2*NH*HW];   // [ABh(80); ABw(80)]
__device__ float d_PAB [2*NH*HW];   // normalized [PA(80); PB(80)]
__device__ float d_W3  [ND*2*NH];   // [w3@efh | w3@efw]  m-major [256][160]
__device__ float d_o1  [NC*HW];
__device__ float d_op  [SPLIT*NC*HW];
__device__ float d_mp  [SPLIT*HW];
__device__ float d_lp  [SPLIT*HW];

// ---------------- tf32 GEMM (x1 conv) with register-prefetch pipeline --------
template<int EPI>
__global__ void __launch_bounds__(256) tgemm(
    const float* __restrict__ A, const float* __restrict__ B,
    float* __restrict__ C, int M, int K,
    const float* __restrict__ g, const float* __restrict__ bb,
    const float* __restrict__ mm, const float* __restrict__ vv)
{
    __shared__ float Wt[64 * 72];
    __shared__ float Bt[64 * 72];
    const int tid = threadIdx.x;
    const int wid = tid >> 5, lane = tid & 31;
    const int m0 = blockIdx.y * 64, n0 = blockIdx.x * 64;
    const int i0w = (wid & 3) * 16;
    const int jbase = (wid >> 2) * 32;
    const int lrow = lane >> 2, lk = lane & 3;
    const int mA = tid >> 2, kqA = (tid & 3) << 2;
    const int kkB = tid >> 4, n4B = (tid & 15) << 2;

    float sf[4][4];
    #pragma unroll
    for (int nt = 0; nt < 4; ++nt)
        #pragma unroll
        for (int e = 0; e < 4; ++e) sf[nt][e] = 0.f;

    float4 ar[4], br[4];
    #pragma unroll
    for (int i = 0; i < 4; ++i) {
        ar[i] = *(const float4*)&A[(size_t)(m0 + mA) * K + kqA + 16 * i];
        br[i] = *(const float4*)&B[(size_t)(kkB + 16 * i) * HW + n0 + n4B];
    }

    for (int kc = 0; kc < K; kc += 64) {
        #pragma unroll
        for (int i = 0; i < 4; ++i) {
            int k4 = kqA + 16 * i;
            Wt[(k4 + 0) * 72 + mA] = tf32r(ar[i].x);
            Wt[(k4 + 1) * 72 + mA] = tf32r(ar[i].y);
            Wt[(k4 + 2) * 72 + mA] = tf32r(ar[i].z);
            Wt[(k4 + 3) * 72 + mA] = tf32r(ar[i].w);
            int kk = kkB + 16 * i;
            float* bp = &Bt[kk * 72 + n4B];
            bp[0] = tf32r(br[i].x); bp[1] = tf32r(br[i].y);
            bp[2] = tf32r(br[i].z); bp[3] = tf32r(br[i].w);
        }
        __syncthreads();
        if (kc + 64 < K) {
            #pragma unroll
            for (int i = 0; i < 4; ++i) {
                ar[i] = *(const float4*)&A[(size_t)(m0 + mA) * K + kc + 64 + kqA + 16 * i];
                br[i] = *(const float4*)&B[(size_t)(kc + 64 + kkB + 16 * i) * HW + n0 + n4B];
            }
        }
        #pragma unroll
        for (int ks = 0; ks < 8; ++ks) {
            int k0 = ks * 8;
            uint32_t a0 = __float_as_uint(Wt[(k0 + lk) * 72 + i0w + lrow]);
            uint32_t a1 = __float_as_uint(Wt[(k0 + lk) * 72 + i0w + lrow + 8]);
            uint32_t a2 = __float_as_uint(Wt[(k0 + lk + 4) * 72 + i0w + lrow]);
            uint32_t a3 = __float_as_uint(Wt[(k0 + lk + 4) * 72 + i0w + lrow + 8]);
            #pragma unroll
            for (int np = 0; np < 4; ++np) {
                int ncol = jbase + np * 8 + lrow;
                uint32_t b0 = __float_as_uint(Bt[(k0 + lk) * 72 + ncol]);
                uint32_t b1 = __float_as_uint(Bt[(k0 + lk + 4) * 72 + ncol]);
                mma_tf32(sf[np], a0, a1, a2, a3, b0, b1);
            }
        }
        __syncthreads();
    }

    const int cc0 = 2 * lk;
    #pragma unroll
    for (int rr = 0; rr < 2; ++rr) {
        int gm = m0 + i0w + lrow + rr * 8;
        float sc = 0.f, sh = 0.f;
        if (EPI == 2) {
            sc = g[gm] * rsqrtf(vv[gm] + EPS);
            sh = bb[gm] - mm[gm] * sc;
        }
        #pragma unroll
        for (int nt = 0; nt < 4; ++nt) {
            float e0 = sf[nt][rr * 2 + 0];
            float e1 = sf[nt][rr * 2 + 1];
            if (EPI == 2) {
                e0 = e0 * sc + sh; e1 = e1 * sc + sh;
                e0 = e0 / (1.f + __expf(-e0));
                e1 = e1 / (1.f + __expf(-e1));
            }
            size_t idx = (size_t)gm * HW + n0 + jbase + nt * 8 + cc0;
            *(float2*)&C[idx] = make_float2(e0, e1);
        }
    }
}

// ---------------- fused q/k/v/p projection (z selects weight; prefetch) ------
__global__ void __launch_bounds__(256) proj4(
    const float* __restrict__ x1,
    const float* __restrict__ wq, const float* __restrict__ bq,
    const float* __restrict__ wk, const float* __restrict__ bk,
    const float* __restrict__ wv, const float* __restrict__ bv,
    const float* __restrict__ wp, const float* __restrict__ bp,
    float* __restrict__ qf, __nv_bfloat16* __restrict__ qb,
    __nv_bfloat16* __restrict__ kb, __half* __restrict__ vh,
    float* __restrict__ pf)
{
    __shared__ float Wt[64 * 72];
    __shared__ float Bt[64 * 72];
    const int z = blockIdx.z;
    const float* A    = (z == 0) ? wq : (z == 1) ? wk : (z == 2) ? wv : wp;
    const float* bias = (z == 0) ? bq : (z == 1) ? bk : (z == 2) ? bv : bp;
    const int tid = threadIdx.x;
    const int wid = tid >> 5, lane = tid & 31;
    const int m0 = blockIdx.y * 64, n0 = blockIdx.x * 64;
    const int i0w = (wid & 3) * 16;
    const int jbase = (wid >> 2) * 32;
    const int lrow = lane >> 2, lk = lane & 3;
    const int mA = tid >> 2, kqA = (tid & 3) << 2;
    const int kkB = tid >> 4, n4B = (tid & 15) << 2;

    float sf[4][4];
    #pragma unroll
    for (int nt = 0; nt < 4; ++nt)
        #pragma unroll
        for (int e = 0; e < 4; ++e) sf[nt][e] = 0.f;

    float4 ar[4], br[4];
    #pragma unroll
    for (int i = 0; i < 4; ++i) {
        ar[i] = *(const float4*)&A[(size_t)(m0 + mA) * NC + kqA + 16 * i];
        br[i] = *(const float4*)&x1[(size_t)(kkB + 16 * i) * HW + n0 + n4B];
    }

    for (int kc = 0; kc < NC; kc += 64) {
        #pragma unroll
        for (int i = 0; i < 4; ++i) {
            int k4 = kqA + 16 * i;
            Wt[(k4 + 0) * 72 + mA] = tf32r(ar[i].x);
            Wt[(k4 + 1) * 72 + mA] = tf32r(ar[i].y);
            Wt[(k4 + 2) * 72 + mA] = tf32r(ar[i].z);
            Wt[(k4 + 3) * 72 + mA] = tf32r(ar[i].w);
            int kk = kkB + 16 * i;
            float* bp2 = &Bt[kk * 72 + n4B];
            bp2[0] = tf32r(br[i].x); bp2[1] = tf32r(br[i].y);
            bp2[2] = tf32r(br[i].z); bp2[3] = tf32r(br[i].w);
        }
        __syncthreads();
        if (kc + 64 < NC) {
            #pragma unroll
            for (int i = 0; i < 4; ++i) {
                ar[i] = *(const float4*)&A[(size_t)(m0 + mA) * NC + kc + 64 + kqA + 16 * i];
                br[i] = *(const float4*)&x1[(size_t)(kc + 64 + kkB + 16 * i) * HW + n0 + n4B];
            }
        }
        #pragma unroll
        for (int ks = 0; ks < 8; ++ks) {
            int k0 = ks * 8;
            uint32_t a0 = __float_as_uint(Wt[(k0 + lk) * 72 + i0w + lrow]);
            uint32_t a1 = __float_as_uint(Wt[(k0 + lk) * 72 + i0w + lrow + 8]);
            uint32_t a2 = __float_as_uint(Wt[(k0 + lk + 4) * 72 + i0w + lrow]);
            uint32_t a3 = __float_as_uint(Wt[(k0 + lk + 4) * 72 + i0w + lrow + 8]);
            #pragma unroll
            for (int np = 0; np < 4; ++np) {
                int ncol = jbase + np * 8 + lrow;
                uint32_t b0 = __float_as_uint(Bt[(k0 + lk) * 72 + ncol]);
                uint32_t b1 = __float_as_uint(Bt[(k0 + lk + 4) * 72 + ncol]);
                mma_tf32(sf[np], a0, a1, a2, a3, b0, b1);
            }
        }
        __syncthreads();
    }

    const int cc0 = 2 * lk;
    #pragma unroll
    for (int rr = 0; rr < 2; ++rr) {
        int gm = m0 + i0w + lrow + rr * 8;
        float bsv = bias[gm];
        #pragma unroll
        for (int nt = 0; nt < 4; ++nt) {
            float e0 = sf[nt][rr * 2 + 0] + bsv;
            float e1 = sf[nt][rr * 2 + 1] + bsv;
            size_t idx = (size_t)gm * HW + n0 + jbase + nt * 8 + cc0;
            if (z == 0) {
                *(float2*)&qf[idx] = make_float2(e0, e1);
                *(__nv_bfloat162*)&qb[idx] = __floats2bfloat162_rn(e0, e1);
            } else if (z == 1) {
                *(__nv_bfloat162*)&kb[idx] = __floats2bfloat162_rn(e0, e1);
            } else if (z == 2) {
                *(__half2*)&vh[idx] = __floats2half2_rn(e0, e1);
            } else {
                *(float2*)&pf[idx] = make_float2(e0, e1);
            }
        }
    }
}

// ---------------- stacked k-major GEMM (z=0: RW, z=1: AB; prefetch) ----------
__global__ void __launch_bounds__(256) krgemm(
    const float* __restrict__ lo0, const float* __restrict__ hi0,
    const float* __restrict__ B0, float* __restrict__ C0,
    const float* __restrict__ lo1, const float* __restrict__ hi1,
    const float* __restrict__ B1, float* __restrict__ C1)
{
    __shared__ float Wt[64 * 72];
    __shared__ float Bt[64 * 72];
    const int z = blockIdx.z;
    const float* a_lo = z ? lo1 : lo0;
    const float* a_hi = z ? hi1 : hi0;
    const float* B    = z ? B1  : B0;
    float*       C    = z ? C1  : C0;
    const int tid = threadIdx.x;
    const int wid = tid >> 5, lane = tid & 31;
    const int m0 = blockIdx.y * 64, n0 = blockIdx.x * 64;
    const int i0w = (wid & 3) * 16;
    const int jbase = (wid >> 2) * 32;
    const int lrow = lane >> 2, lk = lane & 3;
    const int M = 2 * NH;
    const int kkB = tid >> 4, n4B = (tid & 15) << 2;
    const int m4A = (tid & 15) << 2;
    const int gmA = m0 + m4A;

    float sf[4][4];
    #pragma unroll
    for (int nt = 0; nt < 4; ++nt)
        #pragma unroll
        for (int e = 0; e < 4; ++e) sf[nt][e] = 0.f;

    float4 ar[4], br[4];
    #pragma unroll
    for (int i = 0; i < 4; ++i) {
        int kk = kkB + 16 * i;
        float4 a4 = make_float4(0.f, 0.f, 0.f, 0.f);
        if (gmA < NH)          a4 = *(const float4*)&a_lo[(size_t)kk * NH + gmA];
        else if (gmA < 2 * NH) a4 = *(const float4*)&a_hi[(size_t)kk * NH + gmA - NH];
        ar[i] = a4;
        br[i] = *(const float4*)&B[(size_t)kk * HW + n0 + n4B];
    }

    for (int kc = 0; kc < NC; kc += 64) {
        #pragma unroll
        for (int i = 0; i < 4; ++i) {
            int kk = kkB + 16 * i;
            float* wp = &Wt[kk * 72 + m4A];
            wp[0] = tf32r(ar[i].x); wp[1] = tf32r(ar[i].y);
            wp[2] = tf32r(ar[i].z); wp[3] = tf32r(ar[i].w);
            float* bp = &Bt[kk * 72 + n4B];
            bp[0] = tf32r(br[i].x); bp[1] = tf32r(br[i].y);
            bp[2] = tf32r(br[i].z); bp[3] = tf32r(br[i].w);
        }
        __syncthreads();
        if (kc + 64 < NC) {
            #pragma unroll
            for (int i = 0; i < 4; ++i) {
                int kk = kc + 64 + kkB + 16 * i;
                float4 a4 = make_float4(0.f, 0.f, 0.f, 0.f);
                if (gmA < NH)          a4 = *(const float4*)&a_lo[(size_t)kk * NH + gmA];
                else if (gmA < 2 * NH) a4 = *(const float4*)&a_hi[(size_t)kk * NH + gmA - NH];
                ar[i] = a4;
                br[i] = *(const float4*)&B[(size_t)kk * HW + n0 + n4B];
            }
        }
        #pragma unroll
        for (int ks = 0; ks < 8; ++ks) {
            int k0 = ks * 8;
            uint32_t a0 = __float_as_uint(Wt[(k0 + lk) * 72 + i0w + lrow]);
            uint32_t a1 = __float_as_uint(Wt[(k0 + lk) * 72 + i0w + lrow + 8]);
            uint32_t a2 = __float_as_uint(Wt[(k0 + lk + 4) * 72 + i0w + lrow]);
            uint32_t a3 = __float_as_uint(Wt[(k0 + lk + 4) * 72 + i0w + lrow + 8]);
            #pragma unroll
            for (int np = 0; np < 4; ++np) {
                int ncol = jbase + np * 8 + lrow;
                uint32_t b0 = __float_as_uint(Bt[(k0 + lk) * 72 + ncol]);
                uint32_t b1 = __float_as_uint(Bt[(k0 + lk + 4) * 72 + ncol]);
                mma_tf32(sf[np], a0, a1, a2, a3, b0, b1);
            }
        }
        __syncthreads();
    }

    const int cc0 = 2 * lk;
    #pragma unroll
    for (int rr = 0; rr < 2; ++rr) {
        int gm = m0 + i0w + lrow + rr * 8;
        if (gm >= M) continue;
        #pragma unroll
        for (int nt = 0; nt < 4; ++nt) {
            size_t idx = (size_t)gm * HW + n0 + jbase + nt * 8 + cc0;
            *(float2*)&C[idx] = make_float2(sf[nt][rr * 2 + 0], sf[nt][rr * 2 + 1]);
        }
    }
}

// ---------------- expnorm: single-store softmax over 80 rows ------------------
__global__ void expnorm(const float* __restrict__ AB, float* __restrict__ PAB)
{
    int gid = blockIdx.x * blockDim.x + threadIdx.x;
    if (gid >= 2 * HW) return;
    int h = (gid >= HW) ? 1 : 0;
    int i = gid - h * HW;
    const float* src = AB  + (size_t)h * NH * HW;
    float*       dst = PAB + (size_t)h * NH * HW;
    float s = 0.f;
    #pragma unroll 8
    for (int t = 0; t < NH; ++t) s += __expf(src[t * HW + i]);
    float inv = 1.f / s;
    #pragma unroll 8
    for (int t = 0; t < NH; ++t)
        dst[t * HW + i] = __expf(src[t * HW + i]) * inv;
}

// ---------------- W3 = [w3@efh | w3@efw]  ([256][160], m-major) --------------
__global__ void __launch_bounds__(192) w3eff_kernel(
    const float* __restrict__ w3, const float* __restrict__ efh,
    const float* __restrict__ efw, float* __restrict__ W)
{
    __shared__ float sw3[NC];
    const int m = blockIdx.x;
    const int t = threadIdx.x;
    if (t < NC) sw3[t] = w3[(size_t)m * NC + t];
    __syncthreads();
    if (t >= 2 * NH) return;
    const float* ef = (t < NH) ? (efh + t) : (efw + t - NH);
    float sum = 0.f;
    #pragma unroll 16
    for (int c = 0; c < NC; ++c)
        sum += sw3[c] * ef[(size_t)c * NH];
    W[(size_t)m * 160 + t] = sum;
}

// ---------------- fused final (prefetched, dual source) ----------------------
__global__ void __launch_bounds__(256) final_gemm(
    const float* __restrict__ w2, const float* __restrict__ o1,
    const float* __restrict__ g2, const float* __restrict__ b2,
    const float* __restrict__ m2, const float* __restrict__ v2,
    const float* __restrict__ W3, const float* __restrict__ PAB,
    const float* __restrict__ g3, const float* __restrict__ b3,
    const float* __restrict__ m3, const float* __restrict__ v3,
    const float* __restrict__ x, float* __restrict__ out)
{
    __shared__ float Wt[64 * 72];
    __shared__ float Bt[64 * 72];
    const int tid = threadIdx.x;
    const int wid = tid >> 5, lane = tid & 31;
    const int m0 = blockIdx.y * 64, n0 = blockIdx.x * 64;
    const int i0w = (wid & 3) * 16;
    const int jbase = (wid >> 2) * 32;
    const int lrow = lane >> 2, lk = lane & 3;
    const int mA = tid >> 2, kqA = (tid & 3) << 2;
    const int kkB = tid >> 4, n4B = (tid & 15) << 2;

    float keep[4][4];
    float sf[4][4];
    #pragma unroll
    for (int nt = 0; nt < 4; ++nt)
        #pragma unroll
        for (int e = 0; e < 4; ++e) sf[nt][e] = 0.f;

    float4 ar[4], br[4];
    #pragma unroll
    for (int i = 0; i < 4; ++i) {
        ar[i] = *(const float4*)&w2[(size_t)(m0 + mA) * NC + kqA + 16 * i];
        br[i] = *(const float4*)&o1[(size_t)(kkB + 16 * i) * HW + n0 + n4B];
    }

    #pragma unroll
    for (int src = 0; src < 2; ++src) {
        const int Kp = src ? 160 : NC;
        for (int kc = 0; kc < Kp; kc += 64) {
            const int ck = (Kp - kc < 64) ? (Kp - kc) : 64;
            #pragma unroll
            for (int i = 0; i < 4; ++i) {
                int k4 = kqA + 16 * i;
                if (k4 < ck) {
                    Wt[(k4 + 0) * 72 + mA] = tf32r(ar[i].x);
                    Wt[(k4 + 1) * 72 + mA] = tf32r(ar[i].y);
                    Wt[(k4 + 2) * 72 + mA] = tf32r(ar[i].z);
                    Wt[(k4 + 3) * 72 + mA] = tf32r(ar[i].w);
                }
                int kk = kkB + 16 * i;
                if (kk < ck) {
                    float* bp = &Bt[kk * 72 + n4B];
                    bp[0] = tf32r(br[i].x); bp[1] = tf32r(br[i].y);
                    bp[2] = tf32r(br[i].z); bp[3] = tf32r(br[i].w);
                }
            }
            __syncthreads();
            {
                int srcN = src, kcN = kc + 64;
                if (kcN >= Kp) { srcN = src + 1; kcN = 0; }
                if (srcN < 2) {
                    const float* ApN = srcN ? W3 : w2;
                    const float* BpN = srcN ? PAB : o1;
                    int KpN = srcN ? 160 : NC;
                    int ckN = (KpN - kcN < 64) ? (KpN - kcN) : 64;
                    #pragma unroll
                    for (int i = 0; i < 4; ++i) {
                        int k4 = kqA + 16 * i;
                        if (k4 < ckN)
                            ar[i] = *(const float4*)&ApN[(size_t)(m0 + mA) * KpN + kcN + k4];
                        int kk = kkB + 16 * i;
                        if (kk < ckN)
                            br[i] = *(const float4*)&BpN[(size_t)(kcN + kk) * HW + n0 + n4B];
                    }
                }
            }
            const int nks = ck >> 3;
            for (int ks = 0; ks < nks; ++ks) {
                int k0 = ks * 8;
                uint32_t a0 = __float_as_uint(Wt[(k0 + lk) * 72 + i0w + lrow]);
                uint32_t a1 = __float_as_uint(Wt[(k0 + lk) * 72 + i0w + lrow + 8]);
                uint32_t a2 = __float_as_uint(Wt[(k0 + lk + 4) * 72 + i0w + lrow]);
                uint32_t a3 = __float_as_uint(Wt[(k0 + lk + 4) * 72 + i0w + lrow + 8]);
                #pragma unroll
                for (int np = 0; np < 4; ++np) {
                    int ncol = jbase + np * 8 + lrow;
                    uint32_t b0 = __float_as_uint(Bt[(k0 + lk) * 72 + ncol]);
                    uint32_t b1 = __float_as_uint(Bt[(k0 + lk + 4) * 72 + ncol]);
                    mma_tf32(sf[np], a0, a1, a2, a3, b0, b1);
                }
            }
            __syncthreads();
        }
        const float* gg  = src ? g3 : g2;
        const float* bbp = src ? b3 : b2;
        const float* mmp = src ? m3 : m2;
        const float* vvp = src ? v3 : v2;
        #pragma unroll
        for (int rr = 0; rr < 2; ++rr) {
            int gm = m0 + i0w + lrow + rr * 8;
            float sc = gg[gm] * rsqrtf(vvp[gm] + EPS);
            float sh = bbp[gm] - mmp[gm] * sc;
            #pragma unroll
            for (int nt = 0; nt < 4; ++nt) {
                #pragma unroll
                for (int e2 = 0; e2 < 2; ++e2) {
                    float val = sf[nt][rr * 2 + e2] * sc + sh;
                    val = val / (1.f + __expf(-val));
                    if (src == 0) { keep[nt][rr * 2 + e2] = val; sf[nt][rr * 2 + e2] = 0.f; }
                    else          { keep[nt][rr * 2 + e2] += val; }
                }
            }
        }
    }

    const int cc0 = 2 * lk;
    #pragma unroll
    for (int rr = 0; rr < 2; ++rr) {
        int gm = m0 + i0w + lrow + rr * 8;
        #pragma unroll
        for (int nt = 0; nt < 4; ++nt) {
            size_t idx = (size_t)gm * HW + n0 + jbase + nt * 8 + cc0;
            float2 x2 = *(const float2*)&x[idx];
            *(float2*)&out[idx] = make_float2(keep[nt][rr * 2 + 0] + x2.x,
                                              keep[nt][rr * 2 + 1] + x2.y);
        }
    }
}

// ---------------- branch-1 flash attention: 4 fat warps, Q + softmax in regs --
#define QS_OFF   0               // bf16 [128][72]
#define KS_OFF   18432           // bf16 [128][72]
#define VS_OFF   36864           // f16  [128][72]
#define RB_OFF   55296           // f16  [64][72] fused Rw+Rh bias
#define FL_SM_BYTES 64512

__global__ void __launch_bounds__(128, 2) flash_kernel(
    const __nv_bfloat16* __restrict__ q, const __nv_bfloat16* __restrict__ k,
    const __half* __restrict__ v, const float* __restrict__ Rh,
    const float* __restrict__ Rw, float* __restrict__ op,
    float* __restrict__ mp, float* __restrict__ lp)
{
    extern __shared__ char smc[];
    __half* RbH = (__half*)(smc + RB_OFF);

    const int tid  = threadIdx.x;
    const int wid  = tid >> 5, lane = tid & 31;
    const int lr   = lane & 7, gq = lane >> 3;
    const int lrowq = lane >> 2, lk = lane & 3;
    const int i0   = blockIdx.x * 64;
    const int spl  = blockIdx.y;
    const int t0   = (spl * 100) / SPLIT;
    const int t1   = ((spl + 1) * 100) / SPLIT;
    const int i0w  = wid * 16;
    const float L2E = 1.4426950408889634f;

    const uint32_t qsb = (uint32_t)__cvta_generic_to_shared(smc + QS_OFF);
    const uint32_t ksb = (uint32_t)__cvta_generic_to_shared(smc + KS_OFF);
    const uint32_t vsb = (uint32_t)__cvta_generic_to_shared(smc + VS_OFF);

    // prologue: Q, K(t0), V(t0) via cp.async (3 groups)
    {
        #pragma unroll
        for (int it = 0; it < 8; ++it) {
            int ch = tid + it * 128;
            int c = ch >> 3, j8 = (ch & 7) * 8;
            cpa16(qsb + (uint32_t)((c * 72 + j8) * 2), &q[(size_t)c * HW + i0 + j8]);
        }
        CPA_COMMIT();
        int j0n = t0 * 64;
        #pragma unroll
        for (int it = 0; it < 8; ++it) {
            int ch = tid + it * 128;
            int c = ch >> 3, j8 = (ch & 7) * 8;
            cpa16(ksb + (uint32_t)((c * 72 + j8) * 2), &k[(size_t)c * HW + j0n + j8]);
        }
        CPA_COMMIT();
        #pragma unroll
        for (int it = 0; it < 8; ++it) {
            int ch = tid + it * 128;
            int c = ch >> 3, j8 = (ch & 7) * 8;
            cpa16(vsb + (uint32_t)((c * 72 + j8) * 2), &v[(size_t)c * HW + j0n + j8]);
        }
        CPA_COMMIT();
    }
    asm volatile("cp.async.wait_group 2;");   // Q landed
    __syncthreads();

    // hoist Q fragments (loop-invariant): 8 k-steps x 4 regs
    uint32_t qf[8][4];
    #pragma unroll
    for (int ks = 0; ks < 8; ++ks)
        ldsm4t(qf[ks][0], qf[ks][1], qf[ks][2], qf[ks][3],
               qsb + (uint32_t)(((ks * 16 + lr + (gq >> 1) * 8) * 72
                                + i0w + (gq & 1) * 8) * 2));

    float d[16][4];
    #pragma unroll
    for (int nt = 0; nt < 16; ++nt)
        #pragma unroll
        for (int e = 0; e < 4; ++e) d[nt][e] = 0.f;
    float m0v = -1e30f, m1v = -1e30f, l0v = 0.f, l1v = 0.f;
    const int r0 = i0w + lrowq, r1 = r0 + 8;

    for (int t = t0; t < t1; ++t) {
        const int j0 = t * 64;
        const bool more = (t + 1 < t1);

        // stage fused bias tile fp16 (safe: previous softmax done at sync C)
        #pragma unroll
        for (int e = 0; e < 8; ++e) {
            int ee = tid + e * 128;
            int row = ee >> 4, c4 = (ee & 15) << 2;
            int gi = i0 + row;
            float4 a = *(const float4*)&Rw[(gi % 80) * HW + j0 + c4];
            float4 b = *(const float4*)&Rh[(gi / 80) * HW + j0 + c4];
            __half2* dst = (__half2*)&RbH[row * 72 + c4];
            dst[0] = __floats2half2_rn(a.x + b.x, a.y + b.y);
            dst[1] = __floats2half2_rn(a.z + b.z, a.w + b.w);
        }
        asm volatile("cp.async.wait_group 1;");   // K(t) landed
        __syncthreads();                          // A: K + bias visible

        // ---- QK^T (bf16), full 64 j per warp ----
        float sf[8][4];
        #pragma unroll
        for (int nb = 0; nb < 8; ++nb)
            #pragma unroll
            for (int e = 0; e < 4; ++e) sf[nb][e] = 0.f;

        #pragma unroll
        for (int ks = 0; ks < 8; ++ks) {
            #pragma unroll
            for (int jn = 0; jn < 4; ++jn) {
                uint32_t b0, b1, b2, b3;
                ldsm4t(b0, b1, b2, b3,
                       ksb + (uint32_t)(((ks * 16 + lr + (gq & 1) * 8) * 72
                                        + jn * 16 + (gq >> 1) * 8) * 2));
                mma_bf16(sf[jn * 2],     qf[ks][0], qf[ks][1], qf[ks][2], qf[ks][3], b0, b1);
                mma_bf16(sf[jn * 2 + 1], qf[ks][0], qf[ks][1], qf[ks][2], qf[ks][3], b2, b3);
            }
        }
        asm volatile("cp.async.wait_group 0;");   // V(t) landed
        __syncthreads();                          // B: Ks free, Vs visible

        if (more) {                               // K(t+1) in place
            int j0n = (t + 1) * 64;
            #pragma unroll
            for (int it = 0; it < 8; ++it) {
                int ch = tid + it * 128;
                int c = ch >> 3, j8 = (ch & 7) * 8;
                cpa16(ksb + (uint32_t)((c * 72 + j8) * 2), &k[(size_t)c * HW + j0n + j8]);
            }
            CPA_COMMIT();
        }

        // ---- softmax entirely warp-local (regs + quad shfl) ----
        #pragma unroll
        for (int nb = 0; nb < 8; ++nb) {
            int col = nb * 8 + 2 * lk;
            float2 b0 = __half22float2(*(__half2*)&RbH[r0 * 72 + col]);
            float2 b1 = __half22float2(*(__half2*)&RbH[r1 * 72 + col]);
            sf[nb][0] += b0.x; sf[nb][1] += b0.y;
            sf[nb][2] += b1.x; sf[nb][3] += b1.y;
        }
        float mx0 = -1e30f, mx1 = -1e30f;
        #pragma unroll
        for (int nb = 0; nb < 8; ++nb) {
            mx0 = fmaxf(mx0, fmaxf(sf[nb][0], sf[nb][1]));
            mx1 = fmaxf(mx1, fmaxf(sf[nb][2], sf[nb][3]));
        }
        mx0 = fmaxf(mx0, __shfl_xor_sync(0xffffffffu, mx0, 1));
        mx0 = fmaxf(mx0, __shfl_xor_sync(0xffffffffu, mx0, 2));
        mx1 = fmaxf(mx1, __shfl_xor_sync(0xffffffffu, mx1, 1));
        mx1 = fmaxf(mx1, __shfl_xor_sync(0xffffffffu, mx1, 2));
        float nm0 = fmaxf(m0v, mx0), nm1 = fmaxf(m1v, mx1);
        float f0 = exp2f((m0v - nm0) * L2E);
        float f1 = exp2f((m1v - nm1) * L2E);
        uint32_t ph[8][2];
        float s0 = 0.f, s1 = 0.f;
        #pragma unroll
        for (int nb = 0; nb < 8; ++nb) {
            float u0 = (sf[nb][0] - nm0) * L2E, u1 = (sf[nb][1] - nm0) * L2E;
            float u2 = (sf[nb][2] - nm1) * L2E, u3 = (sf[nb][3] - nm1) * L2E;
            uint32_t p0, p1;
            asm("cvt.rn.f16x2.f32 %0, %1, %2;" : "=r"(p0) : "f"(u1), "f"(u0));
            asm("ex2.approx.f16x2 %0, %0;" : "+r"(p0));
            asm("cvt.rn.f16x2.f32 %0, %1, %2;" : "=r"(p1) : "f"(u3), "f"(u2));
            asm("ex2.approx.f16x2 %0, %0;" : "+r"(p1));
            ph[nb][0] = p0; ph[nb][1] = p1;
            float2 e0 = __half22float2(*reinterpret_cast<__half2*>(&p0));
            float2 e1 = __half22float2(*reinterpret_cast<__half2*>(&p1));
            s0 += e0.x + e0.y;
            s1 += e1.x + e1.y;
        }
        s0 += __shfl_xor_sync(0xffffffffu, s0, 1);
        s0 += __shfl_xor_sync(0xffffffffu, s0, 2);
        s1 += __shfl_xor_sync(0xffffffffu, s1, 1);
        s1 += __shfl_xor_sync(0xffffffffu, s1, 2);
        l0v = l0v * f0 + s0;  m0v = nm0;
        l1v = l1v * f1 + s1;  m1v = nm1;
        #pragma unroll
        for (int nt = 0; nt < 16; ++nt) {
            d[nt][0] *= f0; d[nt][1] *= f0;
            d[nt][2] *= f1; d[nt][3] *= f1;
        }

        // ---- P @ V^T (fp16): A = register P frags, k = 64 j, n = 128 c ----
        #pragma unroll
        for (int ks = 0; ks < 4; ++ks) {
            uint32_t a0 = ph[2 * ks][0], a1 = ph[2 * ks][1];
            uint32_t a2 = ph[2 * ks + 1][0], a3 = ph[2 * ks + 1][1];
            #pragma unroll
            for (int np = 0; np < 8; ++np) {
                uint32_t b0, b1, b2, b3;
                ldsm4(b0, b1, b2, b3,
                      vsb + (uint32_t)(((np * 16 + lr + (gq >> 1) * 8) * 72
                                       + ks * 16 + (gq & 1) * 8) * 2));
                mma_f16(d[np * 2],     a0, a1, a2, a3, b0, b1);
                mma_f16(d[np * 2 + 1], a0, a1, a2, a3, b2, b3);
            }
        }
        __syncthreads();                          // C: Vs free, bias free

        if (more) {                               // V(t+1)
            int j0n = (t + 1) * 64;
            #pragma unroll
            for (int it = 0; it < 8; ++it) {
                int ch = tid + it * 128;
                int c = ch >> 3, j8 = (ch & 7) * 8;
                cpa16(vsb + (uint32_t)((c * 72 + j8) * 2), &v[(size_t)c * HW + j0n + j8]);
            }
            CPA_COMMIT();
        }
    }

    // ---- epilogue: warp owns 16 rows x all 128 channels; direct writes ----
    #pragma unroll
    for (int nt = 0; nt < 16; ++nt) {
        int c = nt * 8 + 2 * lk;
        op[(size_t)(spl * NC + c)     * HW + i0 + r0] = d[nt][0];
        op[(size_t)(spl * NC + c + 1) * HW + i0 + r0] = d[nt][1];
        op[(size_t)(spl * NC + c)     * HW + i0 + r1] = d[nt][2];
        op[(size_t)(spl * NC + c + 1) * HW + i0 + r1] = d[nt][3];
    }
    if (lk == 0) {
        mp[spl * HW + i0 + r0] = m0v;
        mp[spl * HW + i0 + r1] = m1v;
        lp[spl * HW + i0 + r0] = l0v;
        lp[spl * HW + i0 + r1] = l1v;
    }
}

// ---------------- split-j combine (channel-parallel) -------------------------
__global__ void combine_kernel(const float* __restrict__ op,
                               const float* __restrict__ mp,
                               const float* __restrict__ lp,
                               float* __restrict__ out1)
{
    int i = blockIdx.x * blockDim.x + threadIdx.x;
    if (i >= HW) return;
    int c0 = blockIdx.y * 8;
    float m[SPLIT], w[SPLIT];
    float M = -1e30f;
    #pragma unroll
    for (int s = 0; s < SPLIT; ++s) { m[s] = mp[s * HW + i]; M = fmaxf(M, m[s]); }
    float L = 0.f;
    #pragma unroll
    for (int s = 0; s < SPLIT; ++s) { w[s] = __expf(m[s] - M); L += lp[s * HW + i] * w[s]; }
    float inv = 1.f / L;
    for (int c = c0; c < c0 + 8; ++c) {
        float acc = 0.f;
        #pragma unroll
        for (int s = 0; s < SPLIT; ++s)
            acc += op[((size_t)(s * NC + c)) * HW + i] * w[s];
        out1[(size_t)c * HW + i] = acc * inv;
    }
}

// -------------------------------- launch -------------------------------------
extern "C" void kernel_launch(void* const* d_in, const int* in_sizes, int n_in,
                              void* d_out, int out_size)
{
    (void)in_sizes; (void)n_in; (void)out_size;
    const float* x    = (const float*)d_in[0];
    const float* w1   = (const float*)d_in[1];
    const float* g1   = (const float*)d_in[2];
    const float* b1   = (const float*)d_in[3];
    const float* m1   = (const float*)d_in[4];
    const float* v1   = (const float*)d_in[5];
    const float* w2   = (const float*)d_in[6];
    const float* g2   = (const float*)d_in[7];
    const float* b2   = (const float*)d_in[8];
    const float* m2   = (const float*)d_in[9];
    const float* v2   = (const float*)d_in[10];
    const float* w3   = (const float*)d_in[11];
    const float* g3   = (const float*)d_in[12];
    const float* b3   = (const float*)d_in[13];
    const float* m3   = (const float*)d_in[14];
    const float* v3   = (const float*)d_in[15];
    const float* wq   = (const float*)d_in[16];
    const float* bq   = (const float*)d_in[17];
    const float* wk   = (const float*)d_in[18];
    const float* bk   = (const float*)d_in[19];
    const float* wv   = (const float*)d_in[20];
    const float* bv   = (const float*)d_in[21];
    const float* wp   = (const float*)d_in[22];
    const float* bp   = (const float*)d_in[23];
    const float* relh = (const float*)d_in[24];
    const float* relw = (const float*)d_in[25];
    const float* efh  = (const float*)d_in[26];
    const float* efw  = (const float*)d_in[27];
    float* out = (float*)d_out;

    float *px1, *pq, *pp, *pRW, *pAB, *pPAB, *pW3, *po1, *pop, *pmp, *plp;
    __nv_bfloat16 *pqb, *pkb;
    __half *pvh;
    cudaGetSymbolAddress((void**)&px1, d_x1);
    cudaGetSymbolAddress((void**)&pq,  d_q);
    cudaGetSymbolAddress((void**)&pp,  d_p);
    cudaGetSymbolAddress((void**)&pqb, d_qb);
    cudaGetSymbolAddress((void**)&pkb, d_kb);
    cudaGetSymbolAddress((void**)&pvh, d_vh);
    cudaGetSymbolAddress((void**)&pRW, d_RW);
    cudaGetSymbolAddress((void**)&pAB, d_AB);
    cudaGetSymbolAddress((void**)&pPAB, d_PAB);
    cudaGetSymbolAddress((void**)&pW3, d_W3);
    cudaGetSymbolAddress((void**)&po1, d_o1);
    cudaGetSymbolAddress((void**)&pop, d_op);
    cudaGetSymbolAddress((void**)&pmp, d_mp);
    cudaGetSymbolAddress((void**)&plp, d_lp);

    cudaFuncSetAttribute(flash_kernel,
        cudaFuncAttributeMaxDynamicSharedMemorySize, FL_SM_BYTES);

    dim3 g100_2(100, 2), g100_4(100, 4);
    dim3 gproj(100, 2, 4), gkr(100, 3, 2), gfl(100, SPLIT), gcmb(25, 16);

    // [0] W3 = [w3@efh | w3@efw]
    w3eff_kernel<<<ND, 192>>>(w3, efh, efw, pW3);
    // [1] x1 = SiLU(BN(w1 @ x))
    tgemm<2><<<g100_2, 256>>>(w1, x, px1, NC, ND, g1, b1, m1, v1);
    // [2] fused q/k/v/p projections (fp32 q,p; bf16 q,k; fp16 v)
    proj4<<<gproj, 256>>>(px1, wq, bq, wk, bk, wv, bv, wp, bp,
        pq, pqb, pkb, pvh, pp);
    // [3] z=0: [Rh;Rw] = [rel_h;rel_w]^T q;  z=1: [ABh;ABw] = [ef_h;ef_w]^T p
    krgemm<<<gkr, 256>>>(relh, relw, pq, pRW, efh, efw, pp, pAB);
    // [4] PAB = per-column softmax of both halves (single-store)
    expnorm<<<50, 256>>>(pAB, pPAB);
    // [5] flash attention (4 fat warps, Q-frags + softmax in registers)
    flash_kernel<<<gfl, 128, FL_SM_BYTES>>>(pqb, pkb, pvh,
        pRW, pRW + NH * HW, pop, pmp, plp);
    // [6] combine split partials -> out1
    combine_kernel<<<gcmb, 256>>>(pop, pmp, plp, po1);
    // [7] out = x + SiLU(BN2(w2@o1)) + SiLU(BN3(W3@PAB))
    final_gemm<<<g100_4, 256>>>(w2, po1, g2, b2, m2, v2,
        pW3, pPAB, g3, b3, m3, v3, x, out);
}